// round 10
// baseline (speedup 1.0000x reference)
#include <cuda_runtime.h>
#include <cuda_fp16.h>
#include <math.h>
#include <stdint.h>

// Problem shape (fixed): B=8, T=2048, D=1024
#define BB   8
#define TT   2048
#define DD   1024
#define MM   (BB*TT)          // 16384 rows
#define NCHUNK 32
#define CHLEN  64

// ---- BK=64 GEMM (primary): CTA 128x128, 2 outputs, warp 64x32x2 ----
#define NCH64   16
#define A64_OFF  0
#define BZ64_OFF 16384
#define BH64_OFF 32768
#define STAGE64  49152        // 48KB per stage; 2 stages = 96KB

// ---- BK=32 GEMM (fallback, 48KB default smem) ----
#define NCH32   32
#define A32_OFF  0
#define BZ32_OFF 8192
#define BH32_OFF 16384
#define STAGE32  24576

#define SMEM_Y  (CHLEN * 256 * 8)   // 131072: y16 tile as uint2[64][256]

// ---------------- scratch (device globals) ----------------
__device__ __half2 g_ab[(size_t)MM * DD];   // {a, b} per element (fp16)
__device__ __half  g_y16[(size_t)MM * DD];  // swish output (fallback path only)
__device__ float   g_Ac[BB * NCHUNK * DD];  // chunk summaries (fp32)
__device__ float   g_Bc[BB * NCHUNK * DD];

__device__ __half g_xh[(size_t)MM * DD];    // x in fp16
__device__ __half g_Wtz[DD * DD];           // Wz^T fp16: [n][k]
__device__ __half g_Wth[DD * DD];           // Wh^T fp16: [n][k]

__device__ __forceinline__ float sigmoidf_fast(float v) {
    return 1.0f / (1.0f + __expf(-v));
}

// ---- bit casts ----
__device__ __forceinline__ uint32_t h2_to_u32(__half2 h) {
    return *reinterpret_cast<uint32_t*>(&h);
}
__device__ __forceinline__ __half2 u32_to_h2(uint32_t u) {
    return *reinterpret_cast<__half2*>(&u);
}

// ---------------- PTX helpers ----------------
__device__ __forceinline__ uint32_t smem_u32(const void* p) {
    uint32_t a;
    asm("{ .reg .u64 t; cvta.to.shared.u64 t, %1; cvt.u32.u64 %0, t; }" : "=r"(a) : "l"(p));
    return a;
}
#define SWZ64(o)  ((o) ^ (((o) >> 3) & 0x30))
#define SWZ128(o) ((o) ^ (((o) >> 3) & 0x70))

__device__ __forceinline__ void cp16(uint32_t s, const void* g) {
    asm volatile("cp.async.cg.shared.global [%0], [%1], 16;" :: "r"(s), "l"(g));
}
__device__ __forceinline__ void cp_commit() {
    asm volatile("cp.async.commit_group;" ::: "memory");
}
__device__ __forceinline__ void ldsm_x4(uint32_t& r0, uint32_t& r1, uint32_t& r2,
                                        uint32_t& r3, uint32_t addr) {
    asm volatile("ldmatrix.sync.aligned.m8n8.x4.shared.b16 {%0,%1,%2,%3}, [%4];"
                 : "=r"(r0), "=r"(r1), "=r"(r2), "=r"(r3) : "r"(addr));
}
__device__ __forceinline__ void mma_f16(float* d, const uint32_t* a, const uint32_t* b) {
    asm volatile(
        "mma.sync.aligned.m16n8k16.row.col.f32.f16.f16.f32 "
        "{%0,%1,%2,%3},{%4,%5,%6,%7},{%8,%9},{%0,%1,%2,%3};"
        : "+f"(d[0]), "+f"(d[1]), "+f"(d[2]), "+f"(d[3])
        : "r"(a[0]), "r"(a[1]), "r"(a[2]), "r"(a[3]), "r"(b[0]), "r"(b[1]));
}

// ---------------- prep: convert x to fp16 ----------------
__global__ __launch_bounds__(256)
void convert_x_kernel(const float* __restrict__ x)
{
    const size_t i4 = (size_t)blockIdx.x * 256 + threadIdx.x;
    const float4 v = ((const float4*)x)[i4];
    __half2 p0, p1;
    p0.x = __float2half_rn(v.x); p0.y = __float2half_rn(v.y);
    p1.x = __float2half_rn(v.z); p1.y = __float2half_rn(v.w);
    ((__half2*)g_xh)[i4 * 2]     = p0;
    ((__half2*)g_xh)[i4 * 2 + 1] = p1;
}

// ---------------- prep: transpose W -> Wt[n][k], fp16 ----------------
__global__ __launch_bounds__(256)
void transpose_kernel(const float* __restrict__ Wz, const float* __restrict__ Wh)
{
    __shared__ float sm[32][33];
    const float* W = (blockIdx.z == 0) ? Wz : Wh;
    __half* Wt = (blockIdx.z == 0) ? g_Wtz : g_Wth;

    const int k0 = blockIdx.y * 32;
    const int n0 = blockIdx.x * 32;
    const int r = threadIdx.x >> 5;
    const int c = threadIdx.x & 31;
#pragma unroll
    for (int rr = 0; rr < 4; rr++) {
        const int row = rr * 8 + r;
        sm[row][c] = W[(size_t)(k0 + row) * DD + n0 + c];
    }
    __syncthreads();
#pragma unroll
    for (int rr = 0; rr < 4; rr++) {
        const int row = rr * 8 + r;
        Wt[(size_t)(n0 + row) * DD + k0 + c] = __float2half_rn(sm[c][row]);
    }
}

// ---------------- shared epilogue: {a,b} fp16 interleaved ----------------
__device__ __forceinline__ void gemm_epilogue(
    float accz[4][4][4], float acch[4][4][4],
    const float* __restrict__ bz, const float* __restrict__ bh,
    int mBase, int nBase, int wr, int wc, int lane)
{
    const int er = lane >> 2;
    const int ec = (lane & 3) * 2;
#pragma unroll
    for (int mt = 0; mt < 4; mt++) {
#pragma unroll
        for (int nt = 0; nt < 4; nt++) {
            const int m = mBase + wr * 64 + mt * 16 + er;
            const int n = nBase + wc * 32 + nt * 8 + ec;
            const size_t g0 = (size_t)m * DD + n;
            const size_t g1 = g0 + 8 * DD;
            const float2 bz2 = *(const float2*)(&bz[n]);
            const float2 bh2 = *(const float2*)(&bh[n]);
            float z;
            __half2 p0, p1;
            z = sigmoidf_fast(accz[mt][nt][0] + bz2.x);
            p0.x = __float2half_rn(1.0f - z);
            p0.y = __float2half_rn(z * (acch[mt][nt][0] + bh2.x));
            z = sigmoidf_fast(accz[mt][nt][1] + bz2.y);
            p1.x = __float2half_rn(1.0f - z);
            p1.y = __float2half_rn(z * (acch[mt][nt][1] + bh2.y));
            *(uint2*)(&g_ab[g0]) = make_uint2(h2_to_u32(p0), h2_to_u32(p1));
            z = sigmoidf_fast(accz[mt][nt][2] + bz2.x);
            p0.x = __float2half_rn(1.0f - z);
            p0.y = __float2half_rn(z * (acch[mt][nt][2] + bh2.x));
            z = sigmoidf_fast(accz[mt][nt][3] + bz2.y);
            p1.x = __float2half_rn(1.0f - z);
            p1.y = __float2half_rn(z * (acch[mt][nt][3] + bh2.y));
            *(uint2*)(&g_ab[g1]) = make_uint2(h2_to_u32(p0), h2_to_u32(p1));
        }
    }
}

// ---------------- PRIMARY GEMM: BK=64, 2-stage, 96KB smem --------------------
__global__ __launch_bounds__(256, 1)
void gemm64_kernel(const float* __restrict__ bz, const float* __restrict__ bh)
{
    extern __shared__ char smem[];
    const uint32_t sbase = smem_u32(smem);
    const int tid  = threadIdx.x;
    const int wid  = tid >> 5;
    const int lane = tid & 31;
    const int wr = wid >> 2;
    const int wc = wid & 3;

    const int nBase = blockIdx.x * 128;
    const int mBase = blockIdx.y * 128;

    int ldRow[4];
    int ldCol[4];
    uint32_t ldOff[4];
#pragma unroll
    for (int t = 0; t < 4; t++) {
        const int o = tid + t * 256;
        ldRow[t] = o >> 3;
        ldCol[t] = o & 7;
        ldOff[t] = SWZ128((uint32_t)(o * 16));
    }

    const int quad = lane >> 3;
    const int r8   = lane & 7;
    const int rowA = (quad & 1) * 8 + r8;
    const int kbA  = (quad >> 1) * 16;
    const int rowB = (quad >> 1) * 8 + r8;
    const int kbB  = (quad & 1) * 16;

    uint32_t offA[4][4], offB[4][2];
#pragma unroll
    for (int ks = 0; ks < 4; ks++) {
#pragma unroll
        for (int mt = 0; mt < 4; mt++)
            offA[ks][mt] = SWZ128((uint32_t)((wr * 64 + mt * 16 + rowA) * 128 + ks * 32 + kbA));
#pragma unroll
        for (int bt = 0; bt < 2; bt++)
            offB[ks][bt] = SWZ128((uint32_t)((wc * 32 + bt * 16 + rowB) * 128 + ks * 32 + kbB));
    }

    float accz[4][4][4], acch[4][4][4];
#pragma unroll
    for (int i = 0; i < 4; i++)
#pragma unroll
        for (int j = 0; j < 4; j++)
#pragma unroll
            for (int k = 0; k < 4; k++) { accz[i][j][k] = 0.0f; acch[i][j][k] = 0.0f; }

    auto load_chunk = [&](int chunk, int stage) {
        const int k0 = chunk * 64;
        const uint32_t st = sbase + stage * STAGE64;
#pragma unroll
        for (int t = 0; t < 4; t++) {
            const size_t rowOff = (size_t)ldRow[t] * DD + k0 + ldCol[t] * 8;
            cp16(st + A64_OFF  + ldOff[t], g_xh  + (size_t)mBase * DD + rowOff);
            cp16(st + BZ64_OFF + ldOff[t], g_Wtz + (size_t)nBase * DD + rowOff);
            cp16(st + BH64_OFF + ldOff[t], g_Wth + (size_t)nBase * DD + rowOff);
        }
        cp_commit();
    };

    load_chunk(0, 0);

    for (int i = 0; i < NCH64; i++) {
        const int s = i & 1;
        asm volatile("cp.async.wait_group 0;" ::: "memory");
        __syncthreads();
        if (i + 1 < NCH64) load_chunk(i + 1, s ^ 1);

        const uint32_t st = sbase + s * STAGE64;
#pragma unroll
        for (int ks = 0; ks < 4; ks++) {
            uint32_t af[4][4];
#pragma unroll
            for (int mt = 0; mt < 4; mt++)
                ldsm_x4(af[mt][0], af[mt][1], af[mt][2], af[mt][3],
                        st + A64_OFF + offA[ks][mt]);
            {
                uint32_t bf[4][2];
#pragma unroll
                for (int bt = 0; bt < 2; bt++)
                    ldsm_x4(bf[bt*2][0], bf[bt*2][1], bf[bt*2+1][0], bf[bt*2+1][1],
                            st + BZ64_OFF + offB[ks][bt]);
#pragma unroll
                for (int mt = 0; mt < 4; mt++)
#pragma unroll
                    for (int nt = 0; nt < 4; nt++)
                        mma_f16(accz[mt][nt], af[mt], bf[nt]);
            }
            {
                uint32_t bf[4][2];
#pragma unroll
                for (int bt = 0; bt < 2; bt++)
                    ldsm_x4(bf[bt*2][0], bf[bt*2][1], bf[bt*2+1][0], bf[bt*2+1][1],
                            st + BH64_OFF + offB[ks][bt]);
#pragma unroll
                for (int mt = 0; mt < 4; mt++)
#pragma unroll
                    for (int nt = 0; nt < 4; nt++)
                        mma_f16(acch[mt][nt], af[mt], bf[nt]);
            }
        }
    }

    gemm_epilogue(accz, acch, bz, bh, mBase, nBase, wr, wc, lane);
}

// ---------------- FALLBACK GEMM: BK=32, 2-stage, 48KB ------------
__global__ __launch_bounds__(256, 1)
void gemm32_kernel(const float* __restrict__ bz, const float* __restrict__ bh)
{
    extern __shared__ char smem[];
    const uint32_t sbase = smem_u32(smem);
    const int tid  = threadIdx.x;
    const int wid  = tid >> 5;
    const int lane = tid & 31;
    const int wr = wid >> 2;
    const int wc = wid & 3;

    const int nBase = blockIdx.x * 128;
    const int mBase = blockIdx.y * 128;

    int ldRow[2];
    int ldCol[2];
    uint32_t ldOff[2];
#pragma unroll
    for (int t = 0; t < 2; t++) {
        const int o = tid + t * 256;
        ldRow[t] = o >> 2;
        ldCol[t] = o & 3;
        ldOff[t] = SWZ64((uint32_t)(o * 16));
    }

    const int quad = lane >> 3;
    const int r8   = lane & 7;
    const int rowA = (quad & 1) * 8 + r8;
    const int kbA  = (quad >> 1) * 16;
    const int rowB = (quad >> 1) * 8 + r8;
    const int kbB  = (quad & 1) * 16;

    uint32_t offA[2][4], offB[2][2];
#pragma unroll
    for (int ks = 0; ks < 2; ks++) {
#pragma unroll
        for (int mt = 0; mt < 4; mt++)
            offA[ks][mt] = SWZ64((uint32_t)((wr * 64 + mt * 16 + rowA) * 64 + ks * 32 + kbA));
#pragma unroll
        for (int bt = 0; bt < 2; bt++)
            offB[ks][bt] = SWZ64((uint32_t)((wc * 32 + bt * 16 + rowB) * 64 + ks * 32 + kbB));
    }

    float accz[4][4][4], acch[4][4][4];
#pragma unroll
    for (int i = 0; i < 4; i++)
#pragma unroll
        for (int j = 0; j < 4; j++)
#pragma unroll
            for (int k = 0; k < 4; k++) { accz[i][j][k] = 0.0f; acch[i][j][k] = 0.0f; }

    auto load_chunk = [&](int chunk, int stage) {
        const int k0 = chunk * 32;
        const uint32_t st = sbase + stage * STAGE32;
#pragma unroll
        for (int t = 0; t < 2; t++) {
            const size_t rowOff = (size_t)ldRow[t] * DD + k0 + ldCol[t] * 8;
            cp16(st + A32_OFF  + ldOff[t], g_xh  + (size_t)mBase * DD + rowOff);
            cp16(st + BZ32_OFF + ldOff[t], g_Wtz + (size_t)nBase * DD + rowOff);
            cp16(st + BH32_OFF + ldOff[t], g_Wth + (size_t)nBase * DD + rowOff);
        }
        cp_commit();
    };

    load_chunk(0, 0);

    for (int i = 0; i < NCH32; i++) {
        const int s = i & 1;
        asm volatile("cp.async.wait_group 0;" ::: "memory");
        __syncthreads();
        if (i + 1 < NCH32) load_chunk(i + 1, s ^ 1);

        const uint32_t st = sbase + s * STAGE32;
#pragma unroll
        for (int ks = 0; ks < 2; ks++) {
            uint32_t af[4][4];
#pragma unroll
            for (int mt = 0; mt < 4; mt++)
                ldsm_x4(af[mt][0], af[mt][1], af[mt][2], af[mt][3],
                        st + A32_OFF + offA[ks][mt]);
            {
                uint32_t bf[4][2];
#pragma unroll
                for (int bt = 0; bt < 2; bt++)
                    ldsm_x4(bf[bt*2][0], bf[bt*2][1], bf[bt*2+1][0], bf[bt*2+1][1],
                            st + BZ32_OFF + offB[ks][bt]);
#pragma unroll
                for (int mt = 0; mt < 4; mt++)
#pragma unroll
                    for (int nt = 0; nt < 4; nt++)
                        mma_f16(accz[mt][nt], af[mt], bf[nt]);
            }
            {
                uint32_t bf[4][2];
#pragma unroll
                for (int bt = 0; bt < 2; bt++)
                    ldsm_x4(bf[bt*2][0], bf[bt*2][1], bf[bt*2+1][0], bf[bt*2+1][1],
                            st + BH32_OFF + offB[ks][bt]);
#pragma unroll
                for (int mt = 0; mt < 4; mt++)
#pragma unroll
                    for (int nt = 0; nt < 4; nt++)
                        mma_f16(acch[mt][nt], af[mt], bf[nt]);
            }
        }
    }

    gemm_epilogue(accz, acch, bz, bh, mBase, nBase, wr, wc, lane);
}

// ---------------- scan pass 1: per-chunk (A,B) summary (fp16 in, fp32 out) ---
__global__ __launch_bounds__(256)
void scan_pass1()
{
    const int g2 = blockIdx.x * 256 + threadIdx.x;   // (bc, d/2)
    const int bc = g2 >> 9;
    const int d0 = (g2 & 511) * 2;
    const size_t base = (size_t)bc * CHLEN * DD + d0;

    float2 Ar = make_float2(1.f, 1.f);
    float2 Br = make_float2(0.f, 0.f);
#pragma unroll 16
    for (int t = 0; t < CHLEN; t++) {
        const uint2 raw = *(const uint2*)&g_ab[base + (size_t)t * DD];
        const float2 ab0 = __half22float2(u32_to_h2(raw.x));
        const float2 ab1 = __half22float2(u32_to_h2(raw.y));
        Br.x = fmaf(ab0.x, Br.x, ab0.y); Ar.x *= ab0.x;
        Br.y = fmaf(ab1.x, Br.y, ab1.y); Ar.y *= ab1.x;
    }
    *(float2*)&g_Ac[(size_t)bc * DD + d0] = Ar;
    *(float2*)&g_Bc[(size_t)bc * DD + d0] = Br;
}

// ---------------- fused scan+swish+LN, y tile in SMEM (primary) --------------
__global__ __launch_bounds__(256)
void scan_ln_smem_kernel(const float* __restrict__ swish_beta,
                         const float* __restrict__ gamma,
                         const float* __restrict__ lbeta,
                         float* __restrict__ out)
{
    extern __shared__ uint2 s_y[];        // [CHLEN][256]
    const int bc = blockIdx.x;            // b*NCHUNK + chunk
    const int b = bc >> 5;
    const int chunk = bc & 31;
    const int tid = threadIdx.x;
    const int lane = tid & 31;
    const int w = tid >> 5;
    const int d0 = tid * 4;
    const float beta = __ldg(swish_beta);

    __shared__ float s1s[CHLEN][9], s2s[CHLEN][9];
    __shared__ float smu[CHLEN], sinv[CHLEN];

    // ---- hinit: prefix over predecessor chunk summaries ----
    float4 h = make_float4(0.f, 0.f, 0.f, 0.f);
    for (int c = 0; c < chunk; c++) {
        const size_t idx = (size_t)(b * NCHUNK + c) * DD + d0;
        const float4 A = *(const float4*)&g_Ac[idx];
        const float4 B = *(const float4*)&g_Bc[idx];
        h.x = fmaf(A.x, h.x, B.x);
        h.y = fmaf(A.y, h.y, B.y);
        h.z = fmaf(A.z, h.z, B.z);
        h.w = fmaf(A.w, h.w, B.w);
    }

    const size_t base = (size_t)(b * TT + chunk * CHLEN) * DD + d0;
    // depth-2 prefetch of ab
    uint4 r0 = *(const uint4*)&g_ab[base];
    uint4 r1 = *(const uint4*)&g_ab[base + (size_t)DD];

    // ---- Phase A: recurrence + swish; y->SMEM; per-(t,warp) sums->smem ----
    for (int t = 0; t < CHLEN; t++) {
        const float2 ab0 = __half22float2(u32_to_h2(r0.x));
        const float2 ab1 = __half22float2(u32_to_h2(r0.y));
        const float2 ab2 = __half22float2(u32_to_h2(r0.z));
        const float2 ab3 = __half22float2(u32_to_h2(r0.w));
        r0 = r1;
        if (t + 2 < CHLEN)
            r1 = *(const uint4*)&g_ab[base + (size_t)(t + 2) * DD];
        h.x = fmaf(ab0.x, h.x, ab0.y);
        h.y = fmaf(ab1.x, h.y, ab1.y);
        h.z = fmaf(ab2.x, h.z, ab2.y);
        h.w = fmaf(ab3.x, h.w, ab3.y);
        float4 y;
        {
            float s;
            s = beta * h.x; y.x = s * sigmoidf_fast(s);
            s = beta * h.y; y.y = s * sigmoidf_fast(s);
            s = beta * h.z; y.z = s * sigmoidf_fast(s);
            s = beta * h.w; y.w = s * sigmoidf_fast(s);
        }
        __half2 y0, y1;
        y0.x = __float2half_rn(y.x); y0.y = __float2half_rn(y.y);
        y1.x = __float2half_rn(y.z); y1.y = __float2half_rn(y.w);
        s_y[t * 256 + tid] = make_uint2(h2_to_u32(y0), h2_to_u32(y1));

        float s1 = y.x + y.y + y.z + y.w;
        float s2 = y.x * y.x + y.y * y.y + y.z * y.z + y.w * y.w;
#pragma unroll
        for (int o = 16; o > 0; o >>= 1) {
            s1 += __shfl_xor_sync(0xffffffffu, s1, o);
            s2 += __shfl_xor_sync(0xffffffffu, s2, o);
        }
        if (lane == 0) { s1s[t][w] = s1; s2s[t][w] = s2; }
    }
    __syncthreads();

    // finalize mu / inv per timestep (threads 0..63)
    if (tid < CHLEN) {
        float a1 = 0.0f, b1 = 0.0f;
#pragma unroll
        for (int j = 0; j < 8; j++) { a1 += s1s[tid][j]; b1 += s2s[tid][j]; }
        const float mu  = a1 * (1.0f / DD);
        const float var = b1 * (1.0f / DD) - mu * mu;
        smu[tid]  = mu;
        sinv[tid] = rsqrtf(var + 1e-5f);
    }
    __syncthreads();

    // ---- Phase B: normalize from SMEM ----
    const float4 gm = *(const float4*)&gamma[d0];
    const float4 bt = *(const float4*)&lbeta[d0];
#pragma unroll 4
    for (int t = 0; t < CHLEN; t++) {
        const uint2 yr = s_y[t * 256 + tid];
        const float2 ya = __half22float2(u32_to_h2(yr.x));
        const float2 yb = __half22float2(u32_to_h2(yr.y));
        const float mu  = smu[t];
        const float inv = sinv[t];
        float4 o;
        o.x = (ya.x - mu) * inv * gm.x + bt.x;
        o.y = (ya.y - mu) * inv * gm.y + bt.y;
        o.z = (yb.x - mu) * inv * gm.z + bt.z;
        o.w = (yb.y - mu) * inv * gm.w + bt.w;
        *(float4*)&out[base + (size_t)t * DD] = o;
    }
}

// ---------------- fallback scan_ln (gmem y16, proven R9) ----------------
__global__ __launch_bounds__(256)
void scan_ln_kernel(const float* __restrict__ swish_beta,
                    const float* __restrict__ gamma,
                    const float* __restrict__ lbeta,
                    float* __restrict__ out)
{
    const int bc = blockIdx.x;
    const int b = bc >> 5;
    const int chunk = bc & 31;
    const int tid = threadIdx.x;
    const int lane = tid & 31;
    const int w = tid >> 5;
    const int d0 = tid * 4;
    const float beta = __ldg(swish_beta);

    __shared__ float s1s[CHLEN][9], s2s[CHLEN][9];
    __shared__ float smu[CHLEN], sinv[CHLEN];

    float4 h = make_float4(0.f, 0.f, 0.f, 0.f);
    for (int c = 0; c < chunk; c++) {
        const size_t idx = (size_t)(b * NCHUNK + c) * DD + d0;
        const float4 A = *(const float4*)&g_Ac[idx];
        const float4 B = *(const float4*)&g_Bc[idx];
        h.x = fmaf(A.x, h.x, B.x);
        h.y = fmaf(A.y, h.y, B.y);
        h.z = fmaf(A.z, h.z, B.z);
        h.w = fmaf(A.w, h.w, B.w);
    }

    const size_t base = (size_t)(b * TT + chunk * CHLEN) * DD + d0;
    uint4 raw = *(const uint4*)&g_ab[base];

    for (int t = 0; t < CHLEN; t++) {
        const float2 ab0 = __half22float2(u32_to_h2(raw.x));
        const float2 ab1 = __half22float2(u32_to_h2(raw.y));
        const float2 ab2 = __half22float2(u32_to_h2(raw.z));
        const float2 ab3 = __half22float2(u32_to_h2(raw.w));
        h.x = fmaf(ab0.x, h.x, ab0.y);
        h.y = fmaf(ab1.x, h.y, ab1.y);
        h.z = fmaf(ab2.x, h.z, ab2.y);
        h.w = fmaf(ab3.x, h.w, ab3.y);
        float4 y;
        {
            float s;
            s = beta * h.x; y.x = s * sigmoidf_fast(s);
            s = beta * h.y; y.y = s * sigmoidf_fast(s);
            s = beta * h.z; y.z = s * sigmoidf_fast(s);
            s = beta * h.w; y.w = s * sigmoidf_fast(s);
        }
        if (t + 1 < CHLEN)
            raw = *(const uint4*)&g_ab[base + (size_t)(t + 1) * DD];

        __half2 y0, y1;
        y0.x = __float2half_rn(y.x); y0.y = __float2half_rn(y.y);
        y1.x = __float2half_rn(y.z); y1.y = __float2half_rn(y.w);
        *(uint2*)&g_y16[base + (size_t)t * DD] =
            make_uint2(h2_to_u32(y0), h2_to_u32(y1));

        float s1 = y.x + y.y + y.z + y.w;
        float s2 = y.x * y.x + y.y * y.y + y.z * y.z + y.w * y.w;
#pragma unroll
        for (int o = 16; o > 0; o >>= 1) {
            s1 += __shfl_xor_sync(0xffffffffu, s1, o);
            s2 += __shfl_xor_sync(0xffffffffu, s2, o);
        }
        if (lane == 0) { s1s[t][w] = s1; s2s[t][w] = s2; }
    }
    __syncthreads();

    if (tid < CHLEN) {
        float a1 = 0.0f, b1 = 0.0f;
#pragma unroll
        for (int j = 0; j < 8; j++) { a1 += s1s[tid][j]; b1 += s2s[tid][j]; }
        const float mu  = a1 * (1.0f / DD);
        const float var = b1 * (1.0f / DD) - mu * mu;
        smu[tid]  = mu;
        sinv[tid] = rsqrtf(var + 1e-5f);
    }
    __syncthreads();

    const float4 gm = *(const float4*)&gamma[d0];
    const float4 bt = *(const float4*)&lbeta[d0];
#pragma unroll 4
    for (int t = 0; t < CHLEN; t++) {
        const uint2 yr = *(const uint2*)&g_y16[base + (size_t)t * DD];
        const float2 ya = __half22float2(u32_to_h2(yr.x));
        const float2 yb = __half22float2(u32_to_h2(yr.y));
        const float mu  = smu[t];
        const float inv = sinv[t];
        float4 o;
        o.x = (ya.x - mu) * inv * gm.x + bt.x;
        o.y = (ya.y - mu) * inv * gm.y + bt.y;
        o.z = (yb.x - mu) * inv * gm.z + bt.z;
        o.w = (yb.y - mu) * inv * gm.w + bt.w;
        *(float4*)&out[base + (size_t)t * DD] = o;
    }
}

// ---------------- launch ----------------
extern "C" void kernel_launch(void* const* d_in, const int* in_sizes, int n_in,
                              void* d_out, int out_size)
{
    const float* x     = (const float*)d_in[0];
    const float* Wz    = (const float*)d_in[1];
    const float* bz    = (const float*)d_in[2];
    const float* Wh    = (const float*)d_in[3];
    const float* bh    = (const float*)d_in[4];
    const float* sbeta = (const float*)d_in[5];
    const float* gamma = (const float*)d_in[6];
    const float* lbeta = (const float*)d_in[7];
    float* out = (float*)d_out;

    convert_x_kernel<<<(MM * DD) / (256 * 4), 256>>>(x);
    transpose_kernel<<<dim3(32, 32, 2), 256>>>(Wz, Wh);

    dim3 gemmGrid(DD / 128, MM / 128);   // (8, 128)
    cudaError_t e = cudaFuncSetAttribute(
        gemm64_kernel, cudaFuncAttributeMaxDynamicSharedMemorySize, 2 * STAGE64);
    if (e == cudaSuccess) {
        gemm64_kernel<<<gemmGrid, 256, 2 * STAGE64>>>(bz, bh);
    } else {
        (void)cudaGetLastError();
        gemm32_kernel<<<gemmGrid, 256, 2 * STAGE32>>>(bz, bh);
    }

    scan_pass1<<<(BB * NCHUNK * DD) / (256 * 2), 256>>>();

    cudaError_t e2 = cudaFuncSetAttribute(
        scan_ln_smem_kernel, cudaFuncAttributeMaxDynamicSharedMemorySize, SMEM_Y);
    if (e2 == cudaSuccess) {
        scan_ln_smem_kernel<<<BB * NCHUNK, 256, SMEM_Y>>>(sbeta, gamma, lbeta, out);
    } else {
        (void)cudaGetLastError();
        scan_ln_kernel<<<BB * NCHUNK, 256>>>(sbeta, gamma, lbeta, out);
    }
}

// round 11
// speedup vs baseline: 1.0052x; 1.0052x over previous
#include <cuda_runtime.h>
#include <cuda_fp16.h>
#include <math.h>
#include <stdint.h>

// Problem shape (fixed): B=8, T=2048, D=1024
#define BB   8
#define TT   2048
#define DD   1024
#define MM   (BB*TT)          // 16384 rows
#define NCHUNK 32
#define CHLEN  64

// ---- BK=64 GEMM (primary): CTA 128x128, 2 outputs, warp 64x32x2 ----
#define NCH64   16
#define A64_OFF  0
#define BZ64_OFF 16384
#define BH64_OFF 32768
#define STAGE64  49152        // 48KB per stage; 2 stages = 96KB

// ---- BK=32 GEMM (fallback, 48KB default smem) ----
#define NCH32   32
#define A32_OFF  0
#define BZ32_OFF 8192
#define BH32_OFF 16384
#define STAGE32  24576

// ---------------- scratch (device globals) ----------------
__device__ __half2 g_ab[(size_t)MM * DD];   // {a, b} per element (fp16)
__device__ __half  g_y16[(size_t)MM * DD];  // swish output (fp16)
__device__ float   g_Ac[BB * NCHUNK * DD];  // chunk summaries (fp32)
__device__ float   g_Bc[BB * NCHUNK * DD];

__device__ __half g_xh[(size_t)MM * DD];    // x in fp16
__device__ __half g_Wtz[DD * DD];           // Wz^T fp16: [n][k]
__device__ __half g_Wth[DD * DD];           // Wh^T fp16: [n][k]

__device__ __forceinline__ float sigmoidf_fast(float v) {
    return 1.0f / (1.0f + __expf(-v));
}

// ---- bit casts ----
__device__ __forceinline__ uint32_t h2_to_u32(__half2 h) {
    return *reinterpret_cast<uint32_t*>(&h);
}
__device__ __forceinline__ __half2 u32_to_h2(uint32_t u) {
    return *reinterpret_cast<__half2*>(&u);
}

// ---------------- PTX helpers ----------------
__device__ __forceinline__ uint32_t smem_u32(const void* p) {
    uint32_t a;
    asm("{ .reg .u64 t; cvta.to.shared.u64 t, %1; cvt.u32.u64 %0, t; }" : "=r"(a) : "l"(p));
    return a;
}
#define SWZ64(o)  ((o) ^ (((o) >> 3) & 0x30))
#define SWZ128(o) ((o) ^ (((o) >> 3) & 0x70))

__device__ __forceinline__ void cp16(uint32_t s, const void* g) {
    asm volatile("cp.async.cg.shared.global [%0], [%1], 16;" :: "r"(s), "l"(g));
}
__device__ __forceinline__ void cp_commit() {
    asm volatile("cp.async.commit_group;" ::: "memory");
}
__device__ __forceinline__ void ldsm_x4(uint32_t& r0, uint32_t& r1, uint32_t& r2,
                                        uint32_t& r3, uint32_t addr) {
    asm volatile("ldmatrix.sync.aligned.m8n8.x4.shared.b16 {%0,%1,%2,%3}, [%4];"
                 : "=r"(r0), "=r"(r1), "=r"(r2), "=r"(r3) : "r"(addr));
}
__device__ __forceinline__ void mma_f16(float* d, const uint32_t* a, const uint32_t* b) {
    asm volatile(
        "mma.sync.aligned.m16n8k16.row.col.f32.f16.f16.f32 "
        "{%0,%1,%2,%3},{%4,%5,%6,%7},{%8,%9},{%0,%1,%2,%3};"
        : "+f"(d[0]), "+f"(d[1]), "+f"(d[2]), "+f"(d[3])
        : "r"(a[0]), "r"(a[1]), "r"(a[2]), "r"(a[3]), "r"(b[0]), "r"(b[1]));
}

// ---------------- prep: convert x to fp16 ----------------
__global__ __launch_bounds__(256)
void convert_x_kernel(const float* __restrict__ x)
{
    const size_t i4 = (size_t)blockIdx.x * 256 + threadIdx.x;
    const float4 v = ((const float4*)x)[i4];
    __half2 p0, p1;
    p0.x = __float2half_rn(v.x); p0.y = __float2half_rn(v.y);
    p1.x = __float2half_rn(v.z); p1.y = __float2half_rn(v.w);
    ((__half2*)g_xh)[i4 * 2]     = p0;
    ((__half2*)g_xh)[i4 * 2 + 1] = p1;
}

// ---------------- prep: transpose W -> Wt[n][k], fp16 ----------------
__global__ __launch_bounds__(256)
void transpose_kernel(const float* __restrict__ Wz, const float* __restrict__ Wh)
{
    __shared__ float sm[32][33];
    const float* W = (blockIdx.z == 0) ? Wz : Wh;
    __half* Wt = (blockIdx.z == 0) ? g_Wtz : g_Wth;

    const int k0 = blockIdx.y * 32;
    const int n0 = blockIdx.x * 32;
    const int r = threadIdx.x >> 5;
    const int c = threadIdx.x & 31;
#pragma unroll
    for (int rr = 0; rr < 4; rr++) {
        const int row = rr * 8 + r;
        sm[row][c] = W[(size_t)(k0 + row) * DD + n0 + c];
    }
    __syncthreads();
#pragma unroll
    for (int rr = 0; rr < 4; rr++) {
        const int row = rr * 8 + r;
        Wt[(size_t)(n0 + row) * DD + k0 + c] = __float2half_rn(sm[c][row]);
    }
}

// ---------------- fallback epilogue: {a,b} fp16 to gmem only ----------------
__device__ __forceinline__ void gemm_epilogue(
    float accz[4][4][4], float acch[4][4][4],
    const float* __restrict__ bz, const float* __restrict__ bh,
    int mBase, int nBase, int wr, int wc, int lane)
{
    const int er = lane >> 2;
    const int ec = (lane & 3) * 2;
#pragma unroll
    for (int mt = 0; mt < 4; mt++) {
#pragma unroll
        for (int nt = 0; nt < 4; nt++) {
            const int m = mBase + wr * 64 + mt * 16 + er;
            const int n = nBase + wc * 32 + nt * 8 + ec;
            const size_t g0 = (size_t)m * DD + n;
            const size_t g1 = g0 + 8 * DD;
            const float2 bz2 = *(const float2*)(&bz[n]);
            const float2 bh2 = *(const float2*)(&bh[n]);
            float z;
            __half2 p0, p1;
            z = sigmoidf_fast(accz[mt][nt][0] + bz2.x);
            p0.x = __float2half_rn(1.0f - z);
            p0.y = __float2half_rn(z * (acch[mt][nt][0] + bh2.x));
            z = sigmoidf_fast(accz[mt][nt][1] + bz2.y);
            p1.x = __float2half_rn(1.0f - z);
            p1.y = __float2half_rn(z * (acch[mt][nt][1] + bh2.y));
            *(uint2*)(&g_ab[g0]) = make_uint2(h2_to_u32(p0), h2_to_u32(p1));
            z = sigmoidf_fast(accz[mt][nt][2] + bz2.x);
            p0.x = __float2half_rn(1.0f - z);
            p0.y = __float2half_rn(z * (acch[mt][nt][2] + bh2.x));
            z = sigmoidf_fast(accz[mt][nt][3] + bz2.y);
            p1.x = __float2half_rn(1.0f - z);
            p1.y = __float2half_rn(z * (acch[mt][nt][3] + bh2.y));
            *(uint2*)(&g_ab[g1]) = make_uint2(h2_to_u32(p0), h2_to_u32(p1));
        }
    }
}

// ---------------- PRIMARY GEMM: BK=64, 2-stage, 96KB smem --------------------
// Epilogue also computes the per-chunk scan summaries (2 chunks/CTA) and
// writes g_Ac/g_Bc directly -> no separate scan_pass1 launch on this path.
__global__ __launch_bounds__(256, 1)
void gemm64_kernel(const float* __restrict__ bz, const float* __restrict__ bh)
{
    extern __shared__ char smem[];
    const uint32_t sbase = smem_u32(smem);
    const int tid  = threadIdx.x;
    const int wid  = tid >> 5;
    const int lane = tid & 31;
    const int wr = wid >> 2;
    const int wc = wid & 3;

    const int nBase = blockIdx.x * 128;
    const int mBase = blockIdx.y * 128;

    int ldRow[4];
    int ldCol[4];
    uint32_t ldOff[4];
#pragma unroll
    for (int t = 0; t < 4; t++) {
        const int o = tid + t * 256;
        ldRow[t] = o >> 3;
        ldCol[t] = o & 7;
        ldOff[t] = SWZ128((uint32_t)(o * 16));
    }

    const int quad = lane >> 3;
    const int r8   = lane & 7;
    const int rowA = (quad & 1) * 8 + r8;
    const int kbA  = (quad >> 1) * 16;
    const int rowB = (quad >> 1) * 8 + r8;
    const int kbB  = (quad & 1) * 16;

    uint32_t offA[4][4], offB[4][2];
#pragma unroll
    for (int ks = 0; ks < 4; ks++) {
#pragma unroll
        for (int mt = 0; mt < 4; mt++)
            offA[ks][mt] = SWZ128((uint32_t)((wr * 64 + mt * 16 + rowA) * 128 + ks * 32 + kbA));
#pragma unroll
        for (int bt = 0; bt < 2; bt++)
            offB[ks][bt] = SWZ128((uint32_t)((wc * 32 + bt * 16 + rowB) * 128 + ks * 32 + kbB));
    }

    float accz[4][4][4], acch[4][4][4];
#pragma unroll
    for (int i = 0; i < 4; i++)
#pragma unroll
        for (int j = 0; j < 4; j++)
#pragma unroll
            for (int k = 0; k < 4; k++) { accz[i][j][k] = 0.0f; acch[i][j][k] = 0.0f; }

    auto load_chunk = [&](int chunk, int stage) {
        const int k0 = chunk * 64;
        const uint32_t st = sbase + stage * STAGE64;
#pragma unroll
        for (int t = 0; t < 4; t++) {
            const size_t rowOff = (size_t)ldRow[t] * DD + k0 + ldCol[t] * 8;
            cp16(st + A64_OFF  + ldOff[t], g_xh  + (size_t)mBase * DD + rowOff);
            cp16(st + BZ64_OFF + ldOff[t], g_Wtz + (size_t)nBase * DD + rowOff);
            cp16(st + BH64_OFF + ldOff[t], g_Wth + (size_t)nBase * DD + rowOff);
        }
        cp_commit();
    };

    load_chunk(0, 0);

    for (int i = 0; i < NCH64; i++) {
        const int s = i & 1;
        asm volatile("cp.async.wait_group 0;" ::: "memory");
        __syncthreads();
        if (i + 1 < NCH64) load_chunk(i + 1, s ^ 1);

        const uint32_t st = sbase + s * STAGE64;
#pragma unroll
        for (int ks = 0; ks < 4; ks++) {
            uint32_t af[4][4];
#pragma unroll
            for (int mt = 0; mt < 4; mt++)
                ldsm_x4(af[mt][0], af[mt][1], af[mt][2], af[mt][3],
                        st + A64_OFF + offA[ks][mt]);
            {
                uint32_t bf[4][2];
#pragma unroll
                for (int bt = 0; bt < 2; bt++)
                    ldsm_x4(bf[bt*2][0], bf[bt*2][1], bf[bt*2+1][0], bf[bt*2+1][1],
                            st + BZ64_OFF + offB[ks][bt]);
#pragma unroll
                for (int mt = 0; mt < 4; mt++)
#pragma unroll
                    for (int nt = 0; nt < 4; nt++)
                        mma_f16(accz[mt][nt], af[mt], bf[nt]);
            }
            {
                uint32_t bf[4][2];
#pragma unroll
                for (int bt = 0; bt < 2; bt++)
                    ldsm_x4(bf[bt*2][0], bf[bt*2][1], bf[bt*2+1][0], bf[bt*2+1][1],
                            st + BH64_OFF + offB[ks][bt]);
#pragma unroll
                for (int mt = 0; mt < 4; mt++)
#pragma unroll
                    for (int nt = 0; nt < 4; nt++)
                        mma_f16(acch[mt][nt], af[mt], bf[nt]);
            }
        }
    }

    // ---- epilogue: g_ab to gmem + stage {a,b} into smem [128][129] ----
    __syncthreads();   // all warps done reading pipeline smem before reuse
    __half2* s_ab = (__half2*)smem;
    {
        const int er = lane >> 2;
        const int q2 = (lane & 3) * 2;
#pragma unroll
        for (int mt = 0; mt < 4; mt++) {
#pragma unroll
            for (int nt = 0; nt < 4; nt++) {
                const int tl0 = wr * 64 + mt * 16 + er;   // local timestep, half 0
                const int col = wc * 32 + nt * 8 + q2;
                const int n = nBase + col;
                const size_t g0 = (size_t)(mBase + tl0) * DD + n;
                const size_t g1 = g0 + 8 * DD;
                const float2 bz2 = *(const float2*)(&bz[n]);
                const float2 bh2 = *(const float2*)(&bh[n]);
                float z;
                __half2 p0, p1;
                z = sigmoidf_fast(accz[mt][nt][0] + bz2.x);
                p0.x = __float2half_rn(1.0f - z);
                p0.y = __float2half_rn(z * (acch[mt][nt][0] + bh2.x));
                z = sigmoidf_fast(accz[mt][nt][1] + bz2.y);
                p1.x = __float2half_rn(1.0f - z);
                p1.y = __float2half_rn(z * (acch[mt][nt][1] + bh2.y));
                *(uint2*)(&g_ab[g0]) = make_uint2(h2_to_u32(p0), h2_to_u32(p1));
                s_ab[tl0 * 129 + col]     = p0;
                s_ab[tl0 * 129 + col + 1] = p1;
                z = sigmoidf_fast(accz[mt][nt][2] + bz2.x);
                p0.x = __float2half_rn(1.0f - z);
                p0.y = __float2half_rn(z * (acch[mt][nt][2] + bh2.x));
                z = sigmoidf_fast(accz[mt][nt][3] + bz2.y);
                p1.x = __float2half_rn(1.0f - z);
                p1.y = __float2half_rn(z * (acch[mt][nt][3] + bh2.y));
                *(uint2*)(&g_ab[g1]) = make_uint2(h2_to_u32(p0), h2_to_u32(p1));
                s_ab[(tl0 + 8) * 129 + col]     = p0;
                s_ab[(tl0 + 8) * 129 + col + 1] = p1;
            }
        }
    }
    __syncthreads();

    // ---- per-chunk scan summaries: thread = (chunk_local, column) ----
    {
        const int ch = tid >> 7;          // 0..1 (two 64-step chunks per CTA)
        const int cl = tid & 127;
        float A = 1.0f, Bv = 0.0f;
#pragma unroll 8
        for (int t = 0; t < CHLEN; t++) {
            const float2 f = __half22float2(s_ab[(ch * 64 + t) * 129 + cl]);
            Bv = fmaf(f.x, Bv, f.y);
            A *= f.x;
        }
        const int bc = (mBase >> 6) + ch;   // global chunk index = m/64
        g_Ac[(size_t)bc * DD + nBase + cl] = A;
        g_Bc[(size_t)bc * DD + nBase + cl] = Bv;
    }
}

// ---------------- FALLBACK GEMM: BK=32, 2-stage, 48KB ------------
__global__ __launch_bounds__(256, 1)
void gemm32_kernel(const float* __restrict__ bz, const float* __restrict__ bh)
{
    extern __shared__ char smem[];
    const uint32_t sbase = smem_u32(smem);
    const int tid  = threadIdx.x;
    const int wid  = tid >> 5;
    const int lane = tid & 31;
    const int wr = wid >> 2;
    const int wc = wid & 3;

    const int nBase = blockIdx.x * 128;
    const int mBase = blockIdx.y * 128;

    int ldRow[2];
    int ldCol[2];
    uint32_t ldOff[2];
#pragma unroll
    for (int t = 0; t < 2; t++) {
        const int o = tid + t * 256;
        ldRow[t] = o >> 2;
        ldCol[t] = o & 3;
        ldOff[t] = SWZ64((uint32_t)(o * 16));
    }

    const int quad = lane >> 3;
    const int r8   = lane & 7;
    const int rowA = (quad & 1) * 8 + r8;
    const int kbA  = (quad >> 1) * 16;
    const int rowB = (quad >> 1) * 8 + r8;
    const int kbB  = (quad & 1) * 16;

    uint32_t offA[2][4], offB[2][2];
#pragma unroll
    for (int ks = 0; ks < 2; ks++) {
#pragma unroll
        for (int mt = 0; mt < 4; mt++)
            offA[ks][mt] = SWZ64((uint32_t)((wr * 64 + mt * 16 + rowA) * 64 + ks * 32 + kbA));
#pragma unroll
        for (int bt = 0; bt < 2; bt++)
            offB[ks][bt] = SWZ64((uint32_t)((wc * 32 + bt * 16 + rowB) * 64 + ks * 32 + kbB));
    }

    float accz[4][4][4], acch[4][4][4];
#pragma unroll
    for (int i = 0; i < 4; i++)
#pragma unroll
        for (int j = 0; j < 4; j++)
#pragma unroll
            for (int k = 0; k < 4; k++) { accz[i][j][k] = 0.0f; acch[i][j][k] = 0.0f; }

    auto load_chunk = [&](int chunk, int stage) {
        const int k0 = chunk * 32;
        const uint32_t st = sbase + stage * STAGE32;
#pragma unroll
        for (int t = 0; t < 2; t++) {
            const size_t rowOff = (size_t)ldRow[t] * DD + k0 + ldCol[t] * 8;
            cp16(st + A32_OFF  + ldOff[t], g_xh  + (size_t)mBase * DD + rowOff);
            cp16(st + BZ32_OFF + ldOff[t], g_Wtz + (size_t)nBase * DD + rowOff);
            cp16(st + BH32_OFF + ldOff[t], g_Wth + (size_t)nBase * DD + rowOff);
        }
        cp_commit();
    };

    load_chunk(0, 0);

    for (int i = 0; i < NCH32; i++) {
        const int s = i & 1;
        asm volatile("cp.async.wait_group 0;" ::: "memory");
        __syncthreads();
        if (i + 1 < NCH32) load_chunk(i + 1, s ^ 1);

        const uint32_t st = sbase + s * STAGE32;
#pragma unroll
        for (int ks = 0; ks < 2; ks++) {
            uint32_t af[4][4];
#pragma unroll
            for (int mt = 0; mt < 4; mt++)
                ldsm_x4(af[mt][0], af[mt][1], af[mt][2], af[mt][3],
                        st + A32_OFF + offA[ks][mt]);
            {
                uint32_t bf[4][2];
#pragma unroll
                for (int bt = 0; bt < 2; bt++)
                    ldsm_x4(bf[bt*2][0], bf[bt*2][1], bf[bt*2+1][0], bf[bt*2+1][1],
                            st + BZ32_OFF + offB[ks][bt]);
#pragma unroll
                for (int mt = 0; mt < 4; mt++)
#pragma unroll
                    for (int nt = 0; nt < 4; nt++)
                        mma_f16(accz[mt][nt], af[mt], bf[nt]);
            }
            {
                uint32_t bf[4][2];
#pragma unroll
                for (int bt = 0; bt < 2; bt++)
                    ldsm_x4(bf[bt*2][0], bf[bt*2][1], bf[bt*2+1][0], bf[bt*2+1][1],
                            st + BH32_OFF + offB[ks][bt]);
#pragma unroll
                for (int mt = 0; mt < 4; mt++)
#pragma unroll
                    for (int nt = 0; nt < 4; nt++)
                        mma_f16(acch[mt][nt], af[mt], bf[nt]);
            }
        }
    }

    gemm_epilogue(accz, acch, bz, bh, mBase, nBase, wr, wc, lane);
}

// ---------------- scan pass 1 (fallback path only) ----------------
__global__ __launch_bounds__(256)
void scan_pass1()
{
    const int g2 = blockIdx.x * 256 + threadIdx.x;   // (bc, d/2)
    const int bc = g2 >> 9;
    const int d0 = (g2 & 511) * 2;
    const size_t base = (size_t)bc * CHLEN * DD + d0;

    float2 Ar = make_float2(1.f, 1.f);
    float2 Br = make_float2(0.f, 0.f);
#pragma unroll 16
    for (int t = 0; t < CHLEN; t++) {
        const uint2 raw = *(const uint2*)&g_ab[base + (size_t)t * DD];
        const float2 ab0 = __half22float2(u32_to_h2(raw.x));
        const float2 ab1 = __half22float2(u32_to_h2(raw.y));
        Br.x = fmaf(ab0.x, Br.x, ab0.y); Ar.x *= ab0.x;
        Br.y = fmaf(ab1.x, Br.y, ab1.y); Ar.y *= ab1.x;
    }
    *(float2*)&g_Ac[(size_t)bc * DD + d0] = Ar;
    *(float2*)&g_Bc[(size_t)bc * DD + d0] = Br;
}

// ---------------- fused: chunk-prefix + scan + swish + LayerNorm -------------
__global__ __launch_bounds__(256)
void scan_ln_kernel(const float* __restrict__ swish_beta,
                    const float* __restrict__ gamma,
                    const float* __restrict__ lbeta,
                    float* __restrict__ out)
{
    const int bc = blockIdx.x;            // b*NCHUNK + chunk
    const int b = bc >> 5;
    const int chunk = bc & 31;
    const int tid = threadIdx.x;
    const int lane = tid & 31;
    const int w = tid >> 5;
    const int d0 = tid * 4;
    const float beta = __ldg(swish_beta);

    __shared__ float s1s[CHLEN][9], s2s[CHLEN][9];
    __shared__ float smu[CHLEN], sinv[CHLEN];

    // ---- hinit: prefix over predecessor chunk summaries ----
    float4 h = make_float4(0.f, 0.f, 0.f, 0.f);
    for (int c = 0; c < chunk; c++) {
        const size_t idx = (size_t)(b * NCHUNK + c) * DD + d0;
        const float4 A = *(const float4*)&g_Ac[idx];
        const float4 B = *(const float4*)&g_Bc[idx];
        h.x = fmaf(A.x, h.x, B.x);
        h.y = fmaf(A.y, h.y, B.y);
        h.z = fmaf(A.z, h.z, B.z);
        h.w = fmaf(A.w, h.w, B.w);
    }

    const size_t base = (size_t)(b * TT + chunk * CHLEN) * DD + d0;
    uint4 raw = *(const uint4*)&g_ab[base];

    // ---- Phase A: recurrence + swish; y->gmem fp16; warp sums->smem ----
    for (int t = 0; t < CHLEN; t++) {
        const float2 ab0 = __half22float2(u32_to_h2(raw.x));
        const float2 ab1 = __half22float2(u32_to_h2(raw.y));
        const float2 ab2 = __half22float2(u32_to_h2(raw.z));
        const float2 ab3 = __half22float2(u32_to_h2(raw.w));
        h.x = fmaf(ab0.x, h.x, ab0.y);
        h.y = fmaf(ab1.x, h.y, ab1.y);
        h.z = fmaf(ab2.x, h.z, ab2.y);
        h.w = fmaf(ab3.x, h.w, ab3.y);
        float4 y;
        {
            float s;
            s = beta * h.x; y.x = s * sigmoidf_fast(s);
            s = beta * h.y; y.y = s * sigmoidf_fast(s);
            s = beta * h.z; y.z = s * sigmoidf_fast(s);
            s = beta * h.w; y.w = s * sigmoidf_fast(s);
        }
        if (t + 1 < CHLEN)
            raw = *(const uint4*)&g_ab[base + (size_t)(t + 1) * DD];

        __half2 y0, y1;
        y0.x = __float2half_rn(y.x); y0.y = __float2half_rn(y.y);
        y1.x = __float2half_rn(y.z); y1.y = __float2half_rn(y.w);
        *(uint2*)&g_y16[base + (size_t)t * DD] =
            make_uint2(h2_to_u32(y0), h2_to_u32(y1));

        float s1 = y.x + y.y + y.z + y.w;
        float s2 = y.x * y.x + y.y * y.y + y.z * y.z + y.w * y.w;
#pragma unroll
        for (int o = 16; o > 0; o >>= 1) {
            s1 += __shfl_xor_sync(0xffffffffu, s1, o);
            s2 += __shfl_xor_sync(0xffffffffu, s2, o);
        }
        if (lane == 0) { s1s[t][w] = s1; s2s[t][w] = s2; }
    }
    __syncthreads();

    if (tid < CHLEN) {
        float a1 = 0.0f, b1 = 0.0f;
#pragma unroll
        for (int j = 0; j < 8; j++) { a1 += s1s[tid][j]; b1 += s2s[tid][j]; }
        const float mu  = a1 * (1.0f / DD);
        const float var = b1 * (1.0f / DD) - mu * mu;
        smu[tid]  = mu;
        sinv[tid] = rsqrtf(var + 1e-5f);
    }
    __syncthreads();

    const float4 gm = *(const float4*)&gamma[d0];
    const float4 bt = *(const float4*)&lbeta[d0];
#pragma unroll 4
    for (int t = 0; t < CHLEN; t++) {
        const uint2 yr = *(const uint2*)&g_y16[base + (size_t)t * DD];
        const float2 ya = __half22float2(u32_to_h2(yr.x));
        const float2 yb = __half22float2(u32_to_h2(yr.y));
        const float mu  = smu[t];
        const float inv = sinv[t];
        float4 o;
        o.x = (ya.x - mu) * inv * gm.x + bt.x;
        o.y = (ya.y - mu) * inv * gm.y + bt.y;
        o.z = (yb.x - mu) * inv * gm.z + bt.z;
        o.w = (yb.y - mu) * inv * gm.w + bt.w;
        *(float4*)&out[base + (size_t)t * DD] = o;
    }
}

// ---------------- launch ----------------
extern "C" void kernel_launch(void* const* d_in, const int* in_sizes, int n_in,
                              void* d_out, int out_size)
{
    const float* x     = (const float*)d_in[0];
    const float* Wz    = (const float*)d_in[1];
    const float* bz    = (const float*)d_in[2];
    const float* Wh    = (const float*)d_in[3];
    const float* bh    = (const float*)d_in[4];
    const float* sbeta = (const float*)d_in[5];
    const float* gamma = (const float*)d_in[6];
    const float* lbeta = (const float*)d_in[7];
    float* out = (float*)d_out;

    convert_x_kernel<<<(MM * DD) / (256 * 4), 256>>>(x);
    transpose_kernel<<<dim3(32, 32, 2), 256>>>(Wz, Wh);

    dim3 gemmGrid(DD / 128, MM / 128);   // (8, 128)
    cudaError_t e = cudaFuncSetAttribute(
        gemm64_kernel, cudaFuncAttributeMaxDynamicSharedMemorySize, 2 * STAGE64);
    if (e == cudaSuccess) {
        gemm64_kernel<<<gemmGrid, 256, 2 * STAGE64>>>(bz, bh);
        // summaries computed in-kernel; no scan_pass1 needed
    } else {
        (void)cudaGetLastError();
        gemm32_kernel<<<gemmGrid, 256, 2 * STAGE32>>>(bz, bh);
        scan_pass1<<<(BB * NCHUNK * DD) / (256 * 2), 256>>>();
    }

    scan_ln_kernel<<<BB * NCHUNK, 256>>>(sbeta, gamma, lbeta, out);
}

// round 12
// speedup vs baseline: 1.0070x; 1.0018x over previous
#include <cuda_runtime.h>
#include <cuda_fp16.h>
#include <math.h>
#include <stdint.h>

// Problem shape (fixed): B=8, T=2048, D=1024
#define BB   8
#define TT   2048
#define DD   1024
#define MM   (BB*TT)          // 16384 rows
#define NCHUNK 32
#define CHLEN  64

// ---- BK=64 GEMM (primary): CTA 128x128, 2 outputs, warp 64x32x2 ----
#define NCH64   16
#define A64_OFF  0
#define BZ64_OFF 16384
#define BH64_OFF 32768
#define STAGE64  49152        // 48KB per stage; 2 stages = 96KB

// ---- BK=32 GEMM (fallback, 48KB default smem) ----
#define NCH32   32
#define A32_OFF  0
#define BZ32_OFF 8192
#define BH32_OFF 16384
#define STAGE32  24576

// ---------------- scratch (device globals) ----------------
__device__ __half2 g_ab[(size_t)MM * DD];   // {a, b} per element (fp16)
__device__ __half  g_y16[(size_t)MM * DD];  // swish output (fp16)
__device__ float   g_Ac[BB * NCHUNK * DD];  // chunk summaries (fp32)
__device__ float   g_Bc[BB * NCHUNK * DD];

__device__ __half g_xh[(size_t)MM * DD];    // x in fp16
__device__ __half g_Wtz[DD * DD];           // Wz^T fp16: [n][k]
__device__ __half g_Wth[DD * DD];           // Wh^T fp16: [n][k]

__device__ __forceinline__ float sigmoidf_fast(float v) {
    return 1.0f / (1.0f + __expf(-v));
}

// ---- bit casts ----
__device__ __forceinline__ uint32_t h2_to_u32(__half2 h) {
    return *reinterpret_cast<uint32_t*>(&h);
}
__device__ __forceinline__ __half2 u32_to_h2(uint32_t u) {
    return *reinterpret_cast<__half2*>(&u);
}

// ---------------- PTX helpers ----------------
__device__ __forceinline__ uint32_t smem_u32(const void* p) {
    uint32_t a;
    asm("{ .reg .u64 t; cvta.to.shared.u64 t, %1; cvt.u32.u64 %0, t; }" : "=r"(a) : "l"(p));
    return a;
}
#define SWZ64(o)  ((o) ^ (((o) >> 3) & 0x30))
#define SWZ128(o) ((o) ^ (((o) >> 3) & 0x70))

__device__ __forceinline__ void cp16(uint32_t s, const void* g) {
    asm volatile("cp.async.cg.shared.global [%0], [%1], 16;" :: "r"(s), "l"(g));
}
__device__ __forceinline__ void cp_commit() {
    asm volatile("cp.async.commit_group;" ::: "memory");
}
__device__ __forceinline__ void ldsm_x4(uint32_t& r0, uint32_t& r1, uint32_t& r2,
                                        uint32_t& r3, uint32_t addr) {
    asm volatile("ldmatrix.sync.aligned.m8n8.x4.shared.b16 {%0,%1,%2,%3}, [%4];"
                 : "=r"(r0), "=r"(r1), "=r"(r2), "=r"(r3) : "r"(addr));
}
__device__ __forceinline__ void mma_f16(float* d, const uint32_t* a, const uint32_t* b) {
    asm volatile(
        "mma.sync.aligned.m16n8k16.row.col.f32.f16.f16.f32 "
        "{%0,%1,%2,%3},{%4,%5,%6,%7},{%8,%9},{%0,%1,%2,%3};"
        : "+f"(d[0]), "+f"(d[1]), "+f"(d[2]), "+f"(d[3])
        : "r"(a[0]), "r"(a[1]), "r"(a[2]), "r"(a[3]), "r"(b[0]), "r"(b[1]));
}

// ---------------- prep: convert x to fp16 ----------------
__global__ __launch_bounds__(256)
void convert_x_kernel(const float* __restrict__ x)
{
    const size_t i4 = (size_t)blockIdx.x * 256 + threadIdx.x;
    const float4 v = ((const float4*)x)[i4];
    __half2 p0, p1;
    p0.x = __float2half_rn(v.x); p0.y = __float2half_rn(v.y);
    p1.x = __float2half_rn(v.z); p1.y = __float2half_rn(v.w);
    ((__half2*)g_xh)[i4 * 2]     = p0;
    ((__half2*)g_xh)[i4 * 2 + 1] = p1;
}

// ---------------- prep: transpose W -> Wt[n][k], fp16 ----------------
__global__ __launch_bounds__(256)
void transpose_kernel(const float* __restrict__ Wz, const float* __restrict__ Wh)
{
    __shared__ float sm[32][33];
    const float* W = (blockIdx.z == 0) ? Wz : Wh;
    __half* Wt = (blockIdx.z == 0) ? g_Wtz : g_Wth;

    const int k0 = blockIdx.y * 32;
    const int n0 = blockIdx.x * 32;
    const int r = threadIdx.x >> 5;
    const int c = threadIdx.x & 31;
#pragma unroll
    for (int rr = 0; rr < 4; rr++) {
        const int row = rr * 8 + r;
        sm[row][c] = W[(size_t)(k0 + row) * DD + n0 + c];
    }
    __syncthreads();
#pragma unroll
    for (int rr = 0; rr < 4; rr++) {
        const int row = rr * 8 + r;
        Wt[(size_t)(n0 + row) * DD + k0 + c] = __float2half_rn(sm[c][row]);
    }
}

// ---------------- fallback epilogue: {a,b} fp16 to gmem only ----------------
__device__ __forceinline__ void gemm_epilogue(
    float accz[4][4][4], float acch[4][4][4],
    const float* __restrict__ bz, const float* __restrict__ bh,
    int mBase, int nBase, int wr, int wc, int lane)
{
    const int er = lane >> 2;
    const int ec = (lane & 3) * 2;
#pragma unroll
    for (int mt = 0; mt < 4; mt++) {
#pragma unroll
        for (int nt = 0; nt < 4; nt++) {
            const int m = mBase + wr * 64 + mt * 16 + er;
            const int n = nBase + wc * 32 + nt * 8 + ec;
            const size_t g0 = (size_t)m * DD + n;
            const size_t g1 = g0 + 8 * DD;
            const float2 bz2 = *(const float2*)(&bz[n]);
            const float2 bh2 = *(const float2*)(&bh[n]);
            float z;
            __half2 p0, p1;
            z = sigmoidf_fast(accz[mt][nt][0] + bz2.x);
            p0.x = __float2half_rn(1.0f - z);
            p0.y = __float2half_rn(z * (acch[mt][nt][0] + bh2.x));
            z = sigmoidf_fast(accz[mt][nt][1] + bz2.y);
            p1.x = __float2half_rn(1.0f - z);
            p1.y = __float2half_rn(z * (acch[mt][nt][1] + bh2.y));
            *(uint2*)(&g_ab[g0]) = make_uint2(h2_to_u32(p0), h2_to_u32(p1));
            z = sigmoidf_fast(accz[mt][nt][2] + bz2.x);
            p0.x = __float2half_rn(1.0f - z);
            p0.y = __float2half_rn(z * (acch[mt][nt][2] + bh2.x));
            z = sigmoidf_fast(accz[mt][nt][3] + bz2.y);
            p1.x = __float2half_rn(1.0f - z);
            p1.y = __float2half_rn(z * (acch[mt][nt][3] + bh2.y));
            *(uint2*)(&g_ab[g1]) = make_uint2(h2_to_u32(p0), h2_to_u32(p1));
        }
    }
}

// ---------------- PRIMARY GEMM: BK=64, 2-stage, 96KB smem --------------------
// Epilogue also computes the per-chunk scan summaries (2 chunks/CTA) and
// writes g_Ac/g_Bc directly -> no separate scan_pass1 launch on this path.
__global__ __launch_bounds__(256, 1)
void gemm64_kernel(const float* __restrict__ bz, const float* __restrict__ bh)
{
    extern __shared__ char smem[];
    const uint32_t sbase = smem_u32(smem);
    const int tid  = threadIdx.x;
    const int wid  = tid >> 5;
    const int lane = tid & 31;
    const int wr = wid >> 2;
    const int wc = wid & 3;

    const int nBase = blockIdx.x * 128;
    const int mBase = blockIdx.y * 128;

    int ldRow[4];
    int ldCol[4];
    uint32_t ldOff[4];
#pragma unroll
    for (int t = 0; t < 4; t++) {
        const int o = tid + t * 256;
        ldRow[t] = o >> 3;
        ldCol[t] = o & 7;
        ldOff[t] = SWZ128((uint32_t)(o * 16));
    }

    const int quad = lane >> 3;
    const int r8   = lane & 7;
    const int rowA = (quad & 1) * 8 + r8;
    const int kbA  = (quad >> 1) * 16;
    const int rowB = (quad >> 1) * 8 + r8;
    const int kbB  = (quad & 1) * 16;

    uint32_t offA[4][4], offB[4][2];
#pragma unroll
    for (int ks = 0; ks < 4; ks++) {
#pragma unroll
        for (int mt = 0; mt < 4; mt++)
            offA[ks][mt] = SWZ128((uint32_t)((wr * 64 + mt * 16 + rowA) * 128 + ks * 32 + kbA));
#pragma unroll
        for (int bt = 0; bt < 2; bt++)
            offB[ks][bt] = SWZ128((uint32_t)((wc * 32 + bt * 16 + rowB) * 128 + ks * 32 + kbB));
    }

    float accz[4][4][4], acch[4][4][4];
#pragma unroll
    for (int i = 0; i < 4; i++)
#pragma unroll
        for (int j = 0; j < 4; j++)
#pragma unroll
            for (int k = 0; k < 4; k++) { accz[i][j][k] = 0.0f; acch[i][j][k] = 0.0f; }

    auto load_chunk = [&](int chunk, int stage) {
        const int k0 = chunk * 64;
        const uint32_t st = sbase + stage * STAGE64;
#pragma unroll
        for (int t = 0; t < 4; t++) {
            const size_t rowOff = (size_t)ldRow[t] * DD + k0 + ldCol[t] * 8;
            cp16(st + A64_OFF  + ldOff[t], g_xh  + (size_t)mBase * DD + rowOff);
            cp16(st + BZ64_OFF + ldOff[t], g_Wtz + (size_t)nBase * DD + rowOff);
            cp16(st + BH64_OFF + ldOff[t], g_Wth + (size_t)nBase * DD + rowOff);
        }
        cp_commit();
    };

    load_chunk(0, 0);

    for (int i = 0; i < NCH64; i++) {
        const int s = i & 1;
        asm volatile("cp.async.wait_group 0;" ::: "memory");
        __syncthreads();
        if (i + 1 < NCH64) load_chunk(i + 1, s ^ 1);

        const uint32_t st = sbase + s * STAGE64;
#pragma unroll
        for (int ks = 0; ks < 4; ks++) {
            uint32_t af[4][4];
#pragma unroll
            for (int mt = 0; mt < 4; mt++)
                ldsm_x4(af[mt][0], af[mt][1], af[mt][2], af[mt][3],
                        st + A64_OFF + offA[ks][mt]);
            {
                uint32_t bf[4][2];
#pragma unroll
                for (int bt = 0; bt < 2; bt++)
                    ldsm_x4(bf[bt*2][0], bf[bt*2][1], bf[bt*2+1][0], bf[bt*2+1][1],
                            st + BZ64_OFF + offB[ks][bt]);
#pragma unroll
                for (int mt = 0; mt < 4; mt++)
#pragma unroll
                    for (int nt = 0; nt < 4; nt++)
                        mma_f16(accz[mt][nt], af[mt], bf[nt]);
            }
            {
                uint32_t bf[4][2];
#pragma unroll
                for (int bt = 0; bt < 2; bt++)
                    ldsm_x4(bf[bt*2][0], bf[bt*2][1], bf[bt*2+1][0], bf[bt*2+1][1],
                            st + BH64_OFF + offB[ks][bt]);
#pragma unroll
                for (int mt = 0; mt < 4; mt++)
#pragma unroll
                    for (int nt = 0; nt < 4; nt++)
                        mma_f16(acch[mt][nt], af[mt], bf[nt]);
            }
        }
    }

    // ---- epilogue: g_ab to gmem + stage {a,b} into smem [128][129] ----
    __syncthreads();   // all warps done reading pipeline smem before reuse
    __half2* s_ab = (__half2*)smem;
    {
        const int er = lane >> 2;
        const int q2 = (lane & 3) * 2;
#pragma unroll
        for (int mt = 0; mt < 4; mt++) {
#pragma unroll
            for (int nt = 0; nt < 4; nt++) {
                const int tl0 = wr * 64 + mt * 16 + er;   // local timestep, half 0
                const int col = wc * 32 + nt * 8 + q2;
                const int n = nBase + col;
                const size_t g0 = (size_t)(mBase + tl0) * DD + n;
                const size_t g1 = g0 + 8 * DD;
                const float2 bz2 = *(const float2*)(&bz[n]);
                const float2 bh2 = *(const float2*)(&bh[n]);
                float z;
                __half2 p0, p1;
                z = sigmoidf_fast(accz[mt][nt][0] + bz2.x);
                p0.x = __float2half_rn(1.0f - z);
                p0.y = __float2half_rn(z * (acch[mt][nt][0] + bh2.x));
                z = sigmoidf_fast(accz[mt][nt][1] + bz2.y);
                p1.x = __float2half_rn(1.0f - z);
                p1.y = __float2half_rn(z * (acch[mt][nt][1] + bh2.y));
                *(uint2*)(&g_ab[g0]) = make_uint2(h2_to_u32(p0), h2_to_u32(p1));
                s_ab[tl0 * 129 + col]     = p0;
                s_ab[tl0 * 129 + col + 1] = p1;
                z = sigmoidf_fast(accz[mt][nt][2] + bz2.x);
                p0.x = __float2half_rn(1.0f - z);
                p0.y = __float2half_rn(z * (acch[mt][nt][2] + bh2.x));
                z = sigmoidf_fast(accz[mt][nt][3] + bz2.y);
                p1.x = __float2half_rn(1.0f - z);
                p1.y = __float2half_rn(z * (acch[mt][nt][3] + bh2.y));
                *(uint2*)(&g_ab[g1]) = make_uint2(h2_to_u32(p0), h2_to_u32(p1));
                s_ab[(tl0 + 8) * 129 + col]     = p0;
                s_ab[(tl0 + 8) * 129 + col + 1] = p1;
            }
        }
    }
    __syncthreads();

    // ---- per-chunk scan summaries: thread = (chunk_local, column) ----
    {
        const int ch = tid >> 7;          // 0..1 (two 64-step chunks per CTA)
        const int cl = tid & 127;
        float A = 1.0f, Bv = 0.0f;
#pragma unroll 8
        for (int t = 0; t < CHLEN; t++) {
            const float2 f = __half22float2(s_ab[(ch * 64 + t) * 129 + cl]);
            Bv = fmaf(f.x, Bv, f.y);
            A *= f.x;
        }
        const int bc = (mBase >> 6) + ch;   // global chunk index = m/64
        g_Ac[(size_t)bc * DD + nBase + cl] = A;
        g_Bc[(size_t)bc * DD + nBase + cl] = Bv;
    }
}

// ---------------- FALLBACK GEMM: BK=32, 2-stage, 48KB ------------
__global__ __launch_bounds__(256, 1)
void gemm32_kernel(const float* __restrict__ bz, const float* __restrict__ bh)
{
    extern __shared__ char smem[];
    const uint32_t sbase = smem_u32(smem);
    const int tid  = threadIdx.x;
    const int wid  = tid >> 5;
    const int lane = tid & 31;
    const int wr = wid >> 2;
    const int wc = wid & 3;

    const int nBase = blockIdx.x * 128;
    const int mBase = blockIdx.y * 128;

    int ldRow[2];
    int ldCol[2];
    uint32_t ldOff[2];
#pragma unroll
    for (int t = 0; t < 2; t++) {
        const int o = tid + t * 256;
        ldRow[t] = o >> 2;
        ldCol[t] = o & 3;
        ldOff[t] = SWZ64((uint32_t)(o * 16));
    }

    const int quad = lane >> 3;
    const int r8   = lane & 7;
    const int rowA = (quad & 1) * 8 + r8;
    const int kbA  = (quad >> 1) * 16;
    const int rowB = (quad >> 1) * 8 + r8;
    const int kbB  = (quad & 1) * 16;

    uint32_t offA[2][4], offB[2][2];
#pragma unroll
    for (int ks = 0; ks < 2; ks++) {
#pragma unroll
        for (int mt = 0; mt < 4; mt++)
            offA[ks][mt] = SWZ64((uint32_t)((wr * 64 + mt * 16 + rowA) * 64 + ks * 32 + kbA));
#pragma unroll
        for (int bt = 0; bt < 2; bt++)
            offB[ks][bt] = SWZ64((uint32_t)((wc * 32 + bt * 16 + rowB) * 64 + ks * 32 + kbB));
    }

    float accz[4][4][4], acch[4][4][4];
#pragma unroll
    for (int i = 0; i < 4; i++)
#pragma unroll
        for (int j = 0; j < 4; j++)
#pragma unroll
            for (int k = 0; k < 4; k++) { accz[i][j][k] = 0.0f; acch[i][j][k] = 0.0f; }

    auto load_chunk = [&](int chunk, int stage) {
        const int k0 = chunk * 32;
        const uint32_t st = sbase + stage * STAGE32;
#pragma unroll
        for (int t = 0; t < 2; t++) {
            const size_t rowOff = (size_t)ldRow[t] * DD + k0 + ldCol[t] * 8;
            cp16(st + A32_OFF  + ldOff[t], g_xh  + (size_t)mBase * DD + rowOff);
            cp16(st + BZ32_OFF + ldOff[t], g_Wtz + (size_t)nBase * DD + rowOff);
            cp16(st + BH32_OFF + ldOff[t], g_Wth + (size_t)nBase * DD + rowOff);
        }
        cp_commit();
    };

    load_chunk(0, 0);

    for (int i = 0; i < NCH32; i++) {
        const int s = i & 1;
        asm volatile("cp.async.wait_group 0;" ::: "memory");
        __syncthreads();
        if (i + 1 < NCH32) load_chunk(i + 1, s ^ 1);

        const uint32_t st = sbase + s * STAGE32;
#pragma unroll
        for (int ks = 0; ks < 2; ks++) {
            uint32_t af[4][4];
#pragma unroll
            for (int mt = 0; mt < 4; mt++)
                ldsm_x4(af[mt][0], af[mt][1], af[mt][2], af[mt][3],
                        st + A32_OFF + offA[ks][mt]);
            {
                uint32_t bf[4][2];
#pragma unroll
                for (int bt = 0; bt < 2; bt++)
                    ldsm_x4(bf[bt*2][0], bf[bt*2][1], bf[bt*2+1][0], bf[bt*2+1][1],
                            st + BZ32_OFF + offB[ks][bt]);
#pragma unroll
                for (int mt = 0; mt < 4; mt++)
#pragma unroll
                    for (int nt = 0; nt < 4; nt++)
                        mma_f16(accz[mt][nt], af[mt], bf[nt]);
            }
            {
                uint32_t bf[4][2];
#pragma unroll
                for (int bt = 0; bt < 2; bt++)
                    ldsm_x4(bf[bt*2][0], bf[bt*2][1], bf[bt*2+1][0], bf[bt*2+1][1],
                            st + BH32_OFF + offB[ks][bt]);
#pragma unroll
                for (int mt = 0; mt < 4; mt++)
#pragma unroll
                    for (int nt = 0; nt < 4; nt++)
                        mma_f16(acch[mt][nt], af[mt], bf[nt]);
            }
        }
    }

    gemm_epilogue(accz, acch, bz, bh, mBase, nBase, wr, wc, lane);
}

// ---------------- scan pass 1 (fallback path only) ----------------
__global__ __launch_bounds__(256)
void scan_pass1()
{
    const int g2 = blockIdx.x * 256 + threadIdx.x;   // (bc, d/2)
    const int bc = g2 >> 9;
    const int d0 = (g2 & 511) * 2;
    const size_t base = (size_t)bc * CHLEN * DD + d0;

    float2 Ar = make_float2(1.f, 1.f);
    float2 Br = make_float2(0.f, 0.f);
#pragma unroll 16
    for (int t = 0; t < CHLEN; t++) {
        const uint2 raw = *(const uint2*)&g_ab[base + (size_t)t * DD];
        const float2 ab0 = __half22float2(u32_to_h2(raw.x));
        const float2 ab1 = __half22float2(u32_to_h2(raw.y));
        Br.x = fmaf(ab0.x, Br.x, ab0.y); Ar.x *= ab0.x;
        Br.y = fmaf(ab1.x, Br.y, ab1.y); Ar.y *= ab1.x;
    }
    *(float2*)&g_Ac[(size_t)bc * DD + d0] = Ar;
    *(float2*)&g_Bc[(size_t)bc * DD + d0] = Br;
}

// ---------------- scan + swish (d-parallel, no barriers) ----------------
// thread = (bc, d pair). hinit via prefix over chunk summaries, then 64 steps.
__global__ __launch_bounds__(256)
void scan_swish_kernel(const float* __restrict__ swish_beta)
{
    const int g2 = blockIdx.x * 256 + threadIdx.x;   // (bc, d/2)
    const int bc = g2 >> 9;
    const int d0 = (g2 & 511) * 2;
    const int b = bc >> 5;
    const int chunk = bc & 31;
    const float beta = __ldg(swish_beta);

    // hinit: prefix over predecessor chunk summaries (uniform trip in CTA)
    float2 h = make_float2(0.f, 0.f);
    for (int c = 0; c < chunk; c++) {
        const size_t idx = (size_t)(b * NCHUNK + c) * DD + d0;
        const float2 A = *(const float2*)&g_Ac[idx];
        const float2 B = *(const float2*)&g_Bc[idx];
        h.x = fmaf(A.x, h.x, B.x);
        h.y = fmaf(A.y, h.y, B.y);
    }

    const size_t base = (size_t)bc * CHLEN * DD + d0;
#pragma unroll 8
    for (int t = 0; t < CHLEN; t++) {
        const uint2 raw = *(const uint2*)&g_ab[base + (size_t)t * DD];
        const float2 ab0 = __half22float2(u32_to_h2(raw.x));
        const float2 ab1 = __half22float2(u32_to_h2(raw.y));
        h.x = fmaf(ab0.x, h.x, ab0.y);
        h.y = fmaf(ab1.x, h.y, ab1.y);
        float s;
        __half2 y2;
        s = beta * h.x; y2.x = __float2half_rn(s * sigmoidf_fast(s));
        s = beta * h.y; y2.y = __float2half_rn(s * sigmoidf_fast(s));
        *(__half2*)&g_y16[base + (size_t)t * DD] = y2;
    }
}

// ---------------- LayerNorm: one CTA per row, y16 in, fp32 out ----------------
__global__ __launch_bounds__(256)
void ln_kernel(const float* __restrict__ gamma,
               const float* __restrict__ lbeta,
               float* __restrict__ out)
{
    const int row = blockIdx.x;
    const int tid = threadIdx.x;
    const int lane = tid & 31;
    const int w = tid >> 5;
    const int d0 = tid * 4;

    const uint2 yr = *(const uint2*)&g_y16[(size_t)row * DD + d0];
    const float2 ya = __half22float2(u32_to_h2(yr.x));
    const float2 yb = __half22float2(u32_to_h2(yr.y));

    float s1 = ya.x + ya.y + yb.x + yb.y;
    float s2 = ya.x * ya.x + ya.y * ya.y + yb.x * yb.x + yb.y * yb.y;
#pragma unroll
    for (int o = 16; o > 0; o >>= 1) {
        s1 += __shfl_xor_sync(0xffffffffu, s1, o);
        s2 += __shfl_xor_sync(0xffffffffu, s2, o);
    }
    __shared__ float sa[8], sb[8];
    if (lane == 0) { sa[w] = s1; sb[w] = s2; }
    __syncthreads();
    if (w == 0) {
        float a1 = (lane < 8) ? sa[lane] : 0.0f;
        float b1 = (lane < 8) ? sb[lane] : 0.0f;
#pragma unroll
        for (int o = 4; o > 0; o >>= 1) {
            a1 += __shfl_xor_sync(0xffffffffu, a1, o);
            b1 += __shfl_xor_sync(0xffffffffu, b1, o);
        }
        if (lane == 0) { sa[0] = a1; sb[0] = b1; }
    }
    __syncthreads();
    const float mu  = sa[0] * (1.0f / DD);
    const float var = sb[0] * (1.0f / DD) - mu * mu;
    const float inv = rsqrtf(var + 1e-5f);

    const float4 gm = *(const float4*)&gamma[d0];
    const float4 bt = *(const float4*)&lbeta[d0];
    float4 o;
    o.x = (ya.x - mu) * inv * gm.x + bt.x;
    o.y = (ya.y - mu) * inv * gm.y + bt.y;
    o.z = (yb.x - mu) * inv * gm.z + bt.z;
    o.w = (yb.y - mu) * inv * gm.w + bt.w;
    *(float4*)&out[(size_t)row * DD + d0] = o;
}

// ---------------- launch ----------------
extern "C" void kernel_launch(void* const* d_in, const int* in_sizes, int n_in,
                              void* d_out, int out_size)
{
    const float* x     = (const float*)d_in[0];
    const float* Wz    = (const float*)d_in[1];
    const float* bz    = (const float*)d_in[2];
    const float* Wh    = (const float*)d_in[3];
    const float* bh    = (const float*)d_in[4];
    const float* sbeta = (const float*)d_in[5];
    const float* gamma = (const float*)d_in[6];
    const float* lbeta = (const float*)d_in[7];
    float* out = (float*)d_out;

    convert_x_kernel<<<(MM * DD) / (256 * 4), 256>>>(x);
    transpose_kernel<<<dim3(32, 32, 2), 256>>>(Wz, Wh);

    dim3 gemmGrid(DD / 128, MM / 128);   // (8, 128)
    cudaError_t e = cudaFuncSetAttribute(
        gemm64_kernel, cudaFuncAttributeMaxDynamicSharedMemorySize, 2 * STAGE64);
    if (e == cudaSuccess) {
        gemm64_kernel<<<gemmGrid, 256, 2 * STAGE64>>>(bz, bh);
        // chunk summaries computed in-kernel
    } else {
        (void)cudaGetLastError();
        gemm32_kernel<<<gemmGrid, 256, 2 * STAGE32>>>(bz, bh);
        scan_pass1<<<(BB * NCHUNK * DD) / (256 * 2), 256>>>();
    }

    scan_swish_kernel<<<(BB * NCHUNK * DD) / (256 * 2), 256>>>(sbeta);
    ln_kernel<<<MM, 256>>>(gamma, lbeta, out);
}

// round 13
// speedup vs baseline: 1.1034x; 1.0957x over previous
#include <cuda_runtime.h>
#include <cuda_fp16.h>
#include <math.h>
#include <stdint.h>

// Problem shape (fixed): B=8, T=2048, D=1024
#define BB   8
#define TT   2048
#define DD   1024
#define MM   (BB*TT)          // 16384 rows
#define NCHUNK 32
#define CHLEN  64

// ---- BK=64 GEMM (primary): CTA 128x128, 2 outputs, warp 64x32x2 ----
#define NCH64   16
#define A64_OFF  0
#define BZ64_OFF 16384
#define BH64_OFF 32768
#define STAGE64  49152        // 48KB per stage; 2 stages = 96KB

// ---- BK=32 GEMM (fallback, 48KB default smem) ----
#define NCH32   32
#define A32_OFF  0
#define BZ32_OFF 8192
#define BH32_OFF 16384
#define STAGE32  24576

// ---------------- scratch (device globals) ----------------
__device__ __half2 g_ab[(size_t)MM * DD];   // {a, b} per element (fp16)
__device__ __half  g_y16[(size_t)MM * DD];  // swish output (fp16)
__device__ float   g_Ac[BB * NCHUNK * DD];  // chunk summaries (fp32)
__device__ float   g_Bc[BB * NCHUNK * DD];

__device__ __half g_xh[(size_t)MM * DD];    // x in fp16
__device__ __half g_Wtz[DD * DD];           // Wz^T fp16: [n][k]
__device__ __half g_Wth[DD * DD];           // Wh^T fp16: [n][k]

__device__ __forceinline__ float sigmoidf_fast(float v) {
    return 1.0f / (1.0f + __expf(-v));
}

// ---- bit casts ----
__device__ __forceinline__ uint32_t h2_to_u32(__half2 h) {
    return *reinterpret_cast<uint32_t*>(&h);
}
__device__ __forceinline__ __half2 u32_to_h2(uint32_t u) {
    return *reinterpret_cast<__half2*>(&u);
}

// ---------------- PTX helpers ----------------
__device__ __forceinline__ uint32_t smem_u32(const void* p) {
    uint32_t a;
    asm("{ .reg .u64 t; cvta.to.shared.u64 t, %1; cvt.u32.u64 %0, t; }" : "=r"(a) : "l"(p));
    return a;
}
#define SWZ64(o)  ((o) ^ (((o) >> 3) & 0x30))
#define SWZ128(o) ((o) ^ (((o) >> 3) & 0x70))

__device__ __forceinline__ void cp16(uint32_t s, const void* g) {
    asm volatile("cp.async.cg.shared.global [%0], [%1], 16;" :: "r"(s), "l"(g));
}
__device__ __forceinline__ void cp_commit() {
    asm volatile("cp.async.commit_group;" ::: "memory");
}
__device__ __forceinline__ void ldsm_x4(uint32_t& r0, uint32_t& r1, uint32_t& r2,
                                        uint32_t& r3, uint32_t addr) {
    asm volatile("ldmatrix.sync.aligned.m8n8.x4.shared.b16 {%0,%1,%2,%3}, [%4];"
                 : "=r"(r0), "=r"(r1), "=r"(r2), "=r"(r3) : "r"(addr));
}
__device__ __forceinline__ void mma_f16(float* d, const uint32_t* a, const uint32_t* b) {
    asm volatile(
        "mma.sync.aligned.m16n8k16.row.col.f32.f16.f16.f32 "
        "{%0,%1,%2,%3},{%4,%5,%6,%7},{%8,%9},{%0,%1,%2,%3};"
        : "+f"(d[0]), "+f"(d[1]), "+f"(d[2]), "+f"(d[3])
        : "r"(a[0]), "r"(a[1]), "r"(a[2]), "r"(a[3]), "r"(b[0]), "r"(b[1]));
}

// ---------------- prep: convert x to fp16 ----------------
__global__ __launch_bounds__(256)
void convert_x_kernel(const float* __restrict__ x)
{
    const size_t i4 = (size_t)blockIdx.x * 256 + threadIdx.x;
    const float4 v = ((const float4*)x)[i4];
    __half2 p0, p1;
    p0.x = __float2half_rn(v.x); p0.y = __float2half_rn(v.y);
    p1.x = __float2half_rn(v.z); p1.y = __float2half_rn(v.w);
    ((__half2*)g_xh)[i4 * 2]     = p0;
    ((__half2*)g_xh)[i4 * 2 + 1] = p1;
}

// ---------------- prep: transpose W -> Wt[n][k], fp16 ----------------
__global__ __launch_bounds__(256)
void transpose_kernel(const float* __restrict__ Wz, const float* __restrict__ Wh)
{
    __shared__ float sm[32][33];
    const float* W = (blockIdx.z == 0) ? Wz : Wh;
    __half* Wt = (blockIdx.z == 0) ? g_Wtz : g_Wth;

    const int k0 = blockIdx.y * 32;
    const int n0 = blockIdx.x * 32;
    const int r = threadIdx.x >> 5;
    const int c = threadIdx.x & 31;
#pragma unroll
    for (int rr = 0; rr < 4; rr++) {
        const int row = rr * 8 + r;
        sm[row][c] = W[(size_t)(k0 + row) * DD + n0 + c];
    }
    __syncthreads();
#pragma unroll
    for (int rr = 0; rr < 4; rr++) {
        const int row = rr * 8 + r;
        Wt[(size_t)(n0 + row) * DD + k0 + c] = __float2half_rn(sm[c][row]);
    }
}

// ---------------- fallback epilogue: {a,b} fp16 to gmem only ----------------
__device__ __forceinline__ void gemm_epilogue(
    float accz[4][4][4], float acch[4][4][4],
    const float* __restrict__ bz, const float* __restrict__ bh,
    int mBase, int nBase, int wr, int wc, int lane)
{
    const int er = lane >> 2;
    const int ec = (lane & 3) * 2;
#pragma unroll
    for (int mt = 0; mt < 4; mt++) {
#pragma unroll
        for (int nt = 0; nt < 4; nt++) {
            const int m = mBase + wr * 64 + mt * 16 + er;
            const int n = nBase + wc * 32 + nt * 8 + ec;
            const size_t g0 = (size_t)m * DD + n;
            const size_t g1 = g0 + 8 * DD;
            const float2 bz2 = *(const float2*)(&bz[n]);
            const float2 bh2 = *(const float2*)(&bh[n]);
            float z;
            __half2 p0, p1;
            z = sigmoidf_fast(accz[mt][nt][0] + bz2.x);
            p0.x = __float2half_rn(1.0f - z);
            p0.y = __float2half_rn(z * (acch[mt][nt][0] + bh2.x));
            z = sigmoidf_fast(accz[mt][nt][1] + bz2.y);
            p1.x = __float2half_rn(1.0f - z);
            p1.y = __float2half_rn(z * (acch[mt][nt][1] + bh2.y));
            *(uint2*)(&g_ab[g0]) = make_uint2(h2_to_u32(p0), h2_to_u32(p1));
            z = sigmoidf_fast(accz[mt][nt][2] + bz2.x);
            p0.x = __float2half_rn(1.0f - z);
            p0.y = __float2half_rn(z * (acch[mt][nt][2] + bh2.x));
            z = sigmoidf_fast(accz[mt][nt][3] + bz2.y);
            p1.x = __float2half_rn(1.0f - z);
            p1.y = __float2half_rn(z * (acch[mt][nt][3] + bh2.y));
            *(uint2*)(&g_ab[g1]) = make_uint2(h2_to_u32(p0), h2_to_u32(p1));
        }
    }
}

// ---------------- PRIMARY GEMM: BK=64, 2-stage, 96KB smem --------------------
// Epilogue also computes the per-chunk scan summaries (2 chunks/CTA) and
// writes g_Ac/g_Bc directly -> no separate scan_pass1 launch on this path.
__global__ __launch_bounds__(256, 1)
void gemm64_kernel(const float* __restrict__ bz, const float* __restrict__ bh)
{
    extern __shared__ char smem[];
    const uint32_t sbase = smem_u32(smem);
    const int tid  = threadIdx.x;
    const int wid  = tid >> 5;
    const int lane = tid & 31;
    const int wr = wid >> 2;
    const int wc = wid & 3;

    const int nBase = blockIdx.x * 128;
    const int mBase = blockIdx.y * 128;

    int ldRow[4];
    int ldCol[4];
    uint32_t ldOff[4];
#pragma unroll
    for (int t = 0; t < 4; t++) {
        const int o = tid + t * 256;
        ldRow[t] = o >> 3;
        ldCol[t] = o & 7;
        ldOff[t] = SWZ128((uint32_t)(o * 16));
    }

    const int quad = lane >> 3;
    const int r8   = lane & 7;
    const int rowA = (quad & 1) * 8 + r8;
    const int kbA  = (quad >> 1) * 16;
    const int rowB = (quad >> 1) * 8 + r8;
    const int kbB  = (quad & 1) * 16;

    uint32_t offA[4][4], offB[4][2];
#pragma unroll
    for (int ks = 0; ks < 4; ks++) {
#pragma unroll
        for (int mt = 0; mt < 4; mt++)
            offA[ks][mt] = SWZ128((uint32_t)((wr * 64 + mt * 16 + rowA) * 128 + ks * 32 + kbA));
#pragma unroll
        for (int bt = 0; bt < 2; bt++)
            offB[ks][bt] = SWZ128((uint32_t)((wc * 32 + bt * 16 + rowB) * 128 + ks * 32 + kbB));
    }

    float accz[4][4][4], acch[4][4][4];
#pragma unroll
    for (int i = 0; i < 4; i++)
#pragma unroll
        for (int j = 0; j < 4; j++)
#pragma unroll
            for (int k = 0; k < 4; k++) { accz[i][j][k] = 0.0f; acch[i][j][k] = 0.0f; }

    auto load_chunk = [&](int chunk, int stage) {
        const int k0 = chunk * 64;
        const uint32_t st = sbase + stage * STAGE64;
#pragma unroll
        for (int t = 0; t < 4; t++) {
            const size_t rowOff = (size_t)ldRow[t] * DD + k0 + ldCol[t] * 8;
            cp16(st + A64_OFF  + ldOff[t], g_xh  + (size_t)mBase * DD + rowOff);
            cp16(st + BZ64_OFF + ldOff[t], g_Wtz + (size_t)nBase * DD + rowOff);
            cp16(st + BH64_OFF + ldOff[t], g_Wth + (size_t)nBase * DD + rowOff);
        }
        cp_commit();
    };

    load_chunk(0, 0);

    for (int i = 0; i < NCH64; i++) {
        const int s = i & 1;
        asm volatile("cp.async.wait_group 0;" ::: "memory");
        __syncthreads();
        if (i + 1 < NCH64) load_chunk(i + 1, s ^ 1);

        const uint32_t st = sbase + s * STAGE64;
#pragma unroll
        for (int ks = 0; ks < 4; ks++) {
            uint32_t af[4][4];
#pragma unroll
            for (int mt = 0; mt < 4; mt++)
                ldsm_x4(af[mt][0], af[mt][1], af[mt][2], af[mt][3],
                        st + A64_OFF + offA[ks][mt]);
            {
                uint32_t bf[4][2];
#pragma unroll
                for (int bt = 0; bt < 2; bt++)
                    ldsm_x4(bf[bt*2][0], bf[bt*2][1], bf[bt*2+1][0], bf[bt*2+1][1],
                            st + BZ64_OFF + offB[ks][bt]);
#pragma unroll
                for (int mt = 0; mt < 4; mt++)
#pragma unroll
                    for (int nt = 0; nt < 4; nt++)
                        mma_f16(accz[mt][nt], af[mt], bf[nt]);
            }
            {
                uint32_t bf[4][2];
#pragma unroll
                for (int bt = 0; bt < 2; bt++)
                    ldsm_x4(bf[bt*2][0], bf[bt*2][1], bf[bt*2+1][0], bf[bt*2+1][1],
                            st + BH64_OFF + offB[ks][bt]);
#pragma unroll
                for (int mt = 0; mt < 4; mt++)
#pragma unroll
                    for (int nt = 0; nt < 4; nt++)
                        mma_f16(acch[mt][nt], af[mt], bf[nt]);
            }
        }
    }

    // ---- epilogue: g_ab to gmem + stage {a,b} into smem [128][129] ----
    __syncthreads();   // all warps done reading pipeline smem before reuse
    __half2* s_ab = (__half2*)smem;
    {
        const int er = lane >> 2;
        const int q2 = (lane & 3) * 2;
#pragma unroll
        for (int mt = 0; mt < 4; mt++) {
#pragma unroll
            for (int nt = 0; nt < 4; nt++) {
                const int tl0 = wr * 64 + mt * 16 + er;   // local timestep, half 0
                const int col = wc * 32 + nt * 8 + q2;
                const int n = nBase + col;
                const size_t g0 = (size_t)(mBase + tl0) * DD + n;
                const size_t g1 = g0 + 8 * DD;
                const float2 bz2 = *(const float2*)(&bz[n]);
                const float2 bh2 = *(const float2*)(&bh[n]);
                float z;
                __half2 p0, p1;
                z = sigmoidf_fast(accz[mt][nt][0] + bz2.x);
                p0.x = __float2half_rn(1.0f - z);
                p0.y = __float2half_rn(z * (acch[mt][nt][0] + bh2.x));
                z = sigmoidf_fast(accz[mt][nt][1] + bz2.y);
                p1.x = __float2half_rn(1.0f - z);
                p1.y = __float2half_rn(z * (acch[mt][nt][1] + bh2.y));
                *(uint2*)(&g_ab[g0]) = make_uint2(h2_to_u32(p0), h2_to_u32(p1));
                s_ab[tl0 * 129 + col]     = p0;
                s_ab[tl0 * 129 + col + 1] = p1;
                z = sigmoidf_fast(accz[mt][nt][2] + bz2.x);
                p0.x = __float2half_rn(1.0f - z);
                p0.y = __float2half_rn(z * (acch[mt][nt][2] + bh2.x));
                z = sigmoidf_fast(accz[mt][nt][3] + bz2.y);
                p1.x = __float2half_rn(1.0f - z);
                p1.y = __float2half_rn(z * (acch[mt][nt][3] + bh2.y));
                *(uint2*)(&g_ab[g1]) = make_uint2(h2_to_u32(p0), h2_to_u32(p1));
                s_ab[(tl0 + 8) * 129 + col]     = p0;
                s_ab[(tl0 + 8) * 129 + col + 1] = p1;
            }
        }
    }
    __syncthreads();

    // ---- per-chunk scan summaries: thread = (chunk_local, column) ----
    {
        const int ch = tid >> 7;          // 0..1 (two 64-step chunks per CTA)
        const int cl = tid & 127;
        float A = 1.0f, Bv = 0.0f;
#pragma unroll 8
        for (int t = 0; t < CHLEN; t++) {
            const float2 f = __half22float2(s_ab[(ch * 64 + t) * 129 + cl]);
            Bv = fmaf(f.x, Bv, f.y);
            A *= f.x;
        }
        const int bc = (mBase >> 6) + ch;   // global chunk index = m/64
        g_Ac[(size_t)bc * DD + nBase + cl] = A;
        g_Bc[(size_t)bc * DD + nBase + cl] = Bv;
    }
}

// ---------------- FALLBACK GEMM: BK=32, 2-stage, 48KB ------------
__global__ __launch_bounds__(256, 1)
void gemm32_kernel(const float* __restrict__ bz, const float* __restrict__ bh)
{
    extern __shared__ char smem[];
    const uint32_t sbase = smem_u32(smem);
    const int tid  = threadIdx.x;
    const int wid  = tid >> 5;
    const int lane = tid & 31;
    const int wr = wid >> 2;
    const int wc = wid & 3;

    const int nBase = blockIdx.x * 128;
    const int mBase = blockIdx.y * 128;

    int ldRow[2];
    int ldCol[2];
    uint32_t ldOff[2];
#pragma unroll
    for (int t = 0; t < 2; t++) {
        const int o = tid + t * 256;
        ldRow[t] = o >> 2;
        ldCol[t] = o & 3;
        ldOff[t] = SWZ64((uint32_t)(o * 16));
    }

    const int quad = lane >> 3;
    const int r8   = lane & 7;
    const int rowA = (quad & 1) * 8 + r8;
    const int kbA  = (quad >> 1) * 16;
    const int rowB = (quad >> 1) * 8 + r8;
    const int kbB  = (quad & 1) * 16;

    uint32_t offA[2][4], offB[2][2];
#pragma unroll
    for (int ks = 0; ks < 2; ks++) {
#pragma unroll
        for (int mt = 0; mt < 4; mt++)
            offA[ks][mt] = SWZ64((uint32_t)((wr * 64 + mt * 16 + rowA) * 64 + ks * 32 + kbA));
#pragma unroll
        for (int bt = 0; bt < 2; bt++)
            offB[ks][bt] = SWZ64((uint32_t)((wc * 32 + bt * 16 + rowB) * 64 + ks * 32 + kbB));
    }

    float accz[4][4][4], acch[4][4][4];
#pragma unroll
    for (int i = 0; i < 4; i++)
#pragma unroll
        for (int j = 0; j < 4; j++)
#pragma unroll
            for (int k = 0; k < 4; k++) { accz[i][j][k] = 0.0f; acch[i][j][k] = 0.0f; }

    auto load_chunk = [&](int chunk, int stage) {
        const int k0 = chunk * 32;
        const uint32_t st = sbase + stage * STAGE32;
#pragma unroll
        for (int t = 0; t < 2; t++) {
            const size_t rowOff = (size_t)ldRow[t] * DD + k0 + ldCol[t] * 8;
            cp16(st + A32_OFF  + ldOff[t], g_xh  + (size_t)mBase * DD + rowOff);
            cp16(st + BZ32_OFF + ldOff[t], g_Wtz + (size_t)nBase * DD + rowOff);
            cp16(st + BH32_OFF + ldOff[t], g_Wth + (size_t)nBase * DD + rowOff);
        }
        cp_commit();
    };

    load_chunk(0, 0);

    for (int i = 0; i < NCH32; i++) {
        const int s = i & 1;
        asm volatile("cp.async.wait_group 0;" ::: "memory");
        __syncthreads();
        if (i + 1 < NCH32) load_chunk(i + 1, s ^ 1);

        const uint32_t st = sbase + s * STAGE32;
#pragma unroll
        for (int ks = 0; ks < 2; ks++) {
            uint32_t af[4][4];
#pragma unroll
            for (int mt = 0; mt < 4; mt++)
                ldsm_x4(af[mt][0], af[mt][1], af[mt][2], af[mt][3],
                        st + A32_OFF + offA[ks][mt]);
            {
                uint32_t bf[4][2];
#pragma unroll
                for (int bt = 0; bt < 2; bt++)
                    ldsm_x4(bf[bt*2][0], bf[bt*2][1], bf[bt*2+1][0], bf[bt*2+1][1],
                            st + BZ32_OFF + offB[ks][bt]);
#pragma unroll
                for (int mt = 0; mt < 4; mt++)
#pragma unroll
                    for (int nt = 0; nt < 4; nt++)
                        mma_f16(accz[mt][nt], af[mt], bf[nt]);
            }
            {
                uint32_t bf[4][2];
#pragma unroll
                for (int bt = 0; bt < 2; bt++)
                    ldsm_x4(bf[bt*2][0], bf[bt*2][1], bf[bt*2+1][0], bf[bt*2+1][1],
                            st + BH32_OFF + offB[ks][bt]);
#pragma unroll
                for (int mt = 0; mt < 4; mt++)
#pragma unroll
                    for (int nt = 0; nt < 4; nt++)
                        mma_f16(acch[mt][nt], af[mt], bf[nt]);
            }
        }
    }

    gemm_epilogue(accz, acch, bz, bh, mBase, nBase, wr, wc, lane);
}

// ---------------- scan pass 1 (fallback path only) ----------------
__global__ __launch_bounds__(256)
void scan_pass1()
{
    const int g2 = blockIdx.x * 256 + threadIdx.x;   // (bc, d/2)
    const int bc = g2 >> 9;
    const int d0 = (g2 & 511) * 2;
    const size_t base = (size_t)bc * CHLEN * DD + d0;

    float2 Ar = make_float2(1.f, 1.f);
    float2 Br = make_float2(0.f, 0.f);
#pragma unroll 16
    for (int t = 0; t < CHLEN; t++) {
        const uint2 raw = *(const uint2*)&g_ab[base + (size_t)t * DD];
        const float2 ab0 = __half22float2(u32_to_h2(raw.x));
        const float2 ab1 = __half22float2(u32_to_h2(raw.y));
        Br.x = fmaf(ab0.x, Br.x, ab0.y); Ar.x *= ab0.x;
        Br.y = fmaf(ab1.x, Br.y, ab1.y); Ar.y *= ab1.x;
    }
    *(float2*)&g_Ac[(size_t)bc * DD + d0] = Ar;
    *(float2*)&g_Bc[(size_t)bc * DD + d0] = Br;
}

// ---------------- scan + swish: software-pipelined (depth-4 prefetch) --------
// thread = (bc, d pair). hinit via prefix over chunk summaries, then 64 steps
// computed in groups of 4 with the NEXT 4 ab loads issued before the group's
// compute (raises MLP from ~1 to ~4-8; the h-chain itself is only 4cyc/step).
__global__ __launch_bounds__(256)
void scan_swish_kernel(const float* __restrict__ swish_beta)
{
    const int g2 = blockIdx.x * 256 + threadIdx.x;   // (bc, d/2)
    const int bc = g2 >> 9;
    const int d0 = (g2 & 511) * 2;
    const int b = bc >> 5;
    const int chunk = bc & 31;
    const float beta = __ldg(swish_beta);

    // hinit: prefix over predecessor chunk summaries (loads batch with unroll)
    float2 h = make_float2(0.f, 0.f);
#pragma unroll 4
    for (int c = 0; c < chunk; c++) {
        const size_t idx = (size_t)(b * NCHUNK + c) * DD + d0;
        const float2 A = *(const float2*)&g_Ac[idx];
        const float2 B = *(const float2*)&g_Bc[idx];
        h.x = fmaf(A.x, h.x, B.x);
        h.y = fmaf(A.y, h.y, B.y);
    }

    const size_t base = (size_t)bc * CHLEN * DD + d0;

    uint2 buf[4];
#pragma unroll
    for (int j = 0; j < 4; j++)
        buf[j] = *(const uint2*)&g_ab[base + (size_t)j * DD];

    for (int t0 = 0; t0 < CHLEN; t0 += 4) {
        uint2 nxt[4];
        if (t0 + 4 < CHLEN) {
#pragma unroll
            for (int j = 0; j < 4; j++)
                nxt[j] = *(const uint2*)&g_ab[base + (size_t)(t0 + 4 + j) * DD];
        }
#pragma unroll
        for (int j = 0; j < 4; j++) {
            const float2 ab0 = __half22float2(u32_to_h2(buf[j].x));
            const float2 ab1 = __half22float2(u32_to_h2(buf[j].y));
            h.x = fmaf(ab0.x, h.x, ab0.y);
            h.y = fmaf(ab1.x, h.y, ab1.y);
            float s;
            __half2 y2;
            s = beta * h.x; y2.x = __float2half_rn(s * sigmoidf_fast(s));
            s = beta * h.y; y2.y = __float2half_rn(s * sigmoidf_fast(s));
            *(__half2*)&g_y16[base + (size_t)(t0 + j) * DD] = y2;
        }
#pragma unroll
        for (int j = 0; j < 4; j++) buf[j] = nxt[j];
    }
}

// ---------------- LayerNorm: one CTA per row, y16 in, fp32 out ----------------
__global__ __launch_bounds__(256)
void ln_kernel(const float* __restrict__ gamma,
               const float* __restrict__ lbeta,
               float* __restrict__ out)
{
    const int row = blockIdx.x;
    const int tid = threadIdx.x;
    const int lane = tid & 31;
    const int w = tid >> 5;
    const int d0 = tid * 4;

    const uint2 yr = *(const uint2*)&g_y16[(size_t)row * DD + d0];
    const float2 ya = __half22float2(u32_to_h2(yr.x));
    const float2 yb = __half22float2(u32_to_h2(yr.y));

    float s1 = ya.x + ya.y + yb.x + yb.y;
    float s2 = ya.x * ya.x + ya.y * ya.y + yb.x * yb.x + yb.y * yb.y;
#pragma unroll
    for (int o = 16; o > 0; o >>= 1) {
        s1 += __shfl_xor_sync(0xffffffffu, s1, o);
        s2 += __shfl_xor_sync(0xffffffffu, s2, o);
    }
    __shared__ float sa[8], sb[8];
    if (lane == 0) { sa[w] = s1; sb[w] = s2; }
    __syncthreads();
    if (w == 0) {
        float a1 = (lane < 8) ? sa[lane] : 0.0f;
        float b1 = (lane < 8) ? sb[lane] : 0.0f;
#pragma unroll
        for (int o = 4; o > 0; o >>= 1) {
            a1 += __shfl_xor_sync(0xffffffffu, a1, o);
            b1 += __shfl_xor_sync(0xffffffffu, b1, o);
        }
        if (lane == 0) { sa[0] = a1; sb[0] = b1; }
    }
    __syncthreads();
    const float mu  = sa[0] * (1.0f / DD);
    const float var = sb[0] * (1.0f / DD) - mu * mu;
    const float inv = rsqrtf(var + 1e-5f);

    const float4 gm = *(const float4*)&gamma[d0];
    const float4 bt = *(const float4*)&lbeta[d0];
    float4 o;
    o.x = (ya.x - mu) * inv * gm.x + bt.x;
    o.y = (ya.y - mu) * inv * gm.y + bt.y;
    o.z = (yb.x - mu) * inv * gm.z + bt.z;
    o.w = (yb.y - mu) * inv * gm.w + bt.w;
    *(float4*)&out[(size_t)row * DD + d0] = o;
}

// ---------------- launch ----------------
extern "C" void kernel_launch(void* const* d_in, const int* in_sizes, int n_in,
                              void* d_out, int out_size)
{
    const float* x     = (const float*)d_in[0];
    const float* Wz    = (const float*)d_in[1];
    const float* bz    = (const float*)d_in[2];
    const float* Wh    = (const float*)d_in[3];
    const float* bh    = (const float*)d_in[4];
    const float* sbeta = (const float*)d_in[5];
    const float* gamma = (const float*)d_in[6];
    const float* lbeta = (const float*)d_in[7];
    float* out = (float*)d_out;

    convert_x_kernel<<<(MM * DD) / (256 * 4), 256>>>(x);
    transpose_kernel<<<dim3(32, 32, 2), 256>>>(Wz, Wh);

    dim3 gemmGrid(DD / 128, MM / 128);   // (8, 128)
    cudaError_t e = cudaFuncSetAttribute(
        gemm64_kernel, cudaFuncAttributeMaxDynamicSharedMemorySize, 2 * STAGE64);
    if (e == cudaSuccess) {
        gemm64_kernel<<<gemmGrid, 256, 2 * STAGE64>>>(bz, bh);
        // chunk summaries computed in-kernel
    } else {
        (void)cudaGetLastError();
        gemm32_kernel<<<gemmGrid, 256, 2 * STAGE32>>>(bz, bh);
        scan_pass1<<<(BB * NCHUNK * DD) / (256 * 2), 256>>>();
    }

    scan_swish_kernel<<<(BB * NCHUNK * DD) / (256 * 2), 256>>>(sbeta);
    ln_kernel<<<MM, 256>>>(gamma, lbeta, out);
}

// round 14
// speedup vs baseline: 1.2553x; 1.1377x over previous
#include <cuda_runtime.h>
#include <cuda_fp16.h>
#include <math.h>
#include <stdint.h>

// Problem shape (fixed): B=8, T=2048, D=1024
#define BB   8
#define TT   2048
#define DD   1024
#define MM   (BB*TT)          // 16384 rows
#define NCHUNK 32
#define CHLEN  64

// ---- N64 GEMM (primary): CTA 128(M)x64(N), 2 outputs, warp 32x32, occ 2 ----
#define NCHN   16             // K chunks of 64
#define AN_OFF  0
#define BZN_OFF 16384
#define BHN_OFF 24576
#define STAGEN  32768          // 32KB per stage; 2 stages = 64KB

// ---- BK=64 GEMM (fallback 1): CTA 128x128, 96KB ----
#define NCH64   16
#define A64_OFF  0
#define BZ64_OFF 16384
#define BH64_OFF 32768
#define STAGE64  49152

// ---- BK=32 GEMM (fallback 2, 48KB default smem) ----
#define NCH32   32
#define A32_OFF  0
#define BZ32_OFF 8192
#define BH32_OFF 16384
#define STAGE32  24576

// ---------------- scratch (device globals) ----------------
__device__ __half2 g_ab[(size_t)MM * DD];   // {a, b} per element (fp16)
__device__ __half  g_y16[(size_t)MM * DD];  // swish output (fp16)
__device__ float   g_Ac[BB * NCHUNK * DD];  // chunk summaries (fp32)
__device__ float   g_Bc[BB * NCHUNK * DD];

__device__ __half g_xh[(size_t)MM * DD];    // x in fp16
__device__ __half g_Wtz[DD * DD];           // Wz^T fp16: [n][k]
__device__ __half g_Wth[DD * DD];           // Wh^T fp16: [n][k]

__device__ __forceinline__ float sigmoidf_fast(float v) {
    return 1.0f / (1.0f + __expf(-v));
}

// ---- bit casts ----
__device__ __forceinline__ uint32_t h2_to_u32(__half2 h) {
    return *reinterpret_cast<uint32_t*>(&h);
}
__device__ __forceinline__ __half2 u32_to_h2(uint32_t u) {
    return *reinterpret_cast<__half2*>(&u);
}

// ---------------- PTX helpers ----------------
__device__ __forceinline__ uint32_t smem_u32(const void* p) {
    uint32_t a;
    asm("{ .reg .u64 t; cvta.to.shared.u64 t, %1; cvt.u32.u64 %0, t; }" : "=r"(a) : "l"(p));
    return a;
}
#define SWZ64(o)  ((o) ^ (((o) >> 3) & 0x30))
#define SWZ128(o) ((o) ^ (((o) >> 3) & 0x70))

__device__ __forceinline__ void cp16(uint32_t s, const void* g) {
    asm volatile("cp.async.cg.shared.global [%0], [%1], 16;" :: "r"(s), "l"(g));
}
__device__ __forceinline__ void cp_commit() {
    asm volatile("cp.async.commit_group;" ::: "memory");
}
__device__ __forceinline__ void ldsm_x4(uint32_t& r0, uint32_t& r1, uint32_t& r2,
                                        uint32_t& r3, uint32_t addr) {
    asm volatile("ldmatrix.sync.aligned.m8n8.x4.shared.b16 {%0,%1,%2,%3}, [%4];"
                 : "=r"(r0), "=r"(r1), "=r"(r2), "=r"(r3) : "r"(addr));
}
__device__ __forceinline__ void mma_f16(float* d, const uint32_t* a, const uint32_t* b) {
    asm volatile(
        "mma.sync.aligned.m16n8k16.row.col.f32.f16.f16.f32 "
        "{%0,%1,%2,%3},{%4,%5,%6,%7},{%8,%9},{%0,%1,%2,%3};"
        : "+f"(d[0]), "+f"(d[1]), "+f"(d[2]), "+f"(d[3])
        : "r"(a[0]), "r"(a[1]), "r"(a[2]), "r"(a[3]), "r"(b[0]), "r"(b[1]));
}

// ---------------- prep: convert x to fp16 ----------------
__global__ __launch_bounds__(256)
void convert_x_kernel(const float* __restrict__ x)
{
    const size_t i4 = (size_t)blockIdx.x * 256 + threadIdx.x;
    const float4 v = ((const float4*)x)[i4];
    __half2 p0, p1;
    p0.x = __float2half_rn(v.x); p0.y = __float2half_rn(v.y);
    p1.x = __float2half_rn(v.z); p1.y = __float2half_rn(v.w);
    ((__half2*)g_xh)[i4 * 2]     = p0;
    ((__half2*)g_xh)[i4 * 2 + 1] = p1;
}

// ---------------- prep: transpose W -> Wt[n][k], fp16 ----------------
__global__ __launch_bounds__(256)
void transpose_kernel(const float* __restrict__ Wz, const float* __restrict__ Wh)
{
    __shared__ float sm[32][33];
    const float* W = (blockIdx.z == 0) ? Wz : Wh;
    __half* Wt = (blockIdx.z == 0) ? g_Wtz : g_Wth;

    const int k0 = blockIdx.y * 32;
    const int n0 = blockIdx.x * 32;
    const int r = threadIdx.x >> 5;
    const int c = threadIdx.x & 31;
#pragma unroll
    for (int rr = 0; rr < 4; rr++) {
        const int row = rr * 8 + r;
        sm[row][c] = W[(size_t)(k0 + row) * DD + n0 + c];
    }
    __syncthreads();
#pragma unroll
    for (int rr = 0; rr < 4; rr++) {
        const int row = rr * 8 + r;
        Wt[(size_t)(n0 + row) * DD + k0 + c] = __float2half_rn(sm[c][row]);
    }
}

// ---------------- PRIMARY GEMM: CTA 128x64, occ 2, 64KB smem -----------------
// Epilogue computes per-chunk scan summaries (2 chunks x 64 cols per CTA).
__global__ __launch_bounds__(256, 2)
void gemmN64_kernel(const float* __restrict__ bz, const float* __restrict__ bh)
{
    extern __shared__ char smem[];
    const uint32_t sbase = smem_u32(smem);
    const int tid  = threadIdx.x;
    const int wid  = tid >> 5;
    const int lane = tid & 31;
    const int wr = wid >> 1;           // 0..3: M 32-row strip
    const int wc = wid & 1;            // 0..1: N 32-col strip

    const int nBase = blockIdx.x * 64;
    const int mBase = blockIdx.y * 128;

    // cp.async addressing (128B rows): A 4x, B 2x each
    int ldRowA[4], ldColA[4];
    uint32_t ldOffA[4];
#pragma unroll
    for (int t = 0; t < 4; t++) {
        const int o = tid + t * 256;
        ldRowA[t] = o >> 3; ldColA[t] = o & 7;
        ldOffA[t] = SWZ128((uint32_t)(o * 16));
    }
    int ldRowB[2], ldColB[2];
    uint32_t ldOffB[2];
#pragma unroll
    for (int t = 0; t < 2; t++) {
        const int o = tid + t * 256;
        ldRowB[t] = o >> 3; ldColB[t] = o & 7;
        ldOffB[t] = SWZ128((uint32_t)(o * 16));
    }

    // ldmatrix static offsets (128B rows, 4 k-steps)
    const int quad = lane >> 3;
    const int r8   = lane & 7;
    const int rowA = (quad & 1) * 8 + r8;
    const int kbA  = (quad >> 1) * 16;
    const int rowB = (quad >> 1) * 8 + r8;
    const int kbB  = (quad & 1) * 16;

    uint32_t offA[4][2], offB[4][2];
#pragma unroll
    for (int ks = 0; ks < 4; ks++) {
#pragma unroll
        for (int mt = 0; mt < 2; mt++)
            offA[ks][mt] = SWZ128((uint32_t)((wr * 32 + mt * 16 + rowA) * 128 + ks * 32 + kbA));
#pragma unroll
        for (int bt = 0; bt < 2; bt++)
            offB[ks][bt] = SWZ128((uint32_t)((wc * 32 + bt * 16 + rowB) * 128 + ks * 32 + kbB));
    }

    float accz[2][4][4], acch[2][4][4];
#pragma unroll
    for (int i = 0; i < 2; i++)
#pragma unroll
        for (int j = 0; j < 4; j++)
#pragma unroll
            for (int k = 0; k < 4; k++) { accz[i][j][k] = 0.0f; acch[i][j][k] = 0.0f; }

    auto load_chunk = [&](int chunk, int stage) {
        const int k0 = chunk * 64;
        const uint32_t st = sbase + stage * STAGEN;
#pragma unroll
        for (int t = 0; t < 4; t++)
            cp16(st + AN_OFF + ldOffA[t],
                 g_xh + (size_t)(mBase + ldRowA[t]) * DD + k0 + ldColA[t] * 8);
#pragma unroll
        for (int t = 0; t < 2; t++) {
            const size_t rowOff = (size_t)(nBase + ldRowB[t]) * DD + k0 + ldColB[t] * 8;
            cp16(st + BZN_OFF + ldOffB[t], g_Wtz + rowOff);
            cp16(st + BHN_OFF + ldOffB[t], g_Wth + rowOff);
        }
        cp_commit();
    };

    load_chunk(0, 0);

    for (int i = 0; i < NCHN; i++) {
        const int s = i & 1;
        asm volatile("cp.async.wait_group 0;" ::: "memory");
        __syncthreads();
        if (i + 1 < NCHN) load_chunk(i + 1, s ^ 1);

        const uint32_t st = sbase + s * STAGEN;
#pragma unroll
        for (int ks = 0; ks < 4; ks++) {
            uint32_t af[2][4];
#pragma unroll
            for (int mt = 0; mt < 2; mt++)
                ldsm_x4(af[mt][0], af[mt][1], af[mt][2], af[mt][3],
                        st + AN_OFF + offA[ks][mt]);
            {
                uint32_t bf[4][2];
#pragma unroll
                for (int bt = 0; bt < 2; bt++)
                    ldsm_x4(bf[bt*2][0], bf[bt*2][1], bf[bt*2+1][0], bf[bt*2+1][1],
                            st + BZN_OFF + offB[ks][bt]);
#pragma unroll
                for (int mt = 0; mt < 2; mt++)
#pragma unroll
                    for (int nt = 0; nt < 4; nt++)
                        mma_f16(accz[mt][nt], af[mt], bf[nt]);
            }
            {
                uint32_t bf[4][2];
#pragma unroll
                for (int bt = 0; bt < 2; bt++)
                    ldsm_x4(bf[bt*2][0], bf[bt*2][1], bf[bt*2+1][0], bf[bt*2+1][1],
                            st + BHN_OFF + offB[ks][bt]);
#pragma unroll
                for (int mt = 0; mt < 2; mt++)
#pragma unroll
                    for (int nt = 0; nt < 4; nt++)
                        mma_f16(acch[mt][nt], af[mt], bf[nt]);
            }
        }
    }

    // ---- epilogue: g_ab to gmem + stage {a,b} into smem [128][65] ----
    __syncthreads();   // all warps done reading pipeline smem before reuse
    __half2* s_ab = (__half2*)smem;   // 128*65*4 = 33280 B <= 64KB
    {
        const int er = lane >> 2;
        const int q2 = (lane & 3) * 2;
#pragma unroll
        for (int mt = 0; mt < 2; mt++) {
#pragma unroll
            for (int nt = 0; nt < 4; nt++) {
                const int tl0 = wr * 32 + mt * 16 + er;
                const int col = wc * 32 + nt * 8 + q2;
                const int n = nBase + col;
                const size_t g0 = (size_t)(mBase + tl0) * DD + n;
                const size_t g1 = g0 + 8 * DD;
                const float2 bz2 = *(const float2*)(&bz[n]);
                const float2 bh2 = *(const float2*)(&bh[n]);
                float z;
                __half2 p0, p1;
                z = sigmoidf_fast(accz[mt][nt][0] + bz2.x);
                p0.x = __float2half_rn(1.0f - z);
                p0.y = __float2half_rn(z * (acch[mt][nt][0] + bh2.x));
                z = sigmoidf_fast(accz[mt][nt][1] + bz2.y);
                p1.x = __float2half_rn(1.0f - z);
                p1.y = __float2half_rn(z * (acch[mt][nt][1] + bh2.y));
                *(uint2*)(&g_ab[g0]) = make_uint2(h2_to_u32(p0), h2_to_u32(p1));
                s_ab[tl0 * 65 + col]     = p0;
                s_ab[tl0 * 65 + col + 1] = p1;
                z = sigmoidf_fast(accz[mt][nt][2] + bz2.x);
                p0.x = __float2half_rn(1.0f - z);
                p0.y = __float2half_rn(z * (acch[mt][nt][2] + bh2.x));
                z = sigmoidf_fast(accz[mt][nt][3] + bz2.y);
                p1.x = __float2half_rn(1.0f - z);
                p1.y = __float2half_rn(z * (acch[mt][nt][3] + bh2.y));
                *(uint2*)(&g_ab[g1]) = make_uint2(h2_to_u32(p0), h2_to_u32(p1));
                s_ab[(tl0 + 8) * 65 + col]     = p0;
                s_ab[(tl0 + 8) * 65 + col + 1] = p1;
            }
        }
    }
    __syncthreads();

    // ---- per-chunk scan summaries: threads 0..127 = (chunk_local, column) ---
    if (tid < 128) {
        const int ch = tid >> 6;          // 0..1
        const int cl = tid & 63;
        float A = 1.0f, Bv = 0.0f;
#pragma unroll 8
        for (int t = 0; t < CHLEN; t++) {
            const float2 f = __half22float2(s_ab[(ch * 64 + t) * 65 + cl]);
            Bv = fmaf(f.x, Bv, f.y);
            A *= f.x;
        }
        const int bc = (mBase >> 6) + ch;   // global chunk index = m/64
        g_Ac[(size_t)bc * DD + nBase + cl] = A;
        g_Bc[(size_t)bc * DD + nBase + cl] = Bv;
    }
}

// ---------------- FALLBACK 1 GEMM: BK=64, CTA 128x128, 96KB smem -------------
__global__ __launch_bounds__(256, 1)
void gemm64_kernel(const float* __restrict__ bz, const float* __restrict__ bh)
{
    extern __shared__ char smem[];
    const uint32_t sbase = smem_u32(smem);
    const int tid  = threadIdx.x;
    const int wid  = tid >> 5;
    const int lane = tid & 31;
    const int wr = wid >> 2;
    const int wc = wid & 3;

    const int nBase = blockIdx.x * 128;
    const int mBase = blockIdx.y * 128;

    int ldRow[4];
    int ldCol[4];
    uint32_t ldOff[4];
#pragma unroll
    for (int t = 0; t < 4; t++) {
        const int o = tid + t * 256;
        ldRow[t] = o >> 3;
        ldCol[t] = o & 7;
        ldOff[t] = SWZ128((uint32_t)(o * 16));
    }

    const int quad = lane >> 3;
    const int r8   = lane & 7;
    const int rowA = (quad & 1) * 8 + r8;
    const int kbA  = (quad >> 1) * 16;
    const int rowB = (quad >> 1) * 8 + r8;
    const int kbB  = (quad & 1) * 16;

    uint32_t offA[4][4], offB[4][2];
#pragma unroll
    for (int ks = 0; ks < 4; ks++) {
#pragma unroll
        for (int mt = 0; mt < 4; mt++)
            offA[ks][mt] = SWZ128((uint32_t)((wr * 64 + mt * 16 + rowA) * 128 + ks * 32 + kbA));
#pragma unroll
        for (int bt = 0; bt < 2; bt++)
            offB[ks][bt] = SWZ128((uint32_t)((wc * 32 + bt * 16 + rowB) * 128 + ks * 32 + kbB));
    }

    float accz[4][4][4], acch[4][4][4];
#pragma unroll
    for (int i = 0; i < 4; i++)
#pragma unroll
        for (int j = 0; j < 4; j++)
#pragma unroll
            for (int k = 0; k < 4; k++) { accz[i][j][k] = 0.0f; acch[i][j][k] = 0.0f; }

    auto load_chunk = [&](int chunk, int stage) {
        const int k0 = chunk * 64;
        const uint32_t st = sbase + stage * STAGE64;
#pragma unroll
        for (int t = 0; t < 4; t++) {
            const size_t rowOff = (size_t)ldRow[t] * DD + k0 + ldCol[t] * 8;
            cp16(st + A64_OFF  + ldOff[t], g_xh  + (size_t)mBase * DD + rowOff);
            cp16(st + BZ64_OFF + ldOff[t], g_Wtz + (size_t)nBase * DD + rowOff);
            cp16(st + BH64_OFF + ldOff[t], g_Wth + (size_t)nBase * DD + rowOff);
        }
        cp_commit();
    };

    load_chunk(0, 0);

    for (int i = 0; i < NCH64; i++) {
        const int s = i & 1;
        asm volatile("cp.async.wait_group 0;" ::: "memory");
        __syncthreads();
        if (i + 1 < NCH64) load_chunk(i + 1, s ^ 1);

        const uint32_t st = sbase + s * STAGE64;
#pragma unroll
        for (int ks = 0; ks < 4; ks++) {
            uint32_t af[4][4];
#pragma unroll
            for (int mt = 0; mt < 4; mt++)
                ldsm_x4(af[mt][0], af[mt][1], af[mt][2], af[mt][3],
                        st + A64_OFF + offA[ks][mt]);
            {
                uint32_t bf[4][2];
#pragma unroll
                for (int bt = 0; bt < 2; bt++)
                    ldsm_x4(bf[bt*2][0], bf[bt*2][1], bf[bt*2+1][0], bf[bt*2+1][1],
                            st + BZ64_OFF + offB[ks][bt]);
#pragma unroll
                for (int mt = 0; mt < 4; mt++)
#pragma unroll
                    for (int nt = 0; nt < 4; nt++)
                        mma_f16(accz[mt][nt], af[mt], bf[nt]);
            }
            {
                uint32_t bf[4][2];
#pragma unroll
                for (int bt = 0; bt < 2; bt++)
                    ldsm_x4(bf[bt*2][0], bf[bt*2][1], bf[bt*2+1][0], bf[bt*2+1][1],
                            st + BH64_OFF + offB[ks][bt]);
#pragma unroll
                for (int mt = 0; mt < 4; mt++)
#pragma unroll
                    for (int nt = 0; nt < 4; nt++)
                        mma_f16(acch[mt][nt], af[mt], bf[nt]);
            }
        }
    }

    __syncthreads();
    __half2* s_ab = (__half2*)smem;
    {
        const int er = lane >> 2;
        const int q2 = (lane & 3) * 2;
#pragma unroll
        for (int mt = 0; mt < 4; mt++) {
#pragma unroll
            for (int nt = 0; nt < 4; nt++) {
                const int tl0 = wr * 64 + mt * 16 + er;
                const int col = wc * 32 + nt * 8 + q2;
                const int n = nBase + col;
                const size_t g0 = (size_t)(mBase + tl0) * DD + n;
                const size_t g1 = g0 + 8 * DD;
                const float2 bz2 = *(const float2*)(&bz[n]);
                const float2 bh2 = *(const float2*)(&bh[n]);
                float z;
                __half2 p0, p1;
                z = sigmoidf_fast(accz[mt][nt][0] + bz2.x);
                p0.x = __float2half_rn(1.0f - z);
                p0.y = __float2half_rn(z * (acch[mt][nt][0] + bh2.x));
                z = sigmoidf_fast(accz[mt][nt][1] + bz2.y);
                p1.x = __float2half_rn(1.0f - z);
                p1.y = __float2half_rn(z * (acch[mt][nt][1] + bh2.y));
                *(uint2*)(&g_ab[g0]) = make_uint2(h2_to_u32(p0), h2_to_u32(p1));
                s_ab[tl0 * 129 + col]     = p0;
                s_ab[tl0 * 129 + col + 1] = p1;
                z = sigmoidf_fast(accz[mt][nt][2] + bz2.x);
                p0.x = __float2half_rn(1.0f - z);
                p0.y = __float2half_rn(z * (acch[mt][nt][2] + bh2.x));
                z = sigmoidf_fast(accz[mt][nt][3] + bz2.y);
                p1.x = __float2half_rn(1.0f - z);
                p1.y = __float2half_rn(z * (acch[mt][nt][3] + bh2.y));
                *(uint2*)(&g_ab[g1]) = make_uint2(h2_to_u32(p0), h2_to_u32(p1));
                s_ab[(tl0 + 8) * 129 + col]     = p0;
                s_ab[(tl0 + 8) * 129 + col + 1] = p1;
            }
        }
    }
    __syncthreads();
    {
        const int ch = tid >> 7;
        const int cl = tid & 127;
        float A = 1.0f, Bv = 0.0f;
#pragma unroll 8
        for (int t = 0; t < CHLEN; t++) {
            const float2 f = __half22float2(s_ab[(ch * 64 + t) * 129 + cl]);
            Bv = fmaf(f.x, Bv, f.y);
            A *= f.x;
        }
        const int bc = (mBase >> 6) + ch;
        g_Ac[(size_t)bc * DD + nBase + cl] = A;
        g_Bc[(size_t)bc * DD + nBase + cl] = Bv;
    }
}

// ---------------- FALLBACK 2 GEMM: BK=32, 48KB; needs scan_pass1 -------------
__global__ __launch_bounds__(256, 1)
void gemm32_kernel(const float* __restrict__ bz, const float* __restrict__ bh)
{
    extern __shared__ char smem[];
    const uint32_t sbase = smem_u32(smem);
    const int tid  = threadIdx.x;
    const int wid  = tid >> 5;
    const int lane = tid & 31;
    const int wr = wid >> 2;
    const int wc = wid & 3;

    const int nBase = blockIdx.x * 128;
    const int mBase = blockIdx.y * 128;

    int ldRow[2];
    int ldCol[2];
    uint32_t ldOff[2];
#pragma unroll
    for (int t = 0; t < 2; t++) {
        const int o = tid + t * 256;
        ldRow[t] = o >> 2;
        ldCol[t] = o & 3;
        ldOff[t] = SWZ64((uint32_t)(o * 16));
    }

    const int quad = lane >> 3;
    const int r8   = lane & 7;
    const int rowA = (quad & 1) * 8 + r8;
    const int kbA  = (quad >> 1) * 16;
    const int rowB = (quad >> 1) * 8 + r8;
    const int kbB  = (quad & 1) * 16;

    uint32_t offA[2][4], offB[2][2];
#pragma unroll
    for (int ks = 0; ks < 2; ks++) {
#pragma unroll
        for (int mt = 0; mt < 4; mt++)
            offA[ks][mt] = SWZ64((uint32_t)((wr * 64 + mt * 16 + rowA) * 64 + ks * 32 + kbA));
#pragma unroll
        for (int bt = 0; bt < 2; bt++)
            offB[ks][bt] = SWZ64((uint32_t)((wc * 32 + bt * 16 + rowB) * 64 + ks * 32 + kbB));
    }

    float accz[4][4][4], acch[4][4][4];
#pragma unroll
    for (int i = 0; i < 4; i++)
#pragma unroll
        for (int j = 0; j < 4; j++)
#pragma unroll
            for (int k = 0; k < 4; k++) { accz[i][j][k] = 0.0f; acch[i][j][k] = 0.0f; }

    auto load_chunk = [&](int chunk, int stage) {
        const int k0 = chunk * 32;
        const uint32_t st = sbase + stage * STAGE32;
#pragma unroll
        for (int t = 0; t < 2; t++) {
            const size_t rowOff = (size_t)ldRow[t] * DD + k0 + ldCol[t] * 8;
            cp16(st + A32_OFF  + ldOff[t], g_xh  + (size_t)mBase * DD + rowOff);
            cp16(st + BZ32_OFF + ldOff[t], g_Wtz + (size_t)nBase * DD + rowOff);
            cp16(st + BH32_OFF + ldOff[t], g_Wth + (size_t)nBase * DD + rowOff);
        }
        cp_commit();
    };

    load_chunk(0, 0);

    for (int i = 0; i < NCH32; i++) {
        const int s = i & 1;
        asm volatile("cp.async.wait_group 0;" ::: "memory");
        __syncthreads();
        if (i + 1 < NCH32) load_chunk(i + 1, s ^ 1);

        const uint32_t st = sbase + s * STAGE32;
#pragma unroll
        for (int ks = 0; ks < 2; ks++) {
            uint32_t af[4][4];
#pragma unroll
            for (int mt = 0; mt < 4; mt++)
                ldsm_x4(af[mt][0], af[mt][1], af[mt][2], af[mt][3],
                        st + A32_OFF + offA[ks][mt]);
            {
                uint32_t bf[4][2];
#pragma unroll
                for (int bt = 0; bt < 2; bt++)
                    ldsm_x4(bf[bt*2][0], bf[bt*2][1], bf[bt*2+1][0], bf[bt*2+1][1],
                            st + BZ32_OFF + offB[ks][bt]);
#pragma unroll
                for (int mt = 0; mt < 4; mt++)
#pragma unroll
                    for (int nt = 0; nt < 4; nt++)
                        mma_f16(accz[mt][nt], af[mt], bf[nt]);
            }
            {
                uint32_t bf[4][2];
#pragma unroll
                for (int bt = 0; bt < 2; bt++)
                    ldsm_x4(bf[bt*2][0], bf[bt*2][1], bf[bt*2+1][0], bf[bt*2+1][1],
                            st + BH32_OFF + offB[ks][bt]);
#pragma unroll
                for (int mt = 0; mt < 4; mt++)
#pragma unroll
                    for (int nt = 0; nt < 4; nt++)
                        mma_f16(acch[mt][nt], af[mt], bf[nt]);
            }
        }
    }

    const int er = lane >> 2;
    const int ec = (lane & 3) * 2;
#pragma unroll
    for (int mt = 0; mt < 4; mt++) {
#pragma unroll
        for (int nt = 0; nt < 4; nt++) {
            const int m = mBase + wr * 64 + mt * 16 + er;
            const int n = nBase + wc * 32 + nt * 8 + ec;
            const size_t g0 = (size_t)m * DD + n;
            const size_t g1 = g0 + 8 * DD;
            const float2 bz2 = *(const float2*)(&bz[n]);
            const float2 bh2 = *(const float2*)(&bh[n]);
            float z;
            __half2 p0, p1;
            z = sigmoidf_fast(accz[mt][nt][0] + bz2.x);
            p0.x = __float2half_rn(1.0f - z);
            p0.y = __float2half_rn(z * (acch[mt][nt][0] + bh2.x));
            z = sigmoidf_fast(accz[mt][nt][1] + bz2.y);
            p1.x = __float2half_rn(1.0f - z);
            p1.y = __float2half_rn(z * (acch[mt][nt][1] + bh2.y));
            *(uint2*)(&g_ab[g0]) = make_uint2(h2_to_u32(p0), h2_to_u32(p1));
            z = sigmoidf_fast(accz[mt][nt][2] + bz2.x);
            p0.x = __float2half_rn(1.0f - z);
            p0.y = __float2half_rn(z * (acch[mt][nt][2] + bh2.x));
            z = sigmoidf_fast(accz[mt][nt][3] + bz2.y);
            p1.x = __float2half_rn(1.0f - z);
            p1.y = __float2half_rn(z * (acch[mt][nt][3] + bh2.y));
            *(uint2*)(&g_ab[g1]) = make_uint2(h2_to_u32(p0), h2_to_u32(p1));
        }
    }
}

// ---------------- scan pass 1 (fallback path only) ----------------
__global__ __launch_bounds__(256)
void scan_pass1()
{
    const int g2 = blockIdx.x * 256 + threadIdx.x;   // (bc, d/2)
    const int bc = g2 >> 9;
    const int d0 = (g2 & 511) * 2;
    const size_t base = (size_t)bc * CHLEN * DD + d0;

    float2 Ar = make_float2(1.f, 1.f);
    float2 Br = make_float2(0.f, 0.f);
#pragma unroll 16
    for (int t = 0; t < CHLEN; t++) {
        const uint2 raw = *(const uint2*)&g_ab[base + (size_t)t * DD];
        const float2 ab0 = __half22float2(u32_to_h2(raw.x));
        const float2 ab1 = __half22float2(u32_to_h2(raw.y));
        Br.x = fmaf(ab0.x, Br.x, ab0.y); Ar.x *= ab0.x;
        Br.y = fmaf(ab1.x, Br.y, ab1.y); Ar.y *= ab1.x;
    }
    *(float2*)&g_Ac[(size_t)bc * DD + d0] = Ar;
    *(float2*)&g_Bc[(size_t)bc * DD + d0] = Br;
}

// ---------------- scan + swish: software-pipelined (depth-4 prefetch) --------
__global__ __launch_bounds__(256)
void scan_swish_kernel(const float* __restrict__ swish_beta)
{
    const int g2 = blockIdx.x * 256 + threadIdx.x;   // (bc, d/2)
    const int bc = g2 >> 9;
    const int d0 = (g2 & 511) * 2;
    const int b = bc >> 5;
    const int chunk = bc & 31;
    const float beta = __ldg(swish_beta);

    float2 h = make_float2(0.f, 0.f);
#pragma unroll 4
    for (int c = 0; c < chunk; c++) {
        const size_t idx = (size_t)(b * NCHUNK + c) * DD + d0;
        const float2 A = *(const float2*)&g_Ac[idx];
        const float2 B = *(const float2*)&g_Bc[idx];
        h.x = fmaf(A.x, h.x, B.x);
        h.y = fmaf(A.y, h.y, B.y);
    }

    const size_t base = (size_t)bc * CHLEN * DD + d0;

    uint2 buf[4];
#pragma unroll
    for (int j = 0; j < 4; j++)
        buf[j] = *(const uint2*)&g_ab[base + (size_t)j * DD];

    for (int t0 = 0; t0 < CHLEN; t0 += 4) {
        uint2 nxt[4];
        if (t0 + 4 < CHLEN) {
#pragma unroll
            for (int j = 0; j < 4; j++)
                nxt[j] = *(const uint2*)&g_ab[base + (size_t)(t0 + 4 + j) * DD];
        }
#pragma unroll
        for (int j = 0; j < 4; j++) {
            const float2 ab0 = __half22float2(u32_to_h2(buf[j].x));
            const float2 ab1 = __half22float2(u32_to_h2(buf[j].y));
            h.x = fmaf(ab0.x, h.x, ab0.y);
            h.y = fmaf(ab1.x, h.y, ab1.y);
            float s;
            __half2 y2;
            s = beta * h.x; y2.x = __float2half_rn(s * sigmoidf_fast(s));
            s = beta * h.y; y2.y = __float2half_rn(s * sigmoidf_fast(s));
            *(__half2*)&g_y16[base + (size_t)(t0 + j) * DD] = y2;
        }
#pragma unroll
        for (int j = 0; j < 4; j++) buf[j] = nxt[j];
    }
}

// ---------------- LayerNorm: one CTA per row, y16 in, fp32 out ----------------
__global__ __launch_bounds__(256)
void ln_kernel(const float* __restrict__ gamma,
               const float* __restrict__ lbeta,
               float* __restrict__ out)
{
    const int row = blockIdx.x;
    const int tid = threadIdx.x;
    const int lane = tid & 31;
    const int w = tid >> 5;
    const int d0 = tid * 4;

    const uint2 yr = *(const uint2*)&g_y16[(size_t)row * DD + d0];
    const float2 ya = __half22float2(u32_to_h2(yr.x));
    const float2 yb = __half22float2(u32_to_h2(yr.y));

    float s1 = ya.x + ya.y + yb.x + yb.y;
    float s2 = ya.x * ya.x + ya.y * ya.y + yb.x * yb.x + yb.y * yb.y;
#pragma unroll
    for (int o = 16; o > 0; o >>= 1) {
        s1 += __shfl_xor_sync(0xffffffffu, s1, o);
        s2 += __shfl_xor_sync(0xffffffffu, s2, o);
    }
    __shared__ float sa[8], sb[8];
    if (lane == 0) { sa[w] = s1; sb[w] = s2; }
    __syncthreads();
    if (w == 0) {
        float a1 = (lane < 8) ? sa[lane] : 0.0f;
        float b1 = (lane < 8) ? sb[lane] : 0.0f;
#pragma unroll
        for (int o = 4; o > 0; o >>= 1) {
            a1 += __shfl_xor_sync(0xffffffffu, a1, o);
            b1 += __shfl_xor_sync(0xffffffffu, b1, o);
        }
        if (lane == 0) { sa[0] = a1; sb[0] = b1; }
    }
    __syncthreads();
    const float mu  = sa[0] * (1.0f / DD);
    const float var = sb[0] * (1.0f / DD) - mu * mu;
    const float inv = rsqrtf(var + 1e-5f);

    const float4 gm = *(const float4*)&gamma[d0];
    const float4 bt = *(const float4*)&lbeta[d0];
    float4 o;
    o.x = (ya.x - mu) * inv * gm.x + bt.x;
    o.y = (ya.y - mu) * inv * gm.y + bt.y;
    o.z = (yb.x - mu) * inv * gm.z + bt.z;
    o.w = (yb.y - mu) * inv * gm.w + bt.w;
    *(float4*)&out[(size_t)row * DD + d0] = o;
}

// ---------------- launch ----------------
extern "C" void kernel_launch(void* const* d_in, const int* in_sizes, int n_in,
                              void* d_out, int out_size)
{
    const float* x     = (const float*)d_in[0];
    const float* Wz    = (const float*)d_in[1];
    const float* bz    = (const float*)d_in[2];
    const float* Wh    = (const float*)d_in[3];
    const float* bh    = (const float*)d_in[4];
    const float* sbeta = (const float*)d_in[5];
    const float* gamma = (const float*)d_in[6];
    const float* lbeta = (const float*)d_in[7];
    float* out = (float*)d_out;

    convert_x_kernel<<<(MM * DD) / (256 * 4), 256>>>(x);
    transpose_kernel<<<dim3(32, 32, 2), 256>>>(Wz, Wh);

    cudaError_t e1 = cudaFuncSetAttribute(
        gemmN64_kernel, cudaFuncAttributeMaxDynamicSharedMemorySize, 2 * STAGEN);
    if (e1 == cudaSuccess) {
        dim3 grid(DD / 64, MM / 128);    // (16, 128)
        gemmN64_kernel<<<grid, 256, 2 * STAGEN>>>(bz, bh);
    } else {
        (void)cudaGetLastError();
        cudaError_t e2 = cudaFuncSetAttribute(
            gemm64_kernel, cudaFuncAttributeMaxDynamicSharedMemorySize, 2 * STAGE64);
        dim3 grid(DD / 128, MM / 128);   // (8, 128)
        if (e2 == cudaSuccess) {
            gemm64_kernel<<<grid, 256, 2 * STAGE64>>>(bz, bh);
        } else {
            (void)cudaGetLastError();
            gemm32_kernel<<<grid, 256, 2 * STAGE32>>>(bz, bh);
            scan_pass1<<<(BB * NCHUNK * DD) / (256 * 2), 256>>>();
        }
    }

    scan_swish_kernel<<<(BB * NCHUNK * DD) / (256 * 2), 256>>>(sbeta);
    ln_kernel<<<MM, 256>>>(gamma, lbeta, out);
}

// round 15
// speedup vs baseline: 1.2632x; 1.0063x over previous
#include <cuda_runtime.h>
#include <cuda_fp16.h>
#include <math.h>
#include <stdint.h>

// Problem shape (fixed): B=8, T=2048, D=1024
#define BB   8
#define TT   2048
#define DD   1024
#define MM   (BB*TT)          // 16384 rows
#define NCHUNK 32
#define CHLEN  64

// ---- N64 GEMM (primary): CTA 128(M)x64(N), 2 outputs, warp 32x32, occ 2 ----
#define NCHN   16             // K chunks of 64
#define AN_OFF  0
#define BZN_OFF 16384
#define BHN_OFF 24576
#define STAGEN  32768          // 32KB per stage; 3 stages = 96KB (occ 2)

// ---- BK=64 GEMM (fallback 1): CTA 128x128, 96KB ----
#define NCH64   16
#define A64_OFF  0
#define BZ64_OFF 16384
#define BH64_OFF 32768
#define STAGE64  49152

// ---- BK=32 GEMM (fallback 2, 48KB default smem) ----
#define NCH32   32
#define A32_OFF  0
#define BZ32_OFF 8192
#define BH32_OFF 16384
#define STAGE32  24576

// ---------------- scratch (device globals) ----------------
__device__ __half2 g_ab[(size_t)MM * DD];   // {a, b} per element (fp16)
__device__ __half  g_y16[(size_t)MM * DD];  // swish output (fp16)
__device__ float   g_Ac[BB * NCHUNK * DD];  // chunk summaries (fp32)
__device__ float   g_Bc[BB * NCHUNK * DD];

__device__ __half g_xh[(size_t)MM * DD];    // x in fp16
__device__ __half g_Wtz[DD * DD];           // Wz^T fp16: [n][k]
__device__ __half g_Wth[DD * DD];           // Wh^T fp16: [n][k]

__device__ __forceinline__ float sigmoidf_fast(float v) {
    return 1.0f / (1.0f + __expf(-v));
}

// ---- bit casts ----
__device__ __forceinline__ uint32_t h2_to_u32(__half2 h) {
    return *reinterpret_cast<uint32_t*>(&h);
}
__device__ __forceinline__ __half2 u32_to_h2(uint32_t u) {
    return *reinterpret_cast<__half2*>(&u);
}

// ---------------- PTX helpers ----------------
__device__ __forceinline__ uint32_t smem_u32(const void* p) {
    uint32_t a;
    asm("{ .reg .u64 t; cvta.to.shared.u64 t, %1; cvt.u32.u64 %0, t; }" : "=r"(a) : "l"(p));
    return a;
}
#define SWZ64(o)  ((o) ^ (((o) >> 3) & 0x30))
#define SWZ128(o) ((o) ^ (((o) >> 3) & 0x70))

__device__ __forceinline__ void cp16(uint32_t s, const void* g) {
    asm volatile("cp.async.cg.shared.global [%0], [%1], 16;" :: "r"(s), "l"(g));
}
__device__ __forceinline__ void cp_commit() {
    asm volatile("cp.async.commit_group;" ::: "memory");
}
__device__ __forceinline__ void ldsm_x4(uint32_t& r0, uint32_t& r1, uint32_t& r2,
                                        uint32_t& r3, uint32_t addr) {
    asm volatile("ldmatrix.sync.aligned.m8n8.x4.shared.b16 {%0,%1,%2,%3}, [%4];"
                 : "=r"(r0), "=r"(r1), "=r"(r2), "=r"(r3) : "r"(addr));
}
__device__ __forceinline__ void mma_f16(float* d, const uint32_t* a, const uint32_t* b) {
    asm volatile(
        "mma.sync.aligned.m16n8k16.row.col.f32.f16.f16.f32 "
        "{%0,%1,%2,%3},{%4,%5,%6,%7},{%8,%9},{%0,%1,%2,%3};"
        : "+f"(d[0]), "+f"(d[1]), "+f"(d[2]), "+f"(d[3])
        : "r"(a[0]), "r"(a[1]), "r"(a[2]), "r"(a[3]), "r"(b[0]), "r"(b[1]));
}

// ---------------- prep: convert x to fp16 AND transpose W (one launch) -------
// blocks [0, MM*DD/1024)          : convert x
// blocks [MM*DD/1024, +2048)      : transpose Wz/Wh
#define CONV_BLOCKS ((MM * DD) / (256 * 4))
__global__ __launch_bounds__(256)
void prep_kernel(const float* __restrict__ x,
                 const float* __restrict__ Wz, const float* __restrict__ Wh)
{
    __shared__ float sm[32][33];
    if (blockIdx.x < CONV_BLOCKS) {
        const size_t i4 = (size_t)blockIdx.x * 256 + threadIdx.x;
        const float4 v = ((const float4*)x)[i4];
        __half2 p0, p1;
        p0.x = __float2half_rn(v.x); p0.y = __float2half_rn(v.y);
        p1.x = __float2half_rn(v.z); p1.y = __float2half_rn(v.w);
        ((__half2*)g_xh)[i4 * 2]     = p0;
        ((__half2*)g_xh)[i4 * 2 + 1] = p1;
    } else {
        const int bid = blockIdx.x - CONV_BLOCKS;   // 0..2047
        const int zz = bid >> 10;                   // 0: Wz, 1: Wh
        const int rem = bid & 1023;
        const int n0 = (rem & 31) * 32;
        const int k0 = (rem >> 5) * 32;
        const float* W = (zz == 0) ? Wz : Wh;
        __half* Wt = (zz == 0) ? g_Wtz : g_Wth;
        const int r = threadIdx.x >> 5;
        const int c = threadIdx.x & 31;
#pragma unroll
        for (int rr = 0; rr < 4; rr++) {
            const int row = rr * 8 + r;
            sm[row][c] = W[(size_t)(k0 + row) * DD + n0 + c];
        }
        __syncthreads();
#pragma unroll
        for (int rr = 0; rr < 4; rr++) {
            const int row = rr * 8 + r;
            Wt[(size_t)(n0 + row) * DD + k0 + c] = __float2half_rn(sm[c][row]);
        }
    }
}

// ---------------- PRIMARY GEMM: CTA 128x64, occ 2, 3-stage, 96KB smem --------
// Epilogue computes per-chunk scan summaries (2 chunks x 64 cols per CTA).
__global__ __launch_bounds__(256, 2)
void gemmN64_kernel(const float* __restrict__ bz, const float* __restrict__ bh)
{
    extern __shared__ char smem[];
    const uint32_t sbase = smem_u32(smem);
    const int tid  = threadIdx.x;
    const int wid  = tid >> 5;
    const int lane = tid & 31;
    const int wr = wid >> 1;           // 0..3: M 32-row strip
    const int wc = wid & 1;            // 0..1: N 32-col strip

    const int nBase = blockIdx.x * 64;
    const int mBase = blockIdx.y * 128;

    // cp.async addressing (128B rows): A 4x, B 2x each
    int ldRowA[4], ldColA[4];
    uint32_t ldOffA[4];
#pragma unroll
    for (int t = 0; t < 4; t++) {
        const int o = tid + t * 256;
        ldRowA[t] = o >> 3; ldColA[t] = o & 7;
        ldOffA[t] = SWZ128((uint32_t)(o * 16));
    }
    int ldRowB[2], ldColB[2];
    uint32_t ldOffB[2];
#pragma unroll
    for (int t = 0; t < 2; t++) {
        const int o = tid + t * 256;
        ldRowB[t] = o >> 3; ldColB[t] = o & 7;
        ldOffB[t] = SWZ128((uint32_t)(o * 16));
    }

    // ldmatrix static offsets (128B rows, 4 k-steps)
    const int quad = lane >> 3;
    const int r8   = lane & 7;
    const int rowA = (quad & 1) * 8 + r8;
    const int kbA  = (quad >> 1) * 16;
    const int rowB = (quad >> 1) * 8 + r8;
    const int kbB  = (quad & 1) * 16;

    uint32_t offA[4][2], offB[4][2];
#pragma unroll
    for (int ks = 0; ks < 4; ks++) {
#pragma unroll
        for (int mt = 0; mt < 2; mt++)
            offA[ks][mt] = SWZ128((uint32_t)((wr * 32 + mt * 16 + rowA) * 128 + ks * 32 + kbA));
#pragma unroll
        for (int bt = 0; bt < 2; bt++)
            offB[ks][bt] = SWZ128((uint32_t)((wc * 32 + bt * 16 + rowB) * 128 + ks * 32 + kbB));
    }

    float accz[2][4][4], acch[2][4][4];
#pragma unroll
    for (int i = 0; i < 2; i++)
#pragma unroll
        for (int j = 0; j < 4; j++)
#pragma unroll
            for (int k = 0; k < 4; k++) { accz[i][j][k] = 0.0f; acch[i][j][k] = 0.0f; }

    auto load_chunk = [&](int chunk, int stage) {
        const int k0 = chunk * 64;
        const uint32_t st = sbase + stage * STAGEN;
#pragma unroll
        for (int t = 0; t < 4; t++)
            cp16(st + AN_OFF + ldOffA[t],
                 g_xh + (size_t)(mBase + ldRowA[t]) * DD + k0 + ldColA[t] * 8);
#pragma unroll
        for (int t = 0; t < 2; t++) {
            const size_t rowOff = (size_t)(nBase + ldRowB[t]) * DD + k0 + ldColB[t] * 8;
            cp16(st + BZN_OFF + ldOffB[t], g_Wtz + rowOff);
            cp16(st + BHN_OFF + ldOffB[t], g_Wth + rowOff);
        }
        cp_commit();
    };

    // 3-stage prologue: chunks 0,1 in flight
    load_chunk(0, 0);
    load_chunk(1, 1);

    for (int i = 0; i < NCHN; i++) {
        const int s = i % 3;
        // chunk i complete: allow <=1 pending (chunk i+1) in steady state
        if (i < NCHN - 1) asm volatile("cp.async.wait_group 1;" ::: "memory");
        else              asm volatile("cp.async.wait_group 0;" ::: "memory");
        __syncthreads();
        // stage (i+2)%3 == (i-1)%3: consumed in iteration i-1 (sync above)
        if (i + 2 < NCHN) load_chunk(i + 2, (i + 2) % 3);

        const uint32_t st = sbase + s * STAGEN;
#pragma unroll
        for (int ks = 0; ks < 4; ks++) {
            uint32_t af[2][4];
#pragma unroll
            for (int mt = 0; mt < 2; mt++)
                ldsm_x4(af[mt][0], af[mt][1], af[mt][2], af[mt][3],
                        st + AN_OFF + offA[ks][mt]);
            {
                uint32_t bf[4][2];
#pragma unroll
                for (int bt = 0; bt < 2; bt++)
                    ldsm_x4(bf[bt*2][0], bf[bt*2][1], bf[bt*2+1][0], bf[bt*2+1][1],
                            st + BZN_OFF + offB[ks][bt]);
#pragma unroll
                for (int mt = 0; mt < 2; mt++)
#pragma unroll
                    for (int nt = 0; nt < 4; nt++)
                        mma_f16(accz[mt][nt], af[mt], bf[nt]);
            }
            {
                uint32_t bf[4][2];
#pragma unroll
                for (int bt = 0; bt < 2; bt++)
                    ldsm_x4(bf[bt*2][0], bf[bt*2][1], bf[bt*2+1][0], bf[bt*2+1][1],
                            st + BHN_OFF + offB[ks][bt]);
#pragma unroll
                for (int mt = 0; mt < 2; mt++)
#pragma unroll
                    for (int nt = 0; nt < 4; nt++)
                        mma_f16(acch[mt][nt], af[mt], bf[nt]);
            }
        }
    }

    // ---- epilogue: g_ab to gmem + stage {a,b} into smem [128][65] ----
    __syncthreads();   // all warps done reading pipeline smem before reuse
    __half2* s_ab = (__half2*)smem;   // 128*65*4 = 33280 B <= 96KB
    {
        const int er = lane >> 2;
        const int q2 = (lane & 3) * 2;
#pragma unroll
        for (int mt = 0; mt < 2; mt++) {
#pragma unroll
            for (int nt = 0; nt < 4; nt++) {
                const int tl0 = wr * 32 + mt * 16 + er;
                const int col = wc * 32 + nt * 8 + q2;
                const int n = nBase + col;
                const size_t g0 = (size_t)(mBase + tl0) * DD + n;
                const size_t g1 = g0 + 8 * DD;
                const float2 bz2 = *(const float2*)(&bz[n]);
                const float2 bh2 = *(const float2*)(&bh[n]);
                float z;
                __half2 p0, p1;
                z = sigmoidf_fast(accz[mt][nt][0] + bz2.x);
                p0.x = __float2half_rn(1.0f - z);
                p0.y = __float2half_rn(z * (acch[mt][nt][0] + bh2.x));
                z = sigmoidf_fast(accz[mt][nt][1] + bz2.y);
                p1.x = __float2half_rn(1.0f - z);
                p1.y = __float2half_rn(z * (acch[mt][nt][1] + bh2.y));
                *(uint2*)(&g_ab[g0]) = make_uint2(h2_to_u32(p0), h2_to_u32(p1));
                s_ab[tl0 * 65 + col]     = p0;
                s_ab[tl0 * 65 + col + 1] = p1;
                z = sigmoidf_fast(accz[mt][nt][2] + bz2.x);
                p0.x = __float2half_rn(1.0f - z);
                p0.y = __float2half_rn(z * (acch[mt][nt][2] + bh2.x));
                z = sigmoidf_fast(accz[mt][nt][3] + bz2.y);
                p1.x = __float2half_rn(1.0f - z);
                p1.y = __float2half_rn(z * (acch[mt][nt][3] + bh2.y));
                *(uint2*)(&g_ab[g1]) = make_uint2(h2_to_u32(p0), h2_to_u32(p1));
                s_ab[(tl0 + 8) * 65 + col]     = p0;
                s_ab[(tl0 + 8) * 65 + col + 1] = p1;
            }
        }
    }
    __syncthreads();

    // ---- per-chunk scan summaries: threads 0..127 = (chunk_local, column) ---
    if (tid < 128) {
        const int ch = tid >> 6;          // 0..1
        const int cl = tid & 63;
        float A = 1.0f, Bv = 0.0f;
#pragma unroll 8
        for (int t = 0; t < CHLEN; t++) {
            const float2 f = __half22float2(s_ab[(ch * 64 + t) * 65 + cl]);
            Bv = fmaf(f.x, Bv, f.y);
            A *= f.x;
        }
        const int bc = (mBase >> 6) + ch;   // global chunk index = m/64
        g_Ac[(size_t)bc * DD + nBase + cl] = A;
        g_Bc[(size_t)bc * DD + nBase + cl] = Bv;
    }
}

// ---------------- FALLBACK 1 GEMM: BK=64, CTA 128x128, 96KB smem -------------
__global__ __launch_bounds__(256, 1)
void gemm64_kernel(const float* __restrict__ bz, const float* __restrict__ bh)
{
    extern __shared__ char smem[];
    const uint32_t sbase = smem_u32(smem);
    const int tid  = threadIdx.x;
    const int wid  = tid >> 5;
    const int lane = tid & 31;
    const int wr = wid >> 2;
    const int wc = wid & 3;

    const int nBase = blockIdx.x * 128;
    const int mBase = blockIdx.y * 128;

    int ldRow[4];
    int ldCol[4];
    uint32_t ldOff[4];
#pragma unroll
    for (int t = 0; t < 4; t++) {
        const int o = tid + t * 256;
        ldRow[t] = o >> 3;
        ldCol[t] = o & 7;
        ldOff[t] = SWZ128((uint32_t)(o * 16));
    }

    const int quad = lane >> 3;
    const int r8   = lane & 7;
    const int rowA = (quad & 1) * 8 + r8;
    const int kbA  = (quad >> 1) * 16;
    const int rowB = (quad >> 1) * 8 + r8;
    const int kbB  = (quad & 1) * 16;

    uint32_t offA[4][4], offB[4][2];
#pragma unroll
    for (int ks = 0; ks < 4; ks++) {
#pragma unroll
        for (int mt = 0; mt < 4; mt++)
            offA[ks][mt] = SWZ128((uint32_t)((wr * 64 + mt * 16 + rowA) * 128 + ks * 32 + kbA));
#pragma unroll
        for (int bt = 0; bt < 2; bt++)
            offB[ks][bt] = SWZ128((uint32_t)((wc * 32 + bt * 16 + rowB) * 128 + ks * 32 + kbB));
    }

    float accz[4][4][4], acch[4][4][4];
#pragma unroll
    for (int i = 0; i < 4; i++)
#pragma unroll
        for (int j = 0; j < 4; j++)
#pragma unroll
            for (int k = 0; k < 4; k++) { accz[i][j][k] = 0.0f; acch[i][j][k] = 0.0f; }

    auto load_chunk = [&](int chunk, int stage) {
        const int k0 = chunk * 64;
        const uint32_t st = sbase + stage * STAGE64;
#pragma unroll
        for (int t = 0; t < 4; t++) {
            const size_t rowOff = (size_t)ldRow[t] * DD + k0 + ldCol[t] * 8;
            cp16(st + A64_OFF  + ldOff[t], g_xh  + (size_t)mBase * DD + rowOff);
            cp16(st + BZ64_OFF + ldOff[t], g_Wtz + (size_t)nBase * DD + rowOff);
            cp16(st + BH64_OFF + ldOff[t], g_Wth + (size_t)nBase * DD + rowOff);
        }
        cp_commit();
    };

    load_chunk(0, 0);

    for (int i = 0; i < NCH64; i++) {
        const int s = i & 1;
        asm volatile("cp.async.wait_group 0;" ::: "memory");
        __syncthreads();
        if (i + 1 < NCH64) load_chunk(i + 1, s ^ 1);

        const uint32_t st = sbase + s * STAGE64;
#pragma unroll
        for (int ks = 0; ks < 4; ks++) {
            uint32_t af[4][4];
#pragma unroll
            for (int mt = 0; mt < 4; mt++)
                ldsm_x4(af[mt][0], af[mt][1], af[mt][2], af[mt][3],
                        st + A64_OFF + offA[ks][mt]);
            {
                uint32_t bf[4][2];
#pragma unroll
                for (int bt = 0; bt < 2; bt++)
                    ldsm_x4(bf[bt*2][0], bf[bt*2][1], bf[bt*2+1][0], bf[bt*2+1][1],
                            st + BZ64_OFF + offB[ks][bt]);
#pragma unroll
                for (int mt = 0; mt < 4; mt++)
#pragma unroll
                    for (int nt = 0; nt < 4; nt++)
                        mma_f16(accz[mt][nt], af[mt], bf[nt]);
            }
            {
                uint32_t bf[4][2];
#pragma unroll
                for (int bt = 0; bt < 2; bt++)
                    ldsm_x4(bf[bt*2][0], bf[bt*2][1], bf[bt*2+1][0], bf[bt*2+1][1],
                            st + BH64_OFF + offB[ks][bt]);
#pragma unroll
                for (int mt = 0; mt < 4; mt++)
#pragma unroll
                    for (int nt = 0; nt < 4; nt++)
                        mma_f16(acch[mt][nt], af[mt], bf[nt]);
            }
        }
    }

    __syncthreads();
    __half2* s_ab = (__half2*)smem;
    {
        const int er = lane >> 2;
        const int q2 = (lane & 3) * 2;
#pragma unroll
        for (int mt = 0; mt < 4; mt++) {
#pragma unroll
            for (int nt = 0; nt < 4; nt++) {
                const int tl0 = wr * 64 + mt * 16 + er;
                const int col = wc * 32 + nt * 8 + q2;
                const int n = nBase + col;
                const size_t g0 = (size_t)(mBase + tl0) * DD + n;
                const size_t g1 = g0 + 8 * DD;
                const float2 bz2 = *(const float2*)(&bz[n]);
                const float2 bh2 = *(const float2*)(&bh[n]);
                float z;
                __half2 p0, p1;
                z = sigmoidf_fast(accz[mt][nt][0] + bz2.x);
                p0.x = __float2half_rn(1.0f - z);
                p0.y = __float2half_rn(z * (acch[mt][nt][0] + bh2.x));
                z = sigmoidf_fast(accz[mt][nt][1] + bz2.y);
                p1.x = __float2half_rn(1.0f - z);
                p1.y = __float2half_rn(z * (acch[mt][nt][1] + bh2.y));
                *(uint2*)(&g_ab[g0]) = make_uint2(h2_to_u32(p0), h2_to_u32(p1));
                s_ab[tl0 * 129 + col]     = p0;
                s_ab[tl0 * 129 + col + 1] = p1;
                z = sigmoidf_fast(accz[mt][nt][2] + bz2.x);
                p0.x = __float2half_rn(1.0f - z);
                p0.y = __float2half_rn(z * (acch[mt][nt][2] + bh2.x));
                z = sigmoidf_fast(accz[mt][nt][3] + bz2.y);
                p1.x = __float2half_rn(1.0f - z);
                p1.y = __float2half_rn(z * (acch[mt][nt][3] + bh2.y));
                *(uint2*)(&g_ab[g1]) = make_uint2(h2_to_u32(p0), h2_to_u32(p1));
                s_ab[(tl0 + 8) * 129 + col]     = p0;
                s_ab[(tl0 + 8) * 129 + col + 1] = p1;
            }
        }
    }
    __syncthreads();
    {
        const int ch = tid >> 7;
        const int cl = tid & 127;
        float A = 1.0f, Bv = 0.0f;
#pragma unroll 8
        for (int t = 0; t < CHLEN; t++) {
            const float2 f = __half22float2(s_ab[(ch * 64 + t) * 129 + cl]);
            Bv = fmaf(f.x, Bv, f.y);
            A *= f.x;
        }
        const int bc = (mBase >> 6) + ch;
        g_Ac[(size_t)bc * DD + nBase + cl] = A;
        g_Bc[(size_t)bc * DD + nBase + cl] = Bv;
    }
}

// ---------------- FALLBACK 2 GEMM: BK=32, 48KB; needs scan_pass1 -------------
__global__ __launch_bounds__(256, 1)
void gemm32_kernel(const float* __restrict__ bz, const float* __restrict__ bh)
{
    extern __shared__ char smem[];
    const uint32_t sbase = smem_u32(smem);
    const int tid  = threadIdx.x;
    const int wid  = tid >> 5;
    const int lane = tid & 31;
    const int wr = wid >> 2;
    const int wc = wid & 3;

    const int nBase = blockIdx.x * 128;
    const int mBase = blockIdx.y * 128;

    int ldRow[2];
    int ldCol[2];
    uint32_t ldOff[2];
#pragma unroll
    for (int t = 0; t < 2; t++) {
        const int o = tid + t * 256;
        ldRow[t] = o >> 2;
        ldCol[t] = o & 3;
        ldOff[t] = SWZ64((uint32_t)(o * 16));
    }

    const int quad = lane >> 3;
    const int r8   = lane & 7;
    const int rowA = (quad & 1) * 8 + r8;
    const int kbA  = (quad >> 1) * 16;
    const int rowB = (quad >> 1) * 8 + r8;
    const int kbB  = (quad & 1) * 16;

    uint32_t offA[2][4], offB[2][2];
#pragma unroll
    for (int ks = 0; ks < 2; ks++) {
#pragma unroll
        for (int mt = 0; mt < 4; mt++)
            offA[ks][mt] = SWZ64((uint32_t)((wr * 64 + mt * 16 + rowA) * 64 + ks * 32 + kbA));
#pragma unroll
        for (int bt = 0; bt < 2; bt++)
            offB[ks][bt] = SWZ64((uint32_t)((wc * 32 + bt * 16 + rowB) * 64 + ks * 32 + kbB));
    }

    float accz[4][4][4], acch[4][4][4];
#pragma unroll
    for (int i = 0; i < 4; i++)
#pragma unroll
        for (int j = 0; j < 4; j++)
#pragma unroll
            for (int k = 0; k < 4; k++) { accz[i][j][k] = 0.0f; acch[i][j][k] = 0.0f; }

    auto load_chunk = [&](int chunk, int stage) {
        const int k0 = chunk * 32;
        const uint32_t st = sbase + stage * STAGE32;
#pragma unroll
        for (int t = 0; t < 2; t++) {
            const size_t rowOff = (size_t)ldRow[t] * DD + k0 + ldCol[t] * 8;
            cp16(st + A32_OFF  + ldOff[t], g_xh  + (size_t)mBase * DD + rowOff);
            cp16(st + BZ32_OFF + ldOff[t], g_Wtz + (size_t)nBase * DD + rowOff);
            cp16(st + BH32_OFF + ldOff[t], g_Wth + (size_t)nBase * DD + rowOff);
        }
        cp_commit();
    };

    load_chunk(0, 0);

    for (int i = 0; i < NCH32; i++) {
        const int s = i & 1;
        asm volatile("cp.async.wait_group 0;" ::: "memory");
        __syncthreads();
        if (i + 1 < NCH32) load_chunk(i + 1, s ^ 1);

        const uint32_t st = sbase + s * STAGE32;
#pragma unroll
        for (int ks = 0; ks < 2; ks++) {
            uint32_t af[4][4];
#pragma unroll
            for (int mt = 0; mt < 4; mt++)
                ldsm_x4(af[mt][0], af[mt][1], af[mt][2], af[mt][3],
                        st + A32_OFF + offA[ks][mt]);
            {
                uint32_t bf[4][2];
#pragma unroll
                for (int bt = 0; bt < 2; bt++)
                    ldsm_x4(bf[bt*2][0], bf[bt*2][1], bf[bt*2+1][0], bf[bt*2+1][1],
                            st + BZ32_OFF + offB[ks][bt]);
#pragma unroll
                for (int mt = 0; mt < 4; mt++)
#pragma unroll
                    for (int nt = 0; nt < 4; nt++)
                        mma_f16(accz[mt][nt], af[mt], bf[nt]);
            }
            {
                uint32_t bf[4][2];
#pragma unroll
                for (int bt = 0; bt < 2; bt++)
                    ldsm_x4(bf[bt*2][0], bf[bt*2][1], bf[bt*2+1][0], bf[bt*2+1][1],
                            st + BH32_OFF + offB[ks][bt]);
#pragma unroll
                for (int mt = 0; mt < 4; mt++)
#pragma unroll
                    for (int nt = 0; nt < 4; nt++)
                        mma_f16(acch[mt][nt], af[mt], bf[nt]);
            }
        }
    }

    const int er = lane >> 2;
    const int ec = (lane & 3) * 2;
#pragma unroll
    for (int mt = 0; mt < 4; mt++) {
#pragma unroll
        for (int nt = 0; nt < 4; nt++) {
            const int m = mBase + wr * 64 + mt * 16 + er;
            const int n = nBase + wc * 32 + nt * 8 + ec;
            const size_t g0 = (size_t)m * DD + n;
            const size_t g1 = g0 + 8 * DD;
            const float2 bz2 = *(const float2*)(&bz[n]);
            const float2 bh2 = *(const float2*)(&bh[n]);
            float z;
            __half2 p0, p1;
            z = sigmoidf_fast(accz[mt][nt][0] + bz2.x);
            p0.x = __float2half_rn(1.0f - z);
            p0.y = __float2half_rn(z * (acch[mt][nt][0] + bh2.x));
            z = sigmoidf_fast(accz[mt][nt][1] + bz2.y);
            p1.x = __float2half_rn(1.0f - z);
            p1.y = __float2half_rn(z * (acch[mt][nt][1] + bh2.y));
            *(uint2*)(&g_ab[g0]) = make_uint2(h2_to_u32(p0), h2_to_u32(p1));
            z = sigmoidf_fast(accz[mt][nt][2] + bz2.x);
            p0.x = __float2half_rn(1.0f - z);
            p0.y = __float2half_rn(z * (acch[mt][nt][2] + bh2.x));
            z = sigmoidf_fast(accz[mt][nt][3] + bz2.y);
            p1.x = __float2half_rn(1.0f - z);
            p1.y = __float2half_rn(z * (acch[mt][nt][3] + bh2.y));
            *(uint2*)(&g_ab[g1]) = make_uint2(h2_to_u32(p0), h2_to_u32(p1));
        }
    }
}

// ---------------- scan pass 1 (fallback path only) ----------------
__global__ __launch_bounds__(256)
void scan_pass1()
{
    const int g2 = blockIdx.x * 256 + threadIdx.x;   // (bc, d/2)
    const int bc = g2 >> 9;
    const int d0 = (g2 & 511) * 2;
    const size_t base = (size_t)bc * CHLEN * DD + d0;

    float2 Ar = make_float2(1.f, 1.f);
    float2 Br = make_float2(0.f, 0.f);
#pragma unroll 16
    for (int t = 0; t < CHLEN; t++) {
        const uint2 raw = *(const uint2*)&g_ab[base + (size_t)t * DD];
        const float2 ab0 = __half22float2(u32_to_h2(raw.x));
        const float2 ab1 = __half22float2(u32_to_h2(raw.y));
        Br.x = fmaf(ab0.x, Br.x, ab0.y); Ar.x *= ab0.x;
        Br.y = fmaf(ab1.x, Br.y, ab1.y); Ar.y *= ab1.x;
    }
    *(float2*)&g_Ac[(size_t)bc * DD + d0] = Ar;
    *(float2*)&g_Bc[(size_t)bc * DD + d0] = Br;
}

// ---------------- scan + swish: software-pipelined (depth-4 prefetch) --------
__global__ __launch_bounds__(256)
void scan_swish_kernel(const float* __restrict__ swish_beta)
{
    const int g2 = blockIdx.x * 256 + threadIdx.x;   // (bc, d/2)
    const int bc = g2 >> 9;
    const int d0 = (g2 & 511) * 2;
    const int b = bc >> 5;
    const int chunk = bc & 31;
    const float beta = __ldg(swish_beta);

    float2 h = make_float2(0.f, 0.f);
#pragma unroll 4
    for (int c = 0; c < chunk; c++) {
        const size_t idx = (size_t)(b * NCHUNK + c) * DD + d0;
        const float2 A = *(const float2*)&g_Ac[idx];
        const float2 B = *(const float2*)&g_Bc[idx];
        h.x = fmaf(A.x, h.x, B.x);
        h.y = fmaf(A.y, h.y, B.y);
    }

    const size_t base = (size_t)bc * CHLEN * DD + d0;

    uint2 buf[4];
#pragma unroll
    for (int j = 0; j < 4; j++)
        buf[j] = *(const uint2*)&g_ab[base + (size_t)j * DD];

    for (int t0 = 0; t0 < CHLEN; t0 += 4) {
        uint2 nxt[4];
        if (t0 + 4 < CHLEN) {
#pragma unroll
            for (int j = 0; j < 4; j++)
                nxt[j] = *(const uint2*)&g_ab[base + (size_t)(t0 + 4 + j) * DD];
        }
#pragma unroll
        for (int j = 0; j < 4; j++) {
            const float2 ab0 = __half22float2(u32_to_h2(buf[j].x));
            const float2 ab1 = __half22float2(u32_to_h2(buf[j].y));
            h.x = fmaf(ab0.x, h.x, ab0.y);
            h.y = fmaf(ab1.x, h.y, ab1.y);
            float s;
            __half2 y2;
            s = beta * h.x; y2.x = __float2half_rn(s * sigmoidf_fast(s));
            s = beta * h.y; y2.y = __float2half_rn(s * sigmoidf_fast(s));
            *(__half2*)&g_y16[base + (size_t)(t0 + j) * DD] = y2;
        }
#pragma unroll
        for (int j = 0; j < 4; j++) buf[j] = nxt[j];
    }
}

// ---------------- LayerNorm: one CTA per row, y16 in, fp32 out ----------------
__global__ __launch_bounds__(256)
void ln_kernel(const float* __restrict__ gamma,
               const float* __restrict__ lbeta,
               float* __restrict__ out)
{
    const int row = blockIdx.x;
    const int tid = threadIdx.x;
    const int lane = tid & 31;
    const int w = tid >> 5;
    const int d0 = tid * 4;

    const uint2 yr = *(const uint2*)&g_y16[(size_t)row * DD + d0];
    const float2 ya = __half22float2(u32_to_h2(yr.x));
    const float2 yb = __half22float2(u32_to_h2(yr.y));

    float s1 = ya.x + ya.y + yb.x + yb.y;
    float s2 = ya.x * ya.x + ya.y * ya.y + yb.x * yb.x + yb.y * yb.y;
#pragma unroll
    for (int o = 16; o > 0; o >>= 1) {
        s1 += __shfl_xor_sync(0xffffffffu, s1, o);
        s2 += __shfl_xor_sync(0xffffffffu, s2, o);
    }
    __shared__ float sa[8], sb[8];
    if (lane == 0) { sa[w] = s1; sb[w] = s2; }
    __syncthreads();
    if (w == 0) {
        float a1 = (lane < 8) ? sa[lane] : 0.0f;
        float b1 = (lane < 8) ? sb[lane] : 0.0f;
#pragma unroll
        for (int o = 4; o > 0; o >>= 1) {
            a1 += __shfl_xor_sync(0xffffffffu, a1, o);
            b1 += __shfl_xor_sync(0xffffffffu, b1, o);
        }
        if (lane == 0) { sa[0] = a1; sb[0] = b1; }
    }
    __syncthreads();
    const float mu  = sa[0] * (1.0f / DD);
    const float var = sb[0] * (1.0f / DD) - mu * mu;
    const float inv = rsqrtf(var + 1e-5f);

    const float4 gm = *(const float4*)&gamma[d0];
    const float4 bt = *(const float4*)&lbeta[d0];
    float4 o;
    o.x = (ya.x - mu) * inv * gm.x + bt.x;
    o.y = (ya.y - mu) * inv * gm.y + bt.y;
    o.z = (yb.x - mu) * inv * gm.z + bt.z;
    o.w = (yb.y - mu) * inv * gm.w + bt.w;
    *(float4*)&out[(size_t)row * DD + d0] = o;
}

// ---------------- launch ----------------
extern "C" void kernel_launch(void* const* d_in, const int* in_sizes, int n_in,
                              void* d_out, int out_size)
{
    const float* x     = (const float*)d_in[0];
    const float* Wz    = (const float*)d_in[1];
    const float* bz    = (const float*)d_in[2];
    const float* Wh    = (const float*)d_in[3];
    const float* bh    = (const float*)d_in[4];
    const float* sbeta = (const float*)d_in[5];
    const float* gamma = (const float*)d_in[6];
    const float* lbeta = (const float*)d_in[7];
    float* out = (float*)d_out;

    prep_kernel<<<CONV_BLOCKS + 2048, 256>>>(x, Wz, Wh);

    cudaError_t e1 = cudaFuncSetAttribute(
        gemmN64_kernel, cudaFuncAttributeMaxDynamicSharedMemorySize, 3 * STAGEN);
    if (e1 == cudaSuccess) {
        dim3 grid(DD / 64, MM / 128);    // (16, 128)
        gemmN64_kernel<<<grid, 256, 3 * STAGEN>>>(bz, bh);
    } else {
        (void)cudaGetLastError();
        cudaError_t e2 = cudaFuncSetAttribute(
            gemm64_kernel, cudaFuncAttributeMaxDynamicSharedMemorySize, 2 * STAGE64);
        dim3 grid(DD / 128, MM / 128);   // (8, 128)
        if (e2 == cudaSuccess) {
            gemm64_kernel<<<grid, 256, 2 * STAGE64>>>(bz, bh);
        } else {
            (void)cudaGetLastError();
            gemm32_kernel<<<grid, 256, 2 * STAGE32>>>(bz, bh);
            scan_pass1<<<(BB * NCHUNK * DD) / (256 * 2), 256>>>();
        }
    }

    scan_swish_kernel<<<(BB * NCHUNK * DD) / (256 * 2), 256>>>(sbeta);
    ln_kernel<<<MM, 256>>>(gamma, lbeta, out);
}

// round 16
// speedup vs baseline: 1.2671x; 1.0031x over previous
#include <cuda_runtime.h>
#include <cuda_fp16.h>
#include <math.h>
#include <stdint.h>

// Problem shape (fixed): B=8, T=2048, D=1024
#define BB   8
#define TT   2048
#define DD   1024
#define MM   (BB*TT)          // 16384 rows
#define NCHUNK 32
#define CHLEN  64

// ---- N64 GEMM (primary): CTA 128(M)x64(N), 2 outputs, warp 32x32, occ 2 ----
#define NCHN   16             // K chunks of 64
#define AN_OFF  0
#define BZN_OFF 16384
#define BHN_OFF 24576
#define STAGEN  32768          // 32KB per stage; 3 stages = 96KB (occ 2)

// ---- BK=64 GEMM (fallback 1): CTA 128x128, 96KB ----
#define NCH64   16
#define A64_OFF  0
#define BZ64_OFF 16384
#define BH64_OFF 32768
#define STAGE64  49152

// ---- BK=32 GEMM (fallback 2, 48KB default smem) ----
#define NCH32   32
#define A32_OFF  0
#define BZ32_OFF 8192
#define BH32_OFF 16384
#define STAGE32  24576

// ---------------- scratch (device globals) ----------------
__device__ __half2 g_ab[(size_t)MM * DD];   // {a, b} per element (fp16)
__device__ __half  g_y16[(size_t)MM * DD];  // swish output (fp16)
__device__ float   g_Ac[BB * NCHUNK * DD];  // chunk summaries (fp32)
__device__ float   g_Bc[BB * NCHUNK * DD];

__device__ __half g_xh[(size_t)MM * DD];    // x in fp16
__device__ __half g_Wtz[DD * DD];           // Wz^T fp16: [n][k]
__device__ __half g_Wth[DD * DD];           // Wh^T fp16: [n][k]

__device__ __forceinline__ float sigmoidf_fast(float v) {
    return 1.0f / (1.0f + __expf(-v));
}

// ---- bit casts ----
__device__ __forceinline__ uint32_t h2_to_u32(__half2 h) {
    return *reinterpret_cast<uint32_t*>(&h);
}
__device__ __forceinline__ __half2 u32_to_h2(uint32_t u) {
    return *reinterpret_cast<__half2*>(&u);
}

// ---------------- PTX helpers ----------------
__device__ __forceinline__ uint32_t smem_u32(const void* p) {
    uint32_t a;
    asm("{ .reg .u64 t; cvta.to.shared.u64 t, %1; cvt.u32.u64 %0, t; }" : "=r"(a) : "l"(p));
    return a;
}
#define SWZ64(o)  ((o) ^ (((o) >> 3) & 0x30))
#define SWZ128(o) ((o) ^ (((o) >> 3) & 0x70))

__device__ __forceinline__ void cp16(uint32_t s, const void* g) {
    asm volatile("cp.async.cg.shared.global [%0], [%1], 16;" :: "r"(s), "l"(g));
}
__device__ __forceinline__ void cp_commit() {
    asm volatile("cp.async.commit_group;" ::: "memory");
}
__device__ __forceinline__ void ldsm_x4(uint32_t& r0, uint32_t& r1, uint32_t& r2,
                                        uint32_t& r3, uint32_t addr) {
    asm volatile("ldmatrix.sync.aligned.m8n8.x4.shared.b16 {%0,%1,%2,%3}, [%4];"
                 : "=r"(r0), "=r"(r1), "=r"(r2), "=r"(r3) : "r"(addr));
}
__device__ __forceinline__ void mma_f16(float* d, const uint32_t* a, const uint32_t* b) {
    asm volatile(
        "mma.sync.aligned.m16n8k16.row.col.f32.f16.f16.f32 "
        "{%0,%1,%2,%3},{%4,%5,%6,%7},{%8,%9},{%0,%1,%2,%3};"
        : "+f"(d[0]), "+f"(d[1]), "+f"(d[2]), "+f"(d[3])
        : "r"(a[0]), "r"(a[1]), "r"(a[2]), "r"(a[3]), "r"(b[0]), "r"(b[1]));
}

// ---------------- prep: convert x to fp16 AND transpose W (one launch) -------
#define CONV_BLOCKS ((MM * DD) / (256 * 4))
__global__ __launch_bounds__(256)
void prep_kernel(const float* __restrict__ x,
                 const float* __restrict__ Wz, const float* __restrict__ Wh)
{
    __shared__ float sm[32][33];
    if (blockIdx.x < CONV_BLOCKS) {
        const size_t i4 = (size_t)blockIdx.x * 256 + threadIdx.x;
        const float4 v = ((const float4*)x)[i4];
        __half2 p0, p1;
        p0.x = __float2half_rn(v.x); p0.y = __float2half_rn(v.y);
        p1.x = __float2half_rn(v.z); p1.y = __float2half_rn(v.w);
        ((__half2*)g_xh)[i4 * 2]     = p0;
        ((__half2*)g_xh)[i4 * 2 + 1] = p1;
    } else {
        const int bid = blockIdx.x - CONV_BLOCKS;   // 0..2047
        const int zz = bid >> 10;                   // 0: Wz, 1: Wh
        const int rem = bid & 1023;
        const int n0 = (rem & 31) * 32;
        const int k0 = (rem >> 5) * 32;
        const float* W = (zz == 0) ? Wz : Wh;
        __half* Wt = (zz == 0) ? g_Wtz : g_Wth;
        const int r = threadIdx.x >> 5;
        const int c = threadIdx.x & 31;
#pragma unroll
        for (int rr = 0; rr < 4; rr++) {
            const int row = rr * 8 + r;
            sm[row][c] = W[(size_t)(k0 + row) * DD + n0 + c];
        }
        __syncthreads();
#pragma unroll
        for (int rr = 0; rr < 4; rr++) {
            const int row = rr * 8 + r;
            Wt[(size_t)(n0 + row) * DD + k0 + c] = __float2half_rn(sm[c][row]);
        }
    }
}

// ---------------- PRIMARY GEMM: CTA 128x64, occ 2, 3-stage, 96KB smem --------
__global__ __launch_bounds__(256, 2)
void gemmN64_kernel(const float* __restrict__ bz, const float* __restrict__ bh)
{
    extern __shared__ char smem[];
    const uint32_t sbase = smem_u32(smem);
    const int tid  = threadIdx.x;
    const int wid  = tid >> 5;
    const int lane = tid & 31;
    const int wr = wid >> 1;           // 0..3: M 32-row strip
    const int wc = wid & 1;            // 0..1: N 32-col strip

    const int nBase = blockIdx.x * 64;
    const int mBase = blockIdx.y * 128;

    int ldRowA[4], ldColA[4];
    uint32_t ldOffA[4];
#pragma unroll
    for (int t = 0; t < 4; t++) {
        const int o = tid + t * 256;
        ldRowA[t] = o >> 3; ldColA[t] = o & 7;
        ldOffA[t] = SWZ128((uint32_t)(o * 16));
    }
    int ldRowB[2], ldColB[2];
    uint32_t ldOffB[2];
#pragma unroll
    for (int t = 0; t < 2; t++) {
        const int o = tid + t * 256;
        ldRowB[t] = o >> 3; ldColB[t] = o & 7;
        ldOffB[t] = SWZ128((uint32_t)(o * 16));
    }

    const int quad = lane >> 3;
    const int r8   = lane & 7;
    const int rowA = (quad & 1) * 8 + r8;
    const int kbA  = (quad >> 1) * 16;
    const int rowB = (quad >> 1) * 8 + r8;
    const int kbB  = (quad & 1) * 16;

    uint32_t offA[4][2], offB[4][2];
#pragma unroll
    for (int ks = 0; ks < 4; ks++) {
#pragma unroll
        for (int mt = 0; mt < 2; mt++)
            offA[ks][mt] = SWZ128((uint32_t)((wr * 32 + mt * 16 + rowA) * 128 + ks * 32 + kbA));
#pragma unroll
        for (int bt = 0; bt < 2; bt++)
            offB[ks][bt] = SWZ128((uint32_t)((wc * 32 + bt * 16 + rowB) * 128 + ks * 32 + kbB));
    }

    float accz[2][4][4], acch[2][4][4];
#pragma unroll
    for (int i = 0; i < 2; i++)
#pragma unroll
        for (int j = 0; j < 4; j++)
#pragma unroll
            for (int k = 0; k < 4; k++) { accz[i][j][k] = 0.0f; acch[i][j][k] = 0.0f; }

    auto load_chunk = [&](int chunk, int stage) {
        const int k0 = chunk * 64;
        const uint32_t st = sbase + stage * STAGEN;
#pragma unroll
        for (int t = 0; t < 4; t++)
            cp16(st + AN_OFF + ldOffA[t],
                 g_xh + (size_t)(mBase + ldRowA[t]) * DD + k0 + ldColA[t] * 8);
#pragma unroll
        for (int t = 0; t < 2; t++) {
            const size_t rowOff = (size_t)(nBase + ldRowB[t]) * DD + k0 + ldColB[t] * 8;
            cp16(st + BZN_OFF + ldOffB[t], g_Wtz + rowOff);
            cp16(st + BHN_OFF + ldOffB[t], g_Wth + rowOff);
        }
        cp_commit();
    };

    load_chunk(0, 0);
    load_chunk(1, 1);

    for (int i = 0; i < NCHN; i++) {
        const int s = i % 3;
        if (i < NCHN - 1) asm volatile("cp.async.wait_group 1;" ::: "memory");
        else              asm volatile("cp.async.wait_group 0;" ::: "memory");
        __syncthreads();
        if (i + 2 < NCHN) load_chunk(i + 2, (i + 2) % 3);

        const uint32_t st = sbase + s * STAGEN;
#pragma unroll
        for (int ks = 0; ks < 4; ks++) {
            uint32_t af[2][4];
#pragma unroll
            for (int mt = 0; mt < 2; mt++)
                ldsm_x4(af[mt][0], af[mt][1], af[mt][2], af[mt][3],
                        st + AN_OFF + offA[ks][mt]);
            {
                uint32_t bf[4][2];
#pragma unroll
                for (int bt = 0; bt < 2; bt++)
                    ldsm_x4(bf[bt*2][0], bf[bt*2][1], bf[bt*2+1][0], bf[bt*2+1][1],
                            st + BZN_OFF + offB[ks][bt]);
#pragma unroll
                for (int mt = 0; mt < 2; mt++)
#pragma unroll
                    for (int nt = 0; nt < 4; nt++)
                        mma_f16(accz[mt][nt], af[mt], bf[nt]);
            }
            {
                uint32_t bf[4][2];
#pragma unroll
                for (int bt = 0; bt < 2; bt++)
                    ldsm_x4(bf[bt*2][0], bf[bt*2][1], bf[bt*2+1][0], bf[bt*2+1][1],
                            st + BHN_OFF + offB[ks][bt]);
#pragma unroll
                for (int mt = 0; mt < 2; mt++)
#pragma unroll
                    for (int nt = 0; nt < 4; nt++)
                        mma_f16(acch[mt][nt], af[mt], bf[nt]);
            }
        }
    }

    // ---- epilogue: g_ab to gmem + stage {a,b} into smem [128][65] ----
    __syncthreads();
    __half2* s_ab = (__half2*)smem;
    {
        const int er = lane >> 2;
        const int q2 = (lane & 3) * 2;
#pragma unroll
        for (int mt = 0; mt < 2; mt++) {
#pragma unroll
            for (int nt = 0; nt < 4; nt++) {
                const int tl0 = wr * 32 + mt * 16 + er;
                const int col = wc * 32 + nt * 8 + q2;
                const int n = nBase + col;
                const size_t g0 = (size_t)(mBase + tl0) * DD + n;
                const size_t g1 = g0 + 8 * DD;
                const float2 bz2 = *(const float2*)(&bz[n]);
                const float2 bh2 = *(const float2*)(&bh[n]);
                float z;
                __half2 p0, p1;
                z = sigmoidf_fast(accz[mt][nt][0] + bz2.x);
                p0.x = __float2half_rn(1.0f - z);
                p0.y = __float2half_rn(z * (acch[mt][nt][0] + bh2.x));
                z = sigmoidf_fast(accz[mt][nt][1] + bz2.y);
                p1.x = __float2half_rn(1.0f - z);
                p1.y = __float2half_rn(z * (acch[mt][nt][1] + bh2.y));
                *(uint2*)(&g_ab[g0]) = make_uint2(h2_to_u32(p0), h2_to_u32(p1));
                s_ab[tl0 * 65 + col]     = p0;
                s_ab[tl0 * 65 + col + 1] = p1;
                z = sigmoidf_fast(accz[mt][nt][2] + bz2.x);
                p0.x = __float2half_rn(1.0f - z);
                p0.y = __float2half_rn(z * (acch[mt][nt][2] + bh2.x));
                z = sigmoidf_fast(accz[mt][nt][3] + bz2.y);
                p1.x = __float2half_rn(1.0f - z);
                p1.y = __float2half_rn(z * (acch[mt][nt][3] + bh2.y));
                *(uint2*)(&g_ab[g1]) = make_uint2(h2_to_u32(p0), h2_to_u32(p1));
                s_ab[(tl0 + 8) * 65 + col]     = p0;
                s_ab[(tl0 + 8) * 65 + col + 1] = p1;
            }
        }
    }
    __syncthreads();

    if (tid < 128) {
        const int ch = tid >> 6;          // 0..1
        const int cl = tid & 63;
        float A = 1.0f, Bv = 0.0f;
#pragma unroll 8
        for (int t = 0; t < CHLEN; t++) {
            const float2 f = __half22float2(s_ab[(ch * 64 + t) * 65 + cl]);
            Bv = fmaf(f.x, Bv, f.y);
            A *= f.x;
        }
        const int bc = (mBase >> 6) + ch;
        g_Ac[(size_t)bc * DD + nBase + cl] = A;
        g_Bc[(size_t)bc * DD + nBase + cl] = Bv;
    }
}

// ---------------- FALLBACK 1 GEMM: BK=64, CTA 128x128, 96KB smem -------------
__global__ __launch_bounds__(256, 1)
void gemm64_kernel(const float* __restrict__ bz, const float* __restrict__ bh)
{
    extern __shared__ char smem[];
    const uint32_t sbase = smem_u32(smem);
    const int tid  = threadIdx.x;
    const int wid  = tid >> 5;
    const int lane = tid & 31;
    const int wr = wid >> 2;
    const int wc = wid & 3;

    const int nBase = blockIdx.x * 128;
    const int mBase = blockIdx.y * 128;

    int ldRow[4];
    int ldCol[4];
    uint32_t ldOff[4];
#pragma unroll
    for (int t = 0; t < 4; t++) {
        const int o = tid + t * 256;
        ldRow[t] = o >> 3;
        ldCol[t] = o & 7;
        ldOff[t] = SWZ128((uint32_t)(o * 16));
    }

    const int quad = lane >> 3;
    const int r8   = lane & 7;
    const int rowA = (quad & 1) * 8 + r8;
    const int kbA  = (quad >> 1) * 16;
    const int rowB = (quad >> 1) * 8 + r8;
    const int kbB  = (quad & 1) * 16;

    uint32_t offA[4][4], offB[4][2];
#pragma unroll
    for (int ks = 0; ks < 4; ks++) {
#pragma unroll
        for (int mt = 0; mt < 4; mt++)
            offA[ks][mt] = SWZ128((uint32_t)((wr * 64 + mt * 16 + rowA) * 128 + ks * 32 + kbA));
#pragma unroll
        for (int bt = 0; bt < 2; bt++)
            offB[ks][bt] = SWZ128((uint32_t)((wc * 32 + bt * 16 + rowB) * 128 + ks * 32 + kbB));
    }

    float accz[4][4][4], acch[4][4][4];
#pragma unroll
    for (int i = 0; i < 4; i++)
#pragma unroll
        for (int j = 0; j < 4; j++)
#pragma unroll
            for (int k = 0; k < 4; k++) { accz[i][j][k] = 0.0f; acch[i][j][k] = 0.0f; }

    auto load_chunk = [&](int chunk, int stage) {
        const int k0 = chunk * 64;
        const uint32_t st = sbase + stage * STAGE64;
#pragma unroll
        for (int t = 0; t < 4; t++) {
            const size_t rowOff = (size_t)ldRow[t] * DD + k0 + ldCol[t] * 8;
            cp16(st + A64_OFF  + ldOff[t], g_xh  + (size_t)mBase * DD + rowOff);
            cp16(st + BZ64_OFF + ldOff[t], g_Wtz + (size_t)nBase * DD + rowOff);
            cp16(st + BH64_OFF + ldOff[t], g_Wth + (size_t)nBase * DD + rowOff);
        }
        cp_commit();
    };

    load_chunk(0, 0);

    for (int i = 0; i < NCH64; i++) {
        const int s = i & 1;
        asm volatile("cp.async.wait_group 0;" ::: "memory");
        __syncthreads();
        if (i + 1 < NCH64) load_chunk(i + 1, s ^ 1);

        const uint32_t st = sbase + s * STAGE64;
#pragma unroll
        for (int ks = 0; ks < 4; ks++) {
            uint32_t af[4][4];
#pragma unroll
            for (int mt = 0; mt < 4; mt++)
                ldsm_x4(af[mt][0], af[mt][1], af[mt][2], af[mt][3],
                        st + A64_OFF + offA[ks][mt]);
            {
                uint32_t bf[4][2];
#pragma unroll
                for (int bt = 0; bt < 2; bt++)
                    ldsm_x4(bf[bt*2][0], bf[bt*2][1], bf[bt*2+1][0], bf[bt*2+1][1],
                            st + BZ64_OFF + offB[ks][bt]);
#pragma unroll
                for (int mt = 0; mt < 4; mt++)
#pragma unroll
                    for (int nt = 0; nt < 4; nt++)
                        mma_f16(accz[mt][nt], af[mt], bf[nt]);
            }
            {
                uint32_t bf[4][2];
#pragma unroll
                for (int bt = 0; bt < 2; bt++)
                    ldsm_x4(bf[bt*2][0], bf[bt*2][1], bf[bt*2+1][0], bf[bt*2+1][1],
                            st + BH64_OFF + offB[ks][bt]);
#pragma unroll
                for (int mt = 0; mt < 4; mt++)
#pragma unroll
                    for (int nt = 0; nt < 4; nt++)
                        mma_f16(acch[mt][nt], af[mt], bf[nt]);
            }
        }
    }

    __syncthreads();
    __half2* s_ab = (__half2*)smem;
    {
        const int er = lane >> 2;
        const int q2 = (lane & 3) * 2;
#pragma unroll
        for (int mt = 0; mt < 4; mt++) {
#pragma unroll
            for (int nt = 0; nt < 4; nt++) {
                const int tl0 = wr * 64 + mt * 16 + er;
                const int col = wc * 32 + nt * 8 + q2;
                const int n = nBase + col;
                const size_t g0 = (size_t)(mBase + tl0) * DD + n;
                const size_t g1 = g0 + 8 * DD;
                const float2 bz2 = *(const float2*)(&bz[n]);
                const float2 bh2 = *(const float2*)(&bh[n]);
                float z;
                __half2 p0, p1;
                z = sigmoidf_fast(accz[mt][nt][0] + bz2.x);
                p0.x = __float2half_rn(1.0f - z);
                p0.y = __float2half_rn(z * (acch[mt][nt][0] + bh2.x));
                z = sigmoidf_fast(accz[mt][nt][1] + bz2.y);
                p1.x = __float2half_rn(1.0f - z);
                p1.y = __float2half_rn(z * (acch[mt][nt][1] + bh2.y));
                *(uint2*)(&g_ab[g0]) = make_uint2(h2_to_u32(p0), h2_to_u32(p1));
                s_ab[tl0 * 129 + col]     = p0;
                s_ab[tl0 * 129 + col + 1] = p1;
                z = sigmoidf_fast(accz[mt][nt][2] + bz2.x);
                p0.x = __float2half_rn(1.0f - z);
                p0.y = __float2half_rn(z * (acch[mt][nt][2] + bh2.x));
                z = sigmoidf_fast(accz[mt][nt][3] + bz2.y);
                p1.x = __float2half_rn(1.0f - z);
                p1.y = __float2half_rn(z * (acch[mt][nt][3] + bh2.y));
                *(uint2*)(&g_ab[g1]) = make_uint2(h2_to_u32(p0), h2_to_u32(p1));
                s_ab[(tl0 + 8) * 129 + col]     = p0;
                s_ab[(tl0 + 8) * 129 + col + 1] = p1;
            }
        }
    }
    __syncthreads();
    {
        const int ch = tid >> 7;
        const int cl = tid & 127;
        float A = 1.0f, Bv = 0.0f;
#pragma unroll 8
        for (int t = 0; t < CHLEN; t++) {
            const float2 f = __half22float2(s_ab[(ch * 64 + t) * 129 + cl]);
            Bv = fmaf(f.x, Bv, f.y);
            A *= f.x;
        }
        const int bc = (mBase >> 6) + ch;
        g_Ac[(size_t)bc * DD + nBase + cl] = A;
        g_Bc[(size_t)bc * DD + nBase + cl] = Bv;
    }
}

// ---------------- FALLBACK 2 GEMM: BK=32, 48KB; needs scan_pass1 -------------
__global__ __launch_bounds__(256, 1)
void gemm32_kernel(const float* __restrict__ bz, const float* __restrict__ bh)
{
    extern __shared__ char smem[];
    const uint32_t sbase = smem_u32(smem);
    const int tid  = threadIdx.x;
    const int wid  = tid >> 5;
    const int lane = tid & 31;
    const int wr = wid >> 2;
    const int wc = wid & 3;

    const int nBase = blockIdx.x * 128;
    const int mBase = blockIdx.y * 128;

    int ldRow[2];
    int ldCol[2];
    uint32_t ldOff[2];
#pragma unroll
    for (int t = 0; t < 2; t++) {
        const int o = tid + t * 256;
        ldRow[t] = o >> 2;
        ldCol[t] = o & 3;
        ldOff[t] = SWZ64((uint32_t)(o * 16));
    }

    const int quad = lane >> 3;
    const int r8   = lane & 7;
    const int rowA = (quad & 1) * 8 + r8;
    const int kbA  = (quad >> 1) * 16;
    const int rowB = (quad >> 1) * 8 + r8;
    const int kbB  = (quad & 1) * 16;

    uint32_t offA[2][4], offB[2][2];
#pragma unroll
    for (int ks = 0; ks < 2; ks++) {
#pragma unroll
        for (int mt = 0; mt < 4; mt++)
            offA[ks][mt] = SWZ64((uint32_t)((wr * 64 + mt * 16 + rowA) * 64 + ks * 32 + kbA));
#pragma unroll
        for (int bt = 0; bt < 2; bt++)
            offB[ks][bt] = SWZ64((uint32_t)((wc * 32 + bt * 16 + rowB) * 64 + ks * 32 + kbB));
    }

    float accz[4][4][4], acch[4][4][4];
#pragma unroll
    for (int i = 0; i < 4; i++)
#pragma unroll
        for (int j = 0; j < 4; j++)
#pragma unroll
            for (int k = 0; k < 4; k++) { accz[i][j][k] = 0.0f; acch[i][j][k] = 0.0f; }

    auto load_chunk = [&](int chunk, int stage) {
        const int k0 = chunk * 32;
        const uint32_t st = sbase + stage * STAGE32;
#pragma unroll
        for (int t = 0; t < 2; t++) {
            const size_t rowOff = (size_t)ldRow[t] * DD + k0 + ldCol[t] * 8;
            cp16(st + A32_OFF  + ldOff[t], g_xh  + (size_t)mBase * DD + rowOff);
            cp16(st + BZ32_OFF + ldOff[t], g_Wtz + (size_t)nBase * DD + rowOff);
            cp16(st + BH32_OFF + ldOff[t], g_Wth + (size_t)nBase * DD + rowOff);
        }
        cp_commit();
    };

    load_chunk(0, 0);

    for (int i = 0; i < NCH32; i++) {
        const int s = i & 1;
        asm volatile("cp.async.wait_group 0;" ::: "memory");
        __syncthreads();
        if (i + 1 < NCH32) load_chunk(i + 1, s ^ 1);

        const uint32_t st = sbase + s * STAGE32;
#pragma unroll
        for (int ks = 0; ks < 2; ks++) {
            uint32_t af[4][4];
#pragma unroll
            for (int mt = 0; mt < 4; mt++)
                ldsm_x4(af[mt][0], af[mt][1], af[mt][2], af[mt][3],
                        st + A32_OFF + offA[ks][mt]);
            {
                uint32_t bf[4][2];
#pragma unroll
                for (int bt = 0; bt < 2; bt++)
                    ldsm_x4(bf[bt*2][0], bf[bt*2][1], bf[bt*2+1][0], bf[bt*2+1][1],
                            st + BZ32_OFF + offB[ks][bt]);
#pragma unroll
                for (int mt = 0; mt < 4; mt++)
#pragma unroll
                    for (int nt = 0; nt < 4; nt++)
                        mma_f16(accz[mt][nt], af[mt], bf[nt]);
            }
            {
                uint32_t bf[4][2];
#pragma unroll
                for (int bt = 0; bt < 2; bt++)
                    ldsm_x4(bf[bt*2][0], bf[bt*2][1], bf[bt*2+1][0], bf[bt*2+1][1],
                            st + BH32_OFF + offB[ks][bt]);
#pragma unroll
                for (int mt = 0; mt < 4; mt++)
#pragma unroll
                    for (int nt = 0; nt < 4; nt++)
                        mma_f16(acch[mt][nt], af[mt], bf[nt]);
            }
        }
    }

    const int er = lane >> 2;
    const int ec = (lane & 3) * 2;
#pragma unroll
    for (int mt = 0; mt < 4; mt++) {
#pragma unroll
        for (int nt = 0; nt < 4; nt++) {
            const int m = mBase + wr * 64 + mt * 16 + er;
            const int n = nBase + wc * 32 + nt * 8 + ec;
            const size_t g0 = (size_t)m * DD + n;
            const size_t g1 = g0 + 8 * DD;
            const float2 bz2 = *(const float2*)(&bz[n]);
            const float2 bh2 = *(const float2*)(&bh[n]);
            float z;
            __half2 p0, p1;
            z = sigmoidf_fast(accz[mt][nt][0] + bz2.x);
            p0.x = __float2half_rn(1.0f - z);
            p0.y = __float2half_rn(z * (acch[mt][nt][0] + bh2.x));
            z = sigmoidf_fast(accz[mt][nt][1] + bz2.y);
            p1.x = __float2half_rn(1.0f - z);
            p1.y = __float2half_rn(z * (acch[mt][nt][1] + bh2.y));
            *(uint2*)(&g_ab[g0]) = make_uint2(h2_to_u32(p0), h2_to_u32(p1));
            z = sigmoidf_fast(accz[mt][nt][2] + bz2.x);
            p0.x = __float2half_rn(1.0f - z);
            p0.y = __float2half_rn(z * (acch[mt][nt][2] + bh2.x));
            z = sigmoidf_fast(accz[mt][nt][3] + bz2.y);
            p1.x = __float2half_rn(1.0f - z);
            p1.y = __float2half_rn(z * (acch[mt][nt][3] + bh2.y));
            *(uint2*)(&g_ab[g1]) = make_uint2(h2_to_u32(p0), h2_to_u32(p1));
        }
    }
}

// ---------------- scan pass 1 (fallback path only) ----------------
__global__ __launch_bounds__(256)
void scan_pass1()
{
    const int g2 = blockIdx.x * 256 + threadIdx.x;
    const int bc = g2 >> 9;
    const int d0 = (g2 & 511) * 2;
    const size_t base = (size_t)bc * CHLEN * DD + d0;

    float2 Ar = make_float2(1.f, 1.f);
    float2 Br = make_float2(0.f, 0.f);
#pragma unroll 16
    for (int t = 0; t < CHLEN; t++) {
        const uint2 raw = *(const uint2*)&g_ab[base + (size_t)t * DD];
        const float2 ab0 = __half22float2(u32_to_h2(raw.x));
        const float2 ab1 = __half22float2(u32_to_h2(raw.y));
        Br.x = fmaf(ab0.x, Br.x, ab0.y); Ar.x *= ab0.x;
        Br.y = fmaf(ab1.x, Br.y, ab1.y); Ar.y *= ab1.x;
    }
    *(float2*)&g_Ac[(size_t)bc * DD + d0] = Ar;
    *(float2*)&g_Bc[(size_t)bc * DD + d0] = Br;
}

// ---------------- scan + swish: software-pipelined (depth-4 prefetch) --------
__global__ __launch_bounds__(256)
void scan_swish_kernel(const float* __restrict__ swish_beta)
{
    const int g2 = blockIdx.x * 256 + threadIdx.x;
    const int bc = g2 >> 9;
    const int d0 = (g2 & 511) * 2;
    const int b = bc >> 5;
    const int chunk = bc & 31;
    const float beta = __ldg(swish_beta);

    float2 h = make_float2(0.f, 0.f);
#pragma unroll 4
    for (int c = 0; c < chunk; c++) {
        const size_t idx = (size_t)(b * NCHUNK + c) * DD + d0;
        const float2 A = *(const float2*)&g_Ac[idx];
        const float2 B = *(const float2*)&g_Bc[idx];
        h.x = fmaf(A.x, h.x, B.x);
        h.y = fmaf(A.y, h.y, B.y);
    }

    const size_t base = (size_t)bc * CHLEN * DD + d0;

    uint2 buf[4];
#pragma unroll
    for (int j = 0; j < 4; j++)
        buf[j] = *(const uint2*)&g_ab[base + (size_t)j * DD];

    for (int t0 = 0; t0 < CHLEN; t0 += 4) {
        uint2 nxt[4];
        if (t0 + 4 < CHLEN) {
#pragma unroll
            for (int j = 0; j < 4; j++)
                nxt[j] = *(const uint2*)&g_ab[base + (size_t)(t0 + 4 + j) * DD];
        }
#pragma unroll
        for (int j = 0; j < 4; j++) {
            const float2 ab0 = __half22float2(u32_to_h2(buf[j].x));
            const float2 ab1 = __half22float2(u32_to_h2(buf[j].y));
            h.x = fmaf(ab0.x, h.x, ab0.y);
            h.y = fmaf(ab1.x, h.y, ab1.y);
            float s;
            __half2 y2;
            s = beta * h.x; y2.x = __float2half_rn(s * sigmoidf_fast(s));
            s = beta * h.y; y2.y = __float2half_rn(s * sigmoidf_fast(s));
            *(__half2*)&g_y16[base + (size_t)(t0 + j) * DD] = y2;
        }
#pragma unroll
        for (int j = 0; j < 4; j++) buf[j] = nxt[j];
    }
}

// ---------------- LayerNorm: one WARP per row, no barriers ----------------
// lane owns 32 d-values in 4 coalesced 16B segments (d = seg*256 + lane*8).
__global__ __launch_bounds__(256)
void ln_kernel(const float* __restrict__ gamma,
               const float* __restrict__ lbeta,
               float* __restrict__ out)
{
    const int row  = blockIdx.x * 8 + (threadIdx.x >> 5);
    const int lane = threadIdx.x & 31;
    const size_t rbase = (size_t)row * DD;

    uint4 yv[4];
    float s1 = 0.0f, s2 = 0.0f;
#pragma unroll
    for (int seg = 0; seg < 4; seg++) {
        yv[seg] = *(const uint4*)&g_y16[rbase + seg * 256 + lane * 8];
        const float2 a = __half22float2(u32_to_h2(yv[seg].x));
        const float2 b = __half22float2(u32_to_h2(yv[seg].y));
        const float2 c = __half22float2(u32_to_h2(yv[seg].z));
        const float2 d = __half22float2(u32_to_h2(yv[seg].w));
        s1 += a.x + a.y + b.x + b.y + c.x + c.y + d.x + d.y;
        s2 += a.x * a.x + a.y * a.y + b.x * b.x + b.y * b.y
            + c.x * c.x + c.y * c.y + d.x * d.x + d.y * d.y;
    }
#pragma unroll
    for (int o = 16; o > 0; o >>= 1) {
        s1 += __shfl_xor_sync(0xffffffffu, s1, o);
        s2 += __shfl_xor_sync(0xffffffffu, s2, o);
    }
    const float mu  = s1 * (1.0f / DD);
    const float var = s2 * (1.0f / DD) - mu * mu;
    const float inv = rsqrtf(var + 1e-5f);

#pragma unroll
    for (int seg = 0; seg < 4; seg++) {
        const int d0 = seg * 256 + lane * 8;
        const float4 gm0 = *(const float4*)&gamma[d0];
        const float4 gm1 = *(const float4*)&gamma[d0 + 4];
        const float4 bt0 = *(const float4*)&lbeta[d0];
        const float4 bt1 = *(const float4*)&lbeta[d0 + 4];
        const float2 a = __half22float2(u32_to_h2(yv[seg].x));
        const float2 b = __half22float2(u32_to_h2(yv[seg].y));
        const float2 c = __half22float2(u32_to_h2(yv[seg].z));
        const float2 d = __half22float2(u32_to_h2(yv[seg].w));
        float4 o0, o1;
        o0.x = (a.x - mu) * inv * gm0.x + bt0.x;
        o0.y = (a.y - mu) * inv * gm0.y + bt0.y;
        o0.z = (b.x - mu) * inv * gm0.z + bt0.z;
        o0.w = (b.y - mu) * inv * gm0.w + bt0.w;
        o1.x = (c.x - mu) * inv * gm1.x + bt1.x;
        o1.y = (c.y - mu) * inv * gm1.y + bt1.y;
        o1.z = (d.x - mu) * inv * gm1.z + bt1.z;
        o1.w = (d.y - mu) * inv * gm1.w + bt1.w;
        *(float4*)&out[rbase + d0]     = o0;
        *(float4*)&out[rbase + d0 + 4] = o1;
    }
}

// ---------------- launch ----------------
extern "C" void kernel_launch(void* const* d_in, const int* in_sizes, int n_in,
                              void* d_out, int out_size)
{
    const float* x     = (const float*)d_in[0];
    const float* Wz    = (const float*)d_in[1];
    const float* bz    = (const float*)d_in[2];
    const float* Wh    = (const float*)d_in[3];
    const float* bh    = (const float*)d_in[4];
    const float* sbeta = (const float*)d_in[5];
    const float* gamma = (const float*)d_in[6];
    const float* lbeta = (const float*)d_in[7];
    float* out = (float*)d_out;

    prep_kernel<<<CONV_BLOCKS + 2048, 256>>>(x, Wz, Wh);

    cudaError_t e1 = cudaFuncSetAttribute(
        gemmN64_kernel, cudaFuncAttributeMaxDynamicSharedMemorySize, 3 * STAGEN);
    if (e1 == cudaSuccess) {
        dim3 grid(DD / 64, MM / 128);    // (16, 128)
        gemmN64_kernel<<<grid, 256, 3 * STAGEN>>>(bz, bh);
    } else {
        (void)cudaGetLastError();
        cudaError_t e2 = cudaFuncSetAttribute(
            gemm64_kernel, cudaFuncAttributeMaxDynamicSharedMemorySize, 2 * STAGE64);
        dim3 grid(DD / 128, MM / 128);   // (8, 128)
        if (e2 == cudaSuccess) {
            gemm64_kernel<<<grid, 256, 2 * STAGE64>>>(bz, bh);
        } else {
            (void)cudaGetLastError();
            gemm32_kernel<<<grid, 256, 2 * STAGE32>>>(bz, bh);
            scan_pass1<<<(BB * NCHUNK * DD) / (256 * 2), 256>>>();
        }
    }

    scan_swish_kernel<<<(BB * NCHUNK * DD) / (256 * 2), 256>>>(sbeta);
    ln_kernel<<<MM / 8, 256>>>(gamma, lbeta, out);
}

// round 17
// speedup vs baseline: 1.2852x; 1.0144x over previous
#include <cuda_runtime.h>
#include <cuda_fp16.h>
#include <math.h>
#include <stdint.h>

// Problem shape (fixed): B=8, T=2048, D=1024
#define BB   8
#define TT   2048
#define DD   1024
#define MM   (BB*TT)          // 16384 rows
#define NCHUNK 32
#define CHLEN  64

// ---- N64 GEMM (primary): CTA 128(M)x64(N), 2 outputs, warp 32x32, occ 2 ----
#define NCHN   16             // K chunks of 64
#define AN_OFF  0
#define BZN_OFF 16384
#define BHN_OFF 24576
#define STAGEN  32768          // 32KB per stage; 3 stages = 96KB (occ 2)

// ---- BK=64 GEMM (fallback 1): CTA 128x128, 96KB ----
#define NCH64   16
#define A64_OFF  0
#define BZ64_OFF 16384
#define BH64_OFF 32768
#define STAGE64  49152

// ---- BK=32 GEMM (fallback 2, 48KB default smem) ----
#define NCH32   32
#define A32_OFF  0
#define BZ32_OFF 8192
#define BH32_OFF 16384
#define STAGE32  24576

// ---------------- scratch (device globals) ----------------
__device__ __half2 g_ab[(size_t)MM * DD];   // {a, b} per element (fp16)
__device__ __half  g_y16[(size_t)MM * DD];  // swish output (fp16)
__device__ float   g_Ac[BB * NCHUNK * DD];  // chunk summaries (fp32)
__device__ float   g_Bc[BB * NCHUNK * DD];

__device__ __half g_xh[(size_t)MM * DD];    // x in fp16
__device__ __half g_Wtz[DD * DD];           // Wz^T fp16: [n][k]
__device__ __half g_Wth[DD * DD];           // Wh^T fp16: [n][k]

__device__ __forceinline__ float sigmoidf_fast(float v) {
    return 1.0f / (1.0f + __expf(-v));
}

// ---- bit casts ----
__device__ __forceinline__ uint32_t h2_to_u32(__half2 h) {
    return *reinterpret_cast<uint32_t*>(&h);
}
__device__ __forceinline__ __half2 u32_to_h2(uint32_t u) {
    return *reinterpret_cast<__half2*>(&u);
}

// ---------------- PTX helpers ----------------
__device__ __forceinline__ uint32_t smem_u32(const void* p) {
    uint32_t a;
    asm("{ .reg .u64 t; cvta.to.shared.u64 t, %1; cvt.u32.u64 %0, t; }" : "=r"(a) : "l"(p));
    return a;
}
#define SWZ64(o)  ((o) ^ (((o) >> 3) & 0x30))
#define SWZ128(o) ((o) ^ (((o) >> 3) & 0x70))

__device__ __forceinline__ void cp16(uint32_t s, const void* g) {
    asm volatile("cp.async.cg.shared.global [%0], [%1], 16;" :: "r"(s), "l"(g));
}
__device__ __forceinline__ void cp_commit() {
    asm volatile("cp.async.commit_group;" ::: "memory");
}
__device__ __forceinline__ void ldsm_x4(uint32_t& r0, uint32_t& r1, uint32_t& r2,
                                        uint32_t& r3, uint32_t addr) {
    asm volatile("ldmatrix.sync.aligned.m8n8.x4.shared.b16 {%0,%1,%2,%3}, [%4];"
                 : "=r"(r0), "=r"(r1), "=r"(r2), "=r"(r3) : "r"(addr));
}
__device__ __forceinline__ void mma_f16(float* d, const uint32_t* a, const uint32_t* b) {
    asm volatile(
        "mma.sync.aligned.m16n8k16.row.col.f32.f16.f16.f32 "
        "{%0,%1,%2,%3},{%4,%5,%6,%7},{%8,%9},{%0,%1,%2,%3};"
        : "+f"(d[0]), "+f"(d[1]), "+f"(d[2]), "+f"(d[3])
        : "r"(a[0]), "r"(a[1]), "r"(a[2]), "r"(a[3]), "r"(b[0]), "r"(b[1]));
}

// ---------------- prep: convert x to fp16 AND transpose W (one launch) -------
#define CONV_BLOCKS ((MM * DD) / (256 * 4))
__global__ __launch_bounds__(256)
void prep_kernel(const float* __restrict__ x,
                 const float* __restrict__ Wz, const float* __restrict__ Wh)
{
    __shared__ float sm[32][33];
    if (blockIdx.x < CONV_BLOCKS) {
        const size_t i4 = (size_t)blockIdx.x * 256 + threadIdx.x;
        const float4 v = ((const float4*)x)[i4];
        __half2 p0, p1;
        p0.x = __float2half_rn(v.x); p0.y = __float2half_rn(v.y);
        p1.x = __float2half_rn(v.z); p1.y = __float2half_rn(v.w);
        ((__half2*)g_xh)[i4 * 2]     = p0;
        ((__half2*)g_xh)[i4 * 2 + 1] = p1;
    } else {
        const int bid = blockIdx.x - CONV_BLOCKS;   // 0..2047
        const int zz = bid >> 10;                   // 0: Wz, 1: Wh
        const int rem = bid & 1023;
        const int n0 = (rem & 31) * 32;
        const int k0 = (rem >> 5) * 32;
        const float* W = (zz == 0) ? Wz : Wh;
        __half* Wt = (zz == 0) ? g_Wtz : g_Wth;
        const int r = threadIdx.x >> 5;
        const int c = threadIdx.x & 31;
#pragma unroll
        for (int rr = 0; rr < 4; rr++) {
            const int row = rr * 8 + r;
            sm[row][c] = W[(size_t)(k0 + row) * DD + n0 + c];
        }
        __syncthreads();
#pragma unroll
        for (int rr = 0; rr < 4; rr++) {
            const int row = rr * 8 + r;
            Wt[(size_t)(n0 + row) * DD + k0 + c] = __float2half_rn(sm[c][row]);
        }
    }
}

// ---------------- PRIMARY GEMM: CTA 128x64, occ 2, 3-stage, 96KB smem --------
__global__ __launch_bounds__(256, 2)
void gemmN64_kernel(const float* __restrict__ bz, const float* __restrict__ bh)
{
    extern __shared__ char smem[];
    const uint32_t sbase = smem_u32(smem);
    const int tid  = threadIdx.x;
    const int wid  = tid >> 5;
    const int lane = tid & 31;
    const int wr = wid >> 1;           // 0..3: M 32-row strip
    const int wc = wid & 1;            // 0..1: N 32-col strip

    const int nBase = blockIdx.x * 64;
    const int mBase = blockIdx.y * 128;

    int ldRowA[4], ldColA[4];
    uint32_t ldOffA[4];
#pragma unroll
    for (int t = 0; t < 4; t++) {
        const int o = tid + t * 256;
        ldRowA[t] = o >> 3; ldColA[t] = o & 7;
        ldOffA[t] = SWZ128((uint32_t)(o * 16));
    }
    int ldRowB[2], ldColB[2];
    uint32_t ldOffB[2];
#pragma unroll
    for (int t = 0; t < 2; t++) {
        const int o = tid + t * 256;
        ldRowB[t] = o >> 3; ldColB[t] = o & 7;
        ldOffB[t] = SWZ128((uint32_t)(o * 16));
    }

    const int quad = lane >> 3;
    const int r8   = lane & 7;
    const int rowA = (quad & 1) * 8 + r8;
    const int kbA  = (quad >> 1) * 16;
    const int rowB = (quad >> 1) * 8 + r8;
    const int kbB  = (quad & 1) * 16;

    uint32_t offA[4][2], offB[4][2];
#pragma unroll
    for (int ks = 0; ks < 4; ks++) {
#pragma unroll
        for (int mt = 0; mt < 2; mt++)
            offA[ks][mt] = SWZ128((uint32_t)((wr * 32 + mt * 16 + rowA) * 128 + ks * 32 + kbA));
#pragma unroll
        for (int bt = 0; bt < 2; bt++)
            offB[ks][bt] = SWZ128((uint32_t)((wc * 32 + bt * 16 + rowB) * 128 + ks * 32 + kbB));
    }

    float accz[2][4][4], acch[2][4][4];
#pragma unroll
    for (int i = 0; i < 2; i++)
#pragma unroll
        for (int j = 0; j < 4; j++)
#pragma unroll
            for (int k = 0; k < 4; k++) { accz[i][j][k] = 0.0f; acch[i][j][k] = 0.0f; }

    auto load_chunk = [&](int chunk, int stage) {
        const int k0 = chunk * 64;
        const uint32_t st = sbase + stage * STAGEN;
#pragma unroll
        for (int t = 0; t < 4; t++)
            cp16(st + AN_OFF + ldOffA[t],
                 g_xh + (size_t)(mBase + ldRowA[t]) * DD + k0 + ldColA[t] * 8);
#pragma unroll
        for (int t = 0; t < 2; t++) {
            const size_t rowOff = (size_t)(nBase + ldRowB[t]) * DD + k0 + ldColB[t] * 8;
            cp16(st + BZN_OFF + ldOffB[t], g_Wtz + rowOff);
            cp16(st + BHN_OFF + ldOffB[t], g_Wth + rowOff);
        }
        cp_commit();
    };

    load_chunk(0, 0);
    load_chunk(1, 1);

    for (int i = 0; i < NCHN; i++) {
        const int s = i % 3;
        if (i < NCHN - 1) asm volatile("cp.async.wait_group 1;" ::: "memory");
        else              asm volatile("cp.async.wait_group 0;" ::: "memory");
        __syncthreads();
        if (i + 2 < NCHN) load_chunk(i + 2, (i + 2) % 3);

        const uint32_t st = sbase + s * STAGEN;
#pragma unroll
        for (int ks = 0; ks < 4; ks++) {
            uint32_t af[2][4];
#pragma unroll
            for (int mt = 0; mt < 2; mt++)
                ldsm_x4(af[mt][0], af[mt][1], af[mt][2], af[mt][3],
                        st + AN_OFF + offA[ks][mt]);
            {
                uint32_t bf[4][2];
#pragma unroll
                for (int bt = 0; bt < 2; bt++)
                    ldsm_x4(bf[bt*2][0], bf[bt*2][1], bf[bt*2+1][0], bf[bt*2+1][1],
                            st + BZN_OFF + offB[ks][bt]);
#pragma unroll
                for (int mt = 0; mt < 2; mt++)
#pragma unroll
                    for (int nt = 0; nt < 4; nt++)
                        mma_f16(accz[mt][nt], af[mt], bf[nt]);
            }
            {
                uint32_t bf[4][2];
#pragma unroll
                for (int bt = 0; bt < 2; bt++)
                    ldsm_x4(bf[bt*2][0], bf[bt*2][1], bf[bt*2+1][0], bf[bt*2+1][1],
                            st + BHN_OFF + offB[ks][bt]);
#pragma unroll
                for (int mt = 0; mt < 2; mt++)
#pragma unroll
                    for (int nt = 0; nt < 4; nt++)
                        mma_f16(acch[mt][nt], af[mt], bf[nt]);
            }
        }
    }

    // ---- epilogue: g_ab to gmem + stage {a,b} into smem [128][65] ----
    __syncthreads();
    __half2* s_ab = (__half2*)smem;
    {
        const int er = lane >> 2;
        const int q2 = (lane & 3) * 2;
#pragma unroll
        for (int mt = 0; mt < 2; mt++) {
#pragma unroll
            for (int nt = 0; nt < 4; nt++) {
                const int tl0 = wr * 32 + mt * 16 + er;
                const int col = wc * 32 + nt * 8 + q2;
                const int n = nBase + col;
                const size_t g0 = (size_t)(mBase + tl0) * DD + n;
                const size_t g1 = g0 + 8 * DD;
                const float2 bz2 = *(const float2*)(&bz[n]);
                const float2 bh2 = *(const float2*)(&bh[n]);
                float z;
                __half2 p0, p1;
                z = sigmoidf_fast(accz[mt][nt][0] + bz2.x);
                p0.x = __float2half_rn(1.0f - z);
                p0.y = __float2half_rn(z * (acch[mt][nt][0] + bh2.x));
                z = sigmoidf_fast(accz[mt][nt][1] + bz2.y);
                p1.x = __float2half_rn(1.0f - z);
                p1.y = __float2half_rn(z * (acch[mt][nt][1] + bh2.y));
                *(uint2*)(&g_ab[g0]) = make_uint2(h2_to_u32(p0), h2_to_u32(p1));
                s_ab[tl0 * 65 + col]     = p0;
                s_ab[tl0 * 65 + col + 1] = p1;
                z = sigmoidf_fast(accz[mt][nt][2] + bz2.x);
                p0.x = __float2half_rn(1.0f - z);
                p0.y = __float2half_rn(z * (acch[mt][nt][2] + bh2.x));
                z = sigmoidf_fast(accz[mt][nt][3] + bz2.y);
                p1.x = __float2half_rn(1.0f - z);
                p1.y = __float2half_rn(z * (acch[mt][nt][3] + bh2.y));
                *(uint2*)(&g_ab[g1]) = make_uint2(h2_to_u32(p0), h2_to_u32(p1));
                s_ab[(tl0 + 8) * 65 + col]     = p0;
                s_ab[(tl0 + 8) * 65 + col + 1] = p1;
            }
        }
    }
    __syncthreads();

    if (tid < 128) {
        const int ch = tid >> 6;          // 0..1
        const int cl = tid & 63;
        float A = 1.0f, Bv = 0.0f;
#pragma unroll 8
        for (int t = 0; t < CHLEN; t++) {
            const float2 f = __half22float2(s_ab[(ch * 64 + t) * 65 + cl]);
            Bv = fmaf(f.x, Bv, f.y);
            A *= f.x;
        }
        const int bc = (mBase >> 6) + ch;
        g_Ac[(size_t)bc * DD + nBase + cl] = A;
        g_Bc[(size_t)bc * DD + nBase + cl] = Bv;
    }
}

// ---------------- FALLBACK 1 GEMM: BK=64, CTA 128x128, 96KB smem -------------
__global__ __launch_bounds__(256, 1)
void gemm64_kernel(const float* __restrict__ bz, const float* __restrict__ bh)
{
    extern __shared__ char smem[];
    const uint32_t sbase = smem_u32(smem);
    const int tid  = threadIdx.x;
    const int wid  = tid >> 5;
    const int lane = tid & 31;
    const int wr = wid >> 2;
    const int wc = wid & 3;

    const int nBase = blockIdx.x * 128;
    const int mBase = blockIdx.y * 128;

    int ldRow[4];
    int ldCol[4];
    uint32_t ldOff[4];
#pragma unroll
    for (int t = 0; t < 4; t++) {
        const int o = tid + t * 256;
        ldRow[t] = o >> 3;
        ldCol[t] = o & 7;
        ldOff[t] = SWZ128((uint32_t)(o * 16));
    }

    const int quad = lane >> 3;
    const int r8   = lane & 7;
    const int rowA = (quad & 1) * 8 + r8;
    const int kbA  = (quad >> 1) * 16;
    const int rowB = (quad >> 1) * 8 + r8;
    const int kbB  = (quad & 1) * 16;

    uint32_t offA[4][4], offB[4][2];
#pragma unroll
    for (int ks = 0; ks < 4; ks++) {
#pragma unroll
        for (int mt = 0; mt < 4; mt++)
            offA[ks][mt] = SWZ128((uint32_t)((wr * 64 + mt * 16 + rowA) * 128 + ks * 32 + kbA));
#pragma unroll
        for (int bt = 0; bt < 2; bt++)
            offB[ks][bt] = SWZ128((uint32_t)((wc * 32 + bt * 16 + rowB) * 128 + ks * 32 + kbB));
    }

    float accz[4][4][4], acch[4][4][4];
#pragma unroll
    for (int i = 0; i < 4; i++)
#pragma unroll
        for (int j = 0; j < 4; j++)
#pragma unroll
            for (int k = 0; k < 4; k++) { accz[i][j][k] = 0.0f; acch[i][j][k] = 0.0f; }

    auto load_chunk = [&](int chunk, int stage) {
        const int k0 = chunk * 64;
        const uint32_t st = sbase + stage * STAGE64;
#pragma unroll
        for (int t = 0; t < 4; t++) {
            const size_t rowOff = (size_t)ldRow[t] * DD + k0 + ldCol[t] * 8;
            cp16(st + A64_OFF  + ldOff[t], g_xh  + (size_t)mBase * DD + rowOff);
            cp16(st + BZ64_OFF + ldOff[t], g_Wtz + (size_t)nBase * DD + rowOff);
            cp16(st + BH64_OFF + ldOff[t], g_Wth + (size_t)nBase * DD + rowOff);
        }
        cp_commit();
    };

    load_chunk(0, 0);

    for (int i = 0; i < NCH64; i++) {
        const int s = i & 1;
        asm volatile("cp.async.wait_group 0;" ::: "memory");
        __syncthreads();
        if (i + 1 < NCH64) load_chunk(i + 1, s ^ 1);

        const uint32_t st = sbase + s * STAGE64;
#pragma unroll
        for (int ks = 0; ks < 4; ks++) {
            uint32_t af[4][4];
#pragma unroll
            for (int mt = 0; mt < 4; mt++)
                ldsm_x4(af[mt][0], af[mt][1], af[mt][2], af[mt][3],
                        st + A64_OFF + offA[ks][mt]);
            {
                uint32_t bf[4][2];
#pragma unroll
                for (int bt = 0; bt < 2; bt++)
                    ldsm_x4(bf[bt*2][0], bf[bt*2][1], bf[bt*2+1][0], bf[bt*2+1][1],
                            st + BZ64_OFF + offB[ks][bt]);
#pragma unroll
                for (int mt = 0; mt < 4; mt++)
#pragma unroll
                    for (int nt = 0; nt < 4; nt++)
                        mma_f16(accz[mt][nt], af[mt], bf[nt]);
            }
            {
                uint32_t bf[4][2];
#pragma unroll
                for (int bt = 0; bt < 2; bt++)
                    ldsm_x4(bf[bt*2][0], bf[bt*2][1], bf[bt*2+1][0], bf[bt*2+1][1],
                            st + BH64_OFF + offB[ks][bt]);
#pragma unroll
                for (int mt = 0; mt < 4; mt++)
#pragma unroll
                    for (int nt = 0; nt < 4; nt++)
                        mma_f16(acch[mt][nt], af[mt], bf[nt]);
            }
        }
    }

    __syncthreads();
    __half2* s_ab = (__half2*)smem;
    {
        const int er = lane >> 2;
        const int q2 = (lane & 3) * 2;
#pragma unroll
        for (int mt = 0; mt < 4; mt++) {
#pragma unroll
            for (int nt = 0; nt < 4; nt++) {
                const int tl0 = wr * 64 + mt * 16 + er;
                const int col = wc * 32 + nt * 8 + q2;
                const int n = nBase + col;
                const size_t g0 = (size_t)(mBase + tl0) * DD + n;
                const size_t g1 = g0 + 8 * DD;
                const float2 bz2 = *(const float2*)(&bz[n]);
                const float2 bh2 = *(const float2*)(&bh[n]);
                float z;
                __half2 p0, p1;
                z = sigmoidf_fast(accz[mt][nt][0] + bz2.x);
                p0.x = __float2half_rn(1.0f - z);
                p0.y = __float2half_rn(z * (acch[mt][nt][0] + bh2.x));
                z = sigmoidf_fast(accz[mt][nt][1] + bz2.y);
                p1.x = __float2half_rn(1.0f - z);
                p1.y = __float2half_rn(z * (acch[mt][nt][1] + bh2.y));
                *(uint2*)(&g_ab[g0]) = make_uint2(h2_to_u32(p0), h2_to_u32(p1));
                s_ab[tl0 * 129 + col]     = p0;
                s_ab[tl0 * 129 + col + 1] = p1;
                z = sigmoidf_fast(accz[mt][nt][2] + bz2.x);
                p0.x = __float2half_rn(1.0f - z);
                p0.y = __float2half_rn(z * (acch[mt][nt][2] + bh2.x));
                z = sigmoidf_fast(accz[mt][nt][3] + bz2.y);
                p1.x = __float2half_rn(1.0f - z);
                p1.y = __float2half_rn(z * (acch[mt][nt][3] + bh2.y));
                *(uint2*)(&g_ab[g1]) = make_uint2(h2_to_u32(p0), h2_to_u32(p1));
                s_ab[(tl0 + 8) * 129 + col]     = p0;
                s_ab[(tl0 + 8) * 129 + col + 1] = p1;
            }
        }
    }
    __syncthreads();
    {
        const int ch = tid >> 7;
        const int cl = tid & 127;
        float A = 1.0f, Bv = 0.0f;
#pragma unroll 8
        for (int t = 0; t < CHLEN; t++) {
            const float2 f = __half22float2(s_ab[(ch * 64 + t) * 129 + cl]);
            Bv = fmaf(f.x, Bv, f.y);
            A *= f.x;
        }
        const int bc = (mBase >> 6) + ch;
        g_Ac[(size_t)bc * DD + nBase + cl] = A;
        g_Bc[(size_t)bc * DD + nBase + cl] = Bv;
    }
}

// ---------------- FALLBACK 2 GEMM: BK=32, 48KB; needs scan_pass1 -------------
__global__ __launch_bounds__(256, 1)
void gemm32_kernel(const float* __restrict__ bz, const float* __restrict__ bh)
{
    extern __shared__ char smem[];
    const uint32_t sbase = smem_u32(smem);
    const int tid  = threadIdx.x;
    const int wid  = tid >> 5;
    const int lane = tid & 31;
    const int wr = wid >> 2;
    const int wc = wid & 3;

    const int nBase = blockIdx.x * 128;
    const int mBase = blockIdx.y * 128;

    int ldRow[2];
    int ldCol[2];
    uint32_t ldOff[2];
#pragma unroll
    for (int t = 0; t < 2; t++) {
        const int o = tid + t * 256;
        ldRow[t] = o >> 2;
        ldCol[t] = o & 3;
        ldOff[t] = SWZ64((uint32_t)(o * 16));
    }

    const int quad = lane >> 3;
    const int r8   = lane & 7;
    const int rowA = (quad & 1) * 8 + r8;
    const int kbA  = (quad >> 1) * 16;
    const int rowB = (quad >> 1) * 8 + r8;
    const int kbB  = (quad & 1) * 16;

    uint32_t offA[2][4], offB[2][2];
#pragma unroll
    for (int ks = 0; ks < 2; ks++) {
#pragma unroll
        for (int mt = 0; mt < 4; mt++)
            offA[ks][mt] = SWZ64((uint32_t)((wr * 64 + mt * 16 + rowA) * 64 + ks * 32 + kbA));
#pragma unroll
        for (int bt = 0; bt < 2; bt++)
            offB[ks][bt] = SWZ64((uint32_t)((wc * 32 + bt * 16 + rowB) * 64 + ks * 32 + kbB));
    }

    float accz[4][4][4], acch[4][4][4];
#pragma unroll
    for (int i = 0; i < 4; i++)
#pragma unroll
        for (int j = 0; j < 4; j++)
#pragma unroll
            for (int k = 0; k < 4; k++) { accz[i][j][k] = 0.0f; acch[i][j][k] = 0.0f; }

    auto load_chunk = [&](int chunk, int stage) {
        const int k0 = chunk * 32;
        const uint32_t st = sbase + stage * STAGE32;
#pragma unroll
        for (int t = 0; t < 2; t++) {
            const size_t rowOff = (size_t)ldRow[t] * DD + k0 + ldCol[t] * 8;
            cp16(st + A32_OFF  + ldOff[t], g_xh  + (size_t)mBase * DD + rowOff);
            cp16(st + BZ32_OFF + ldOff[t], g_Wtz + (size_t)nBase * DD + rowOff);
            cp16(st + BH32_OFF + ldOff[t], g_Wth + (size_t)nBase * DD + rowOff);
        }
        cp_commit();
    };

    load_chunk(0, 0);

    for (int i = 0; i < NCH32; i++) {
        const int s = i & 1;
        asm volatile("cp.async.wait_group 0;" ::: "memory");
        __syncthreads();
        if (i + 1 < NCH32) load_chunk(i + 1, s ^ 1);

        const uint32_t st = sbase + s * STAGE32;
#pragma unroll
        for (int ks = 0; ks < 2; ks++) {
            uint32_t af[4][4];
#pragma unroll
            for (int mt = 0; mt < 4; mt++)
                ldsm_x4(af[mt][0], af[mt][1], af[mt][2], af[mt][3],
                        st + A32_OFF + offA[ks][mt]);
            {
                uint32_t bf[4][2];
#pragma unroll
                for (int bt = 0; bt < 2; bt++)
                    ldsm_x4(bf[bt*2][0], bf[bt*2][1], bf[bt*2+1][0], bf[bt*2+1][1],
                            st + BZ32_OFF + offB[ks][bt]);
#pragma unroll
                for (int mt = 0; mt < 4; mt++)
#pragma unroll
                    for (int nt = 0; nt < 4; nt++)
                        mma_f16(accz[mt][nt], af[mt], bf[nt]);
            }
            {
                uint32_t bf[4][2];
#pragma unroll
                for (int bt = 0; bt < 2; bt++)
                    ldsm_x4(bf[bt*2][0], bf[bt*2][1], bf[bt*2+1][0], bf[bt*2+1][1],
                            st + BH32_OFF + offB[ks][bt]);
#pragma unroll
                for (int mt = 0; mt < 4; mt++)
#pragma unroll
                    for (int nt = 0; nt < 4; nt++)
                        mma_f16(acch[mt][nt], af[mt], bf[nt]);
            }
        }
    }

    const int er = lane >> 2;
    const int ec = (lane & 3) * 2;
#pragma unroll
    for (int mt = 0; mt < 4; mt++) {
#pragma unroll
        for (int nt = 0; nt < 4; nt++) {
            const int m = mBase + wr * 64 + mt * 16 + er;
            const int n = nBase + wc * 32 + nt * 8 + ec;
            const size_t g0 = (size_t)m * DD + n;
            const size_t g1 = g0 + 8 * DD;
            const float2 bz2 = *(const float2*)(&bz[n]);
            const float2 bh2 = *(const float2*)(&bh[n]);
            float z;
            __half2 p0, p1;
            z = sigmoidf_fast(accz[mt][nt][0] + bz2.x);
            p0.x = __float2half_rn(1.0f - z);
            p0.y = __float2half_rn(z * (acch[mt][nt][0] + bh2.x));
            z = sigmoidf_fast(accz[mt][nt][1] + bz2.y);
            p1.x = __float2half_rn(1.0f - z);
            p1.y = __float2half_rn(z * (acch[mt][nt][1] + bh2.y));
            *(uint2*)(&g_ab[g0]) = make_uint2(h2_to_u32(p0), h2_to_u32(p1));
            z = sigmoidf_fast(accz[mt][nt][2] + bz2.x);
            p0.x = __float2half_rn(1.0f - z);
            p0.y = __float2half_rn(z * (acch[mt][nt][2] + bh2.x));
            z = sigmoidf_fast(accz[mt][nt][3] + bz2.y);
            p1.x = __float2half_rn(1.0f - z);
            p1.y = __float2half_rn(z * (acch[mt][nt][3] + bh2.y));
            *(uint2*)(&g_ab[g1]) = make_uint2(h2_to_u32(p0), h2_to_u32(p1));
        }
    }
}

// ---------------- scan pass 1 (fallback path only) ----------------
__global__ __launch_bounds__(256)
void scan_pass1()
{
    const int g2 = blockIdx.x * 256 + threadIdx.x;
    const int bc = g2 >> 9;
    const int d0 = (g2 & 511) * 2;
    const size_t base = (size_t)bc * CHLEN * DD + d0;

    float2 Ar = make_float2(1.f, 1.f);
    float2 Br = make_float2(0.f, 0.f);
#pragma unroll 16
    for (int t = 0; t < CHLEN; t++) {
        const uint2 raw = *(const uint2*)&g_ab[base + (size_t)t * DD];
        const float2 ab0 = __half22float2(u32_to_h2(raw.x));
        const float2 ab1 = __half22float2(u32_to_h2(raw.y));
        Br.x = fmaf(ab0.x, Br.x, ab0.y); Ar.x *= ab0.x;
        Br.y = fmaf(ab1.x, Br.y, ab1.y); Ar.y *= ab1.x;
    }
    *(float2*)&g_Ac[(size_t)bc * DD + d0] = Ar;
    *(float2*)&g_Bc[(size_t)bc * DD + d0] = Br;
}

// ---------------- scan + swish: software-pipelined (depth-8 prefetch) --------
__global__ __launch_bounds__(256)
void scan_swish_kernel(const float* __restrict__ swish_beta)
{
    const int g2 = blockIdx.x * 256 + threadIdx.x;
    const int bc = g2 >> 9;
    const int d0 = (g2 & 511) * 2;
    const int b = bc >> 5;
    const int chunk = bc & 31;
    const float beta = __ldg(swish_beta);

    float2 h = make_float2(0.f, 0.f);
#pragma unroll 4
    for (int c = 0; c < chunk; c++) {
        const size_t idx = (size_t)(b * NCHUNK + c) * DD + d0;
        const float2 A = *(const float2*)&g_Ac[idx];
        const float2 B = *(const float2*)&g_Bc[idx];
        h.x = fmaf(A.x, h.x, B.x);
        h.y = fmaf(A.y, h.y, B.y);
    }

    const size_t base = (size_t)bc * CHLEN * DD + d0;

    uint2 buf[8];
#pragma unroll
    for (int j = 0; j < 8; j++)
        buf[j] = *(const uint2*)&g_ab[base + (size_t)j * DD];

    for (int t0 = 0; t0 < CHLEN; t0 += 8) {
        uint2 nxt[8];
        if (t0 + 8 < CHLEN) {
#pragma unroll
            for (int j = 0; j < 8; j++)
                nxt[j] = *(const uint2*)&g_ab[base + (size_t)(t0 + 8 + j) * DD];
        }
#pragma unroll
        for (int j = 0; j < 8; j++) {
            const float2 ab0 = __half22float2(u32_to_h2(buf[j].x));
            const float2 ab1 = __half22float2(u32_to_h2(buf[j].y));
            h.x = fmaf(ab0.x, h.x, ab0.y);
            h.y = fmaf(ab1.x, h.y, ab1.y);
            float s;
            __half2 y2;
            s = beta * h.x; y2.x = __float2half_rn(s * sigmoidf_fast(s));
            s = beta * h.y; y2.y = __float2half_rn(s * sigmoidf_fast(s));
            *(__half2*)&g_y16[base + (size_t)(t0 + j) * DD] = y2;
        }
#pragma unroll
        for (int j = 0; j < 8; j++) buf[j] = nxt[j];
    }
}

// ---------------- LayerNorm: warp per row; gamma/lbeta cached in smem --------
__global__ __launch_bounds__(256)
void ln_kernel(const float* __restrict__ gamma,
               const float* __restrict__ lbeta,
               float* __restrict__ out)
{
    __shared__ float s_gm[DD], s_bt[DD];
    // cooperative load of gamma/lbeta (1024 floats each; 4 per thread)
    {
        const int t4 = threadIdx.x * 4;
        *(float4*)&s_gm[t4] = *(const float4*)&gamma[t4];
        *(float4*)&s_bt[t4] = *(const float4*)&lbeta[t4];
    }
    __syncthreads();

    const int row  = blockIdx.x * 8 + (threadIdx.x >> 5);
    const int lane = threadIdx.x & 31;
    const size_t rbase = (size_t)row * DD;

    uint4 yv[4];
    float s1 = 0.0f, s2 = 0.0f;
#pragma unroll
    for (int seg = 0; seg < 4; seg++) {
        yv[seg] = *(const uint4*)&g_y16[rbase + seg * 256 + lane * 8];
        const float2 a = __half22float2(u32_to_h2(yv[seg].x));
        const float2 b = __half22float2(u32_to_h2(yv[seg].y));
        const float2 c = __half22float2(u32_to_h2(yv[seg].z));
        const float2 d = __half22float2(u32_to_h2(yv[seg].w));
        s1 += a.x + a.y + b.x + b.y + c.x + c.y + d.x + d.y;
        s2 += a.x * a.x + a.y * a.y + b.x * b.x + b.y * b.y
            + c.x * c.x + c.y * c.y + d.x * d.x + d.y * d.y;
    }
#pragma unroll
    for (int o = 16; o > 0; o >>= 1) {
        s1 += __shfl_xor_sync(0xffffffffu, s1, o);
        s2 += __shfl_xor_sync(0xffffffffu, s2, o);
    }
    const float mu  = s1 * (1.0f / DD);
    const float var = s2 * (1.0f / DD) - mu * mu;
    const float inv = rsqrtf(var + 1e-5f);

#pragma unroll
    for (int seg = 0; seg < 4; seg++) {
        const int d0 = seg * 256 + lane * 8;
        const float4 gm0 = *(const float4*)&s_gm[d0];
        const float4 gm1 = *(const float4*)&s_gm[d0 + 4];
        const float4 bt0 = *(const float4*)&s_bt[d0];
        const float4 bt1 = *(const float4*)&s_bt[d0 + 4];
        const float2 a = __half22float2(u32_to_h2(yv[seg].x));
        const float2 b = __half22float2(u32_to_h2(yv[seg].y));
        const float2 c = __half22float2(u32_to_h2(yv[seg].z));
        const float2 d = __half22float2(u32_to_h2(yv[seg].w));
        float4 o0, o1;
        o0.x = (a.x - mu) * inv * gm0.x + bt0.x;
        o0.y = (a.y - mu) * inv * gm0.y + bt0.y;
        o0.z = (b.x - mu) * inv * gm0.z + bt0.z;
        o0.w = (b.y - mu) * inv * gm0.w + bt0.w;
        o1.x = (c.x - mu) * inv * gm1.x + bt1.x;
        o1.y = (c.y - mu) * inv * gm1.y + bt1.y;
        o1.z = (d.x - mu) * inv * gm1.z + bt1.z;
        o1.w = (d.y - mu) * inv * gm1.w + bt1.w;
        *(float4*)&out[rbase + d0]     = o0;
        *(float4*)&out[rbase + d0 + 4] = o1;
    }
}

// ---------------- launch ----------------
extern "C" void kernel_launch(void* const* d_in, const int* in_sizes, int n_in,
                              void* d_out, int out_size)
{
    const float* x     = (const float*)d_in[0];
    const float* Wz    = (const float*)d_in[1];
    const float* bz    = (const float*)d_in[2];
    const float* Wh    = (const float*)d_in[3];
    const float* bh    = (const float*)d_in[4];
    const float* sbeta = (const float*)d_in[5];
    const float* gamma = (const float*)d_in[6];
    const float* lbeta = (const float*)d_in[7];
    float* out = (float*)d_out;

    prep_kernel<<<CONV_BLOCKS + 2048, 256>>>(x, Wz, Wh);

    cudaError_t e1 = cudaFuncSetAttribute(
        gemmN64_kernel, cudaFuncAttributeMaxDynamicSharedMemorySize, 3 * STAGEN);
    if (e1 == cudaSuccess) {
        dim3 grid(DD / 64, MM / 128);    // (16, 128)
        gemmN64_kernel<<<grid, 256, 3 * STAGEN>>>(bz, bh);
    } else {
        (void)cudaGetLastError();
        cudaError_t e2 = cudaFuncSetAttribute(
            gemm64_kernel, cudaFuncAttributeMaxDynamicSharedMemorySize, 2 * STAGE64);
        dim3 grid(DD / 128, MM / 128);   // (8, 128)
        if (e2 == cudaSuccess) {
            gemm64_kernel<<<grid, 256, 2 * STAGE64>>>(bz, bh);
        } else {
            (void)cudaGetLastError();
            gemm32_kernel<<<grid, 256, 2 * STAGE32>>>(bz, bh);
            scan_pass1<<<(BB * NCHUNK * DD) / (256 * 2), 256>>>();
        }
    }

    scan_swish_kernel<<<(BB * NCHUNK * DD) / (256 * 2), 256>>>(sbeta);
    ln_kernel<<<MM / 8, 256>>>(gamma, lbeta, out);
}